// round 1
// baseline (speedup 1.0000x reference)
#include <cuda_runtime.h>
#include <math.h>

#define EMBED 4096
#define NH 16
#define HD 256
#define NB 2
#define NS 2048
#define NTOK (NB * NS)

// Scratch buffers (allocation-free rule: __device__ globals)
__device__ float g_q[(size_t)NTOK * EMBED];    // [B,H,S,D]
__device__ float g_k[(size_t)NTOK * EMBED];    // [B,H,S,D]
__device__ float g_v[(size_t)NTOK * EMBED];    // [B,H,S,D]
__device__ float g_att[(size_t)NTOK * EMBED];  // [B,S,E] token-major

// ----------------------------------------------------------------------------
// NT SGEMM: C[M,N] = A[M,K] * B[N,K]^T, M=N=K=4096.
// 128x128 tile, BK=16, 256 threads, 8x8 per thread.
// MODE 0: row-major C. MODE 1: scatter to [B,H,S,D] (QKV epilogue).
// ----------------------------------------------------------------------------
template <int MODE>
__global__ void __launch_bounds__(256) gemm_nt(const float* __restrict__ A,
                                               const float* __restrict__ B,
                                               float* __restrict__ C) {
    const int K = EMBED;
    __shared__ float As[16][132];
    __shared__ float Bs[16][132];
    int tid = threadIdx.x;
    int m0 = blockIdx.y * 128;
    int n0 = blockIdx.x * 128;
    int ty = tid >> 4, tx = tid & 15;
    int lr = tid >> 2;          // 0..63
    int lk = (tid & 3) << 2;    // 0,4,8,12
    const float* Ap = A + (size_t)(m0 + lr) * K + lk;
    const float* Bp = B + (size_t)(n0 + lr) * K + lk;

    float acc[8][8];
#pragma unroll
    for (int i = 0; i < 8; i++)
#pragma unroll
        for (int j = 0; j < 8; j++) acc[i][j] = 0.f;

    for (int k0 = 0; k0 < K; k0 += 16) {
        float4 a0 = *(const float4*)(Ap + k0);
        float4 a1 = *(const float4*)(Ap + (size_t)64 * K + k0);
        float4 b0 = *(const float4*)(Bp + k0);
        float4 b1 = *(const float4*)(Bp + (size_t)64 * K + k0);
        As[lk + 0][lr] = a0.x; As[lk + 1][lr] = a0.y;
        As[lk + 2][lr] = a0.z; As[lk + 3][lr] = a0.w;
        As[lk + 0][lr + 64] = a1.x; As[lk + 1][lr + 64] = a1.y;
        As[lk + 2][lr + 64] = a1.z; As[lk + 3][lr + 64] = a1.w;
        Bs[lk + 0][lr] = b0.x; Bs[lk + 1][lr] = b0.y;
        Bs[lk + 2][lr] = b0.z; Bs[lk + 3][lr] = b0.w;
        Bs[lk + 0][lr + 64] = b1.x; Bs[lk + 1][lr + 64] = b1.y;
        Bs[lk + 2][lr + 64] = b1.z; Bs[lk + 3][lr + 64] = b1.w;
        __syncthreads();
#pragma unroll
        for (int kk = 0; kk < 16; kk++) {
            float a[8], b[8];
#pragma unroll
            for (int i = 0; i < 8; i++) a[i] = As[kk][ty * 8 + i];
#pragma unroll
            for (int j = 0; j < 8; j++) b[j] = Bs[kk][tx * 8 + j];
#pragma unroll
            for (int i = 0; i < 8; i++)
#pragma unroll
                for (int j = 0; j < 8; j++)
                    acc[i][j] = fmaf(a[i], b[j], acc[i][j]);
        }
        __syncthreads();
    }

    if (MODE == 0) {
#pragma unroll
        for (int i = 0; i < 8; i++) {
            int m = m0 + ty * 8 + i;
            float* Cp = C + (size_t)m * EMBED + n0 + tx * 8;
#pragma unroll
            for (int j = 0; j < 8; j++) Cp[j] = acc[i][j];
        }
    } else {
#pragma unroll
        for (int i = 0; i < 8; i++) {
            int t = m0 + ty * 8 + i;     // token index
            int b = t >> 11, s = t & 2047;
#pragma unroll
            for (int j = 0; j < 8; j++) {
                int c = n0 + tx * 8 + j; // embed col
                int h = c >> 8, d = c & 255;
                C[(((size_t)(b * NH + h)) * NS + s) * HD + d] = acc[i][j];
            }
        }
    }
}

// ----------------------------------------------------------------------------
// Rotary: in-place on Q and K ([B,H,S,D]). One thread per (b,h,s,pair).
// embed_positions row: [sin(32) | cos(32)]
// ----------------------------------------------------------------------------
__global__ void rotary_kernel(const int* __restrict__ pos_ids,
                              const float* __restrict__ emb,
                              float* __restrict__ q, float* __restrict__ k) {
    int idx = blockIdx.x * blockDim.x + threadIdx.x;  // 2*16*2048*32 threads
    int d = idx & 31;
    int s = (idx >> 5) & 2047;
    int h = (idx >> 16) & 15;
    int b = idx >> 20;
    int pos = pos_ids[b * NS + s];
    float sv = emb[pos * 64 + d];
    float cv = emb[pos * 64 + 32 + d];
    size_t base = (((size_t)(b * NH + h) * NS + s) * HD) + 2 * d;
    float q1 = q[base], q2 = q[base + 1];
    q[base]     = q1 * cv - q2 * sv;
    q[base + 1] = q2 * cv + q1 * sv;
    float k1 = k[base], k2 = k[base + 1];
    k[base]     = k1 * cv - k2 * sv;
    k[base + 1] = k2 * cv + k1 * sv;
}

// ----------------------------------------------------------------------------
// Causal flash attention, D=256, BQ=64, BK=32, 256 threads (16 q x 16 k).
// Q pre-scaled by 1/sqrt(256). Output written token-major [B,S,E].
// ----------------------------------------------------------------------------
#define QSTR 257
#define PSTR 33
#define FL_SMEM ((64 * QSTR + 32 * QSTR + 32 * QSTR + 64 * PSTR) * 4)

__global__ void __launch_bounds__(256) flash_attn(const float* __restrict__ Qg,
                                                  const float* __restrict__ Kg,
                                                  const float* __restrict__ Vg,
                                                  float* __restrict__ Og) {
    extern __shared__ float sm[];
    float* Qs = sm;                  // 64 x 257
    float* Ks = Qs + 64 * QSTR;      // 32 x 257
    float* Vs = Ks + 32 * QSTR;      // 32 x 257
    float* Ps = Vs + 32 * QSTR;      // 64 x 33

    int tid = threadIdx.x;
    int ty = tid >> 4, tx = tid & 15;
    int bh = blockIdx.y;
    int q0 = blockIdx.x * 64;
    const float* Qb = Qg + (size_t)bh * NS * HD;
    const float* Kb = Kg + (size_t)bh * NS * HD;
    const float* Vb = Vg + (size_t)bh * NS * HD;

    for (int i = tid; i < 64 * 256; i += 256) {
        int q = i >> 8, d = i & 255;
        Qs[q * QSTR + d] = Qb[(size_t)(q0 + q) * HD + d] * 0.0625f;
    }

    float m[4], l[4], acc[4][16];
#pragma unroll
    for (int qi = 0; qi < 4; qi++) {
        m[qi] = -1e30f; l[qi] = 0.f;
#pragma unroll
        for (int dj = 0; dj < 16; dj++) acc[qi][dj] = 0.f;
    }

    for (int k0 = 0; k0 < q0 + 64; k0 += 32) {
        __syncthreads();  // prior PV reads done before overwriting K/V/P
        for (int i = tid; i < 32 * 256; i += 256) {
            int kk = i >> 8, d = i & 255;
            Ks[kk * QSTR + d] = Kb[(size_t)(k0 + kk) * HD + d];
            Vs[kk * QSTR + d] = Vb[(size_t)(k0 + kk) * HD + d];
        }
        __syncthreads();

        float s0[4] = {0.f, 0.f, 0.f, 0.f};
        float s1[4] = {0.f, 0.f, 0.f, 0.f};
#pragma unroll 4
        for (int d = 0; d < 256; d++) {
            float kv0 = Ks[(tx * 2 + 0) * QSTR + d];
            float kv1 = Ks[(tx * 2 + 1) * QSTR + d];
#pragma unroll
            for (int qi = 0; qi < 4; qi++) {
                float qv = Qs[(ty * 4 + qi) * QSTR + d];
                s0[qi] = fmaf(qv, kv0, s0[qi]);
                s1[qi] = fmaf(qv, kv1, s1[qi]);
            }
        }

        bool needmask = (k0 + 32 > q0);
#pragma unroll
        for (int qi = 0; qi < 4; qi++) {
            int qg = q0 + ty * 4 + qi;
            float a = s0[qi], b = s1[qi];
            if (needmask) {
                if (k0 + tx * 2 + 0 > qg) a = -1e30f;
                if (k0 + tx * 2 + 1 > qg) b = -1e30f;
            }
            float tmax = fmaxf(a, b);
#pragma unroll
            for (int off = 8; off > 0; off >>= 1)
                tmax = fmaxf(tmax, __shfl_xor_sync(0xffffffffu, tmax, off, 16));
            float mnew = fmaxf(m[qi], tmax);
            float corr = __expf(m[qi] - mnew);
            float p0 = __expf(a - mnew);
            float p1 = __expf(b - mnew);
            float psum = p0 + p1;
#pragma unroll
            for (int off = 8; off > 0; off >>= 1)
                psum += __shfl_xor_sync(0xffffffffu, psum, off, 16);
            l[qi] = l[qi] * corr + psum;
            m[qi] = mnew;
#pragma unroll
            for (int dj = 0; dj < 16; dj++) acc[qi][dj] *= corr;
            Ps[(ty * 4 + qi) * PSTR + tx * 2 + 0] = p0;
            Ps[(ty * 4 + qi) * PSTR + tx * 2 + 1] = p1;
        }
        __syncthreads();

        // PV: acc[q][d] += P[q][k] * V[k][d], d = dj*16 + tx (conflict-free)
#pragma unroll 2
        for (int kk = 0; kk < 32; kk++) {
            float p[4];
#pragma unroll
            for (int qi = 0; qi < 4; qi++) p[qi] = Ps[(ty * 4 + qi) * PSTR + kk];
#pragma unroll
            for (int dj = 0; dj < 16; dj++) {
                float v = Vs[kk * QSTR + dj * 16 + tx];
#pragma unroll
                for (int qi = 0; qi < 4; qi++)
                    acc[qi][dj] = fmaf(p[qi], v, acc[qi][dj]);
            }
        }
    }

    int b = bh >> 4, h = bh & 15;
#pragma unroll
    for (int qi = 0; qi < 4; qi++) {
        float inv = 1.f / l[qi];
        int s = q0 + ty * 4 + qi;
        float* dst = Og + ((size_t)(b * NS + s)) * EMBED + h * HD;
#pragma unroll
        for (int dj = 0; dj < 16; dj++) dst[dj * 16 + tx] = acc[qi][dj] * inv;
    }
}

// ----------------------------------------------------------------------------
extern "C" void kernel_launch(void* const* d_in, const int* in_sizes, int n_in,
                              void* d_out, int out_size) {
    const float* hs  = (const float*)d_in[0];
    const int*   pid = (const int*)  d_in[1];
    const float* qw  = (const float*)d_in[2];
    const float* kw  = (const float*)d_in[3];
    const float* vw  = (const float*)d_in[4];
    const float* ow  = (const float*)d_in[5];
    const float* emb = (const float*)d_in[6];
    float* out = (float*)d_out;

    float *gq, *gk, *gv, *ga;
    cudaGetSymbolAddress((void**)&gq, g_q);
    cudaGetSymbolAddress((void**)&gk, g_k);
    cudaGetSymbolAddress((void**)&gv, g_v);
    cudaGetSymbolAddress((void**)&ga, g_att);

    dim3 gg(32, 32);
    gemm_nt<1><<<gg, 256>>>(hs, qw, gq);
    gemm_nt<1><<<gg, 256>>>(hs, kw, gk);
    gemm_nt<1><<<gg, 256>>>(hs, vw, gv);

    rotary_kernel<<<(2 * 16 * 2048 * 32) / 256, 256>>>(pid, emb, gq, gk);

    cudaFuncSetAttribute(flash_attn, cudaFuncAttributeMaxDynamicSharedMemorySize,
                         FL_SMEM);
    flash_attn<<<dim3(32, 32), 256, FL_SMEM>>>(gq, gk, gv, ga);

    gemm_nt<0><<<gg, 256>>>(ga, ow, out);
}

// round 3
// speedup vs baseline: 2.2953x; 2.2953x over previous
#include <cuda_runtime.h>
#include <cstdint>
#include <math.h>

#define EMBED 4096
#define NH 16
#define HD 256
#define NB 2
#define NS 2048
#define NTOK (NB * NS)

// Scratch (allocation-free rule: __device__ globals), token-major [B,S,E]
__device__ float g_q[(size_t)NTOK * EMBED];
__device__ float g_k[(size_t)NTOK * EMBED];
__device__ float g_v[(size_t)NTOK * EMBED];
__device__ float g_att[(size_t)NTOK * EMBED];

// ---------------------------------------------------------------------------
// helpers
// ---------------------------------------------------------------------------
__device__ __forceinline__ uint32_t smem_u32(const void* p) {
    uint32_t a;
    asm("{ .reg .u64 t; cvta.to.shared.u64 t, %1; cvt.u32.u64 %0, t; }"
        : "=r"(a) : "l"(p));
    return a;
}
__device__ __forceinline__ void cp16(uint32_t s, const void* g) {
    asm volatile("cp.async.cg.shared.global [%0], [%1], 16;\n" ::"r"(s), "l"(g));
}
#define CP_COMMIT() asm volatile("cp.async.commit_group;\n" ::: "memory")
template <int N>
__device__ __forceinline__ void cp_wait() {
    asm volatile("cp.async.wait_group %0;\n" ::"n"(N) : "memory");
}
__device__ __forceinline__ uint32_t f2tf(float f) {
    uint32_t r;
    asm("cvt.rna.tf32.f32 %0, %1;" : "=r"(r) : "f"(f));
    return r;
}
__device__ __forceinline__ void mma8(float* d, const uint32_t* a, const uint32_t* b) {
    asm volatile(
        "mma.sync.aligned.m16n8k8.row.col.f32.tf32.tf32.f32 "
        "{%0,%1,%2,%3}, {%4,%5,%6,%7}, {%8,%9}, {%0,%1,%2,%3};"
        : "+f"(d[0]), "+f"(d[1]), "+f"(d[2]), "+f"(d[3])
        : "r"(a[0]), "r"(a[1]), "r"(a[2]), "r"(a[3]), "r"(b[0]), "r"(b[1]));
}

// ---------------------------------------------------------------------------
// tf32 mma.sync NT GEMM: C[4096,4096] = A[4096,4096] * B[4096,4096]^T
// CTA 128x128, 256 thr (8 warps = 2x4, warp tile 64x32), KC=32, 3 stages.
// ---------------------------------------------------------------------------
#define GKC 32
#define AROW 36                       // 32 + 4 pad floats
#define TILEF (128 * AROW)            // floats per A (or B) tile
#define STAGEF (2 * TILEF)            // floats per stage (A+B)
#define GSTG 3
#define GEMM_SMEM (GSTG * STAGEF * 4) // 110592 bytes

__global__ void __launch_bounds__(256) gemm_tc(const float* __restrict__ A,
                                               const float* __restrict__ B,
                                               float* __restrict__ C) {
    extern __shared__ float sm[];
    const uint32_t smb = smem_u32(sm);

    int tid = threadIdx.x;
    int wid = tid >> 5, lane = tid & 31;
    int gid = lane >> 2, tig = lane & 3;
    int wm = (wid >> 2) * 64, wn = (wid & 3) * 32;
    int m0 = blockIdx.y * 128, n0 = blockIdx.x * 128;

    const float* Ab = A + (size_t)m0 * EMBED;
    const float* Bb = B + (size_t)n0 * EMBED;

    int pr = tid >> 3;         // 0..31 (row group)
    int pc = (tid & 7) * 4;    // 0..28 (float col of 16B chunk)

    float acc[4][4][4];
#pragma unroll
    for (int mi = 0; mi < 4; mi++)
#pragma unroll
        for (int ni = 0; ni < 4; ni++)
#pragma unroll
            for (int q = 0; q < 4; q++) acc[mi][ni][q] = 0.f;

    // producer: load chunk k-index 'c' into stage s
    auto load_tile = [&](int s, int c) {
        uint32_t abase = smb + (s * STAGEF) * 4;
        uint32_t bbase = abase + TILEF * 4;
        int k0 = c * GKC;
#pragma unroll
        for (int i = 0; i < 4; i++) {
            int r = pr + i * 32;
            cp16(abase + (r * AROW + pc) * 4, Ab + (size_t)r * EMBED + k0 + pc);
            cp16(bbase + (r * AROW + pc) * 4, Bb + (size_t)r * EMBED + k0 + pc);
        }
    };

    // prologue: stages 0..GSTG-2
#pragma unroll
    for (int c = 0; c < GSTG - 1; c++) {
        load_tile(c, c);
        CP_COMMIT();
    }

    const int CHUNKS = EMBED / GKC;  // 128
    int s = 0;
    for (int c = 0; c < CHUNKS; c++) {
        cp_wait<GSTG - 2>();
        __syncthreads();

        int nxt = c + GSTG - 1;
        if (nxt < CHUNKS) {
            int sn = s + GSTG - 1;
            if (sn >= GSTG) sn -= GSTG;
            load_tile(sn, nxt);
        }
        CP_COMMIT();

        const float* as = sm + s * STAGEF;
        const float* bs = as + TILEF;
#pragma unroll
        for (int kk = 0; kk < 4; kk++) {
            uint32_t af[4][4], bf[4][2];
#pragma unroll
            for (int mi = 0; mi < 4; mi++) {
                const float* ap = as + (wm + mi * 16 + gid) * AROW + kk * 8 + tig;
                af[mi][0] = f2tf(ap[0]);
                af[mi][1] = f2tf(ap[8 * AROW]);
                af[mi][2] = f2tf(ap[4]);
                af[mi][3] = f2tf(ap[8 * AROW + 4]);
            }
#pragma unroll
            for (int ni = 0; ni < 4; ni++) {
                const float* bp = bs + (wn + ni * 8 + gid) * AROW + kk * 8 + tig;
                bf[ni][0] = f2tf(bp[0]);
                bf[ni][1] = f2tf(bp[4]);
            }
#pragma unroll
            for (int mi = 0; mi < 4; mi++)
#pragma unroll
                for (int ni = 0; ni < 4; ni++)
                    mma8(acc[mi][ni], af[mi], bf[ni]);
        }
        if (++s == GSTG) s = 0;
    }

    // epilogue: float2 stores
#pragma unroll
    for (int mi = 0; mi < 4; mi++) {
        int row = m0 + wm + mi * 16 + gid;
#pragma unroll
        for (int ni = 0; ni < 4; ni++) {
            int col = n0 + wn + ni * 8 + tig * 2;
            float2 v0 = make_float2(acc[mi][ni][0], acc[mi][ni][1]);
            float2 v1 = make_float2(acc[mi][ni][2], acc[mi][ni][3]);
            *reinterpret_cast<float2*>(C + (size_t)row * EMBED + col) = v0;
            *reinterpret_cast<float2*>(C + (size_t)(row + 8) * EMBED + col) = v1;
        }
    }
}

// ---------------------------------------------------------------------------
// Rotary (token-major [B,S,E]): one thread per (b,h,s,pair)
// ---------------------------------------------------------------------------
__global__ void rotary_kernel(const int* __restrict__ pos_ids,
                              const float* __restrict__ emb,
                              float* __restrict__ q, float* __restrict__ k) {
    int idx = blockIdx.x * blockDim.x + threadIdx.x;
    int d = idx & 31;
    int s = (idx >> 5) & 2047;
    int h = (idx >> 16) & 15;
    int b = idx >> 20;
    int pos = pos_ids[b * NS + s];
    float sv = emb[pos * 64 + d];
    float cv = emb[pos * 64 + 32 + d];
    size_t base = ((size_t)(b * NS + s)) * EMBED + h * HD + 2 * d;
    float q1 = q[base], q2 = q[base + 1];
    q[base] = q1 * cv - q2 * sv;
    q[base + 1] = q2 * cv + q1 * sv;
    float k1 = k[base], k2 = k[base + 1];
    k[base] = k1 * cv - k2 * sv;
    k[base + 1] = k2 * cv + k1 * sv;
}

// ---------------------------------------------------------------------------
// Causal flash attention, D=256, BQ=64, BK=32, 256 threads (token-major I/O)
// ---------------------------------------------------------------------------
#define QSTR 257
#define PSTR 33
#define FL_SMEM ((64 * QSTR + 32 * QSTR + 32 * QSTR + 64 * PSTR) * 4)

__global__ void __launch_bounds__(256) flash_attn(const float* __restrict__ Qg,
                                                  const float* __restrict__ Kg,
                                                  const float* __restrict__ Vg,
                                                  float* __restrict__ Og) {
    extern __shared__ float sm[];
    float* Qs = sm;
    float* Ks = Qs + 64 * QSTR;
    float* Vs = Ks + 32 * QSTR;
    float* Ps = Vs + 32 * QSTR;

    int tid = threadIdx.x;
    int ty = tid >> 4, tx = tid & 15;
    int bh = blockIdx.y;
    int b = bh >> 4, h = bh & 15;
    int q0 = blockIdx.x * 64;
    const float* Qb = Qg + (size_t)b * NS * EMBED + h * HD;
    const float* Kb = Kg + (size_t)b * NS * EMBED + h * HD;
    const float* Vb = Vg + (size_t)b * NS * EMBED + h * HD;

    for (int i = tid; i < 64 * 256; i += 256) {
        int q = i >> 8, d = i & 255;
        Qs[q * QSTR + d] = Qb[(size_t)(q0 + q) * EMBED + d] * 0.0625f;
    }

    float m[4], l[4], acc[4][16];
#pragma unroll
    for (int qi = 0; qi < 4; qi++) {
        m[qi] = -1e30f; l[qi] = 0.f;
#pragma unroll
        for (int dj = 0; dj < 16; dj++) acc[qi][dj] = 0.f;
    }

    for (int k0 = 0; k0 < q0 + 64; k0 += 32) {
        __syncthreads();
        for (int i = tid; i < 32 * 256; i += 256) {
            int kk = i >> 8, d = i & 255;
            Ks[kk * QSTR + d] = Kb[(size_t)(k0 + kk) * EMBED + d];
            Vs[kk * QSTR + d] = Vb[(size_t)(k0 + kk) * EMBED + d];
        }
        __syncthreads();

        float s0[4] = {0.f, 0.f, 0.f, 0.f};
        float s1[4] = {0.f, 0.f, 0.f, 0.f};
#pragma unroll 4
        for (int d = 0; d < 256; d++) {
            float kv0 = Ks[(tx * 2 + 0) * QSTR + d];
            float kv1 = Ks[(tx * 2 + 1) * QSTR + d];
#pragma unroll
            for (int qi = 0; qi < 4; qi++) {
                float qv = Qs[(ty * 4 + qi) * QSTR + d];
                s0[qi] = fmaf(qv, kv0, s0[qi]);
                s1[qi] = fmaf(qv, kv1, s1[qi]);
            }
        }

        bool needmask = (k0 + 32 > q0);
#pragma unroll
        for (int qi = 0; qi < 4; qi++) {
            int qg = q0 + ty * 4 + qi;
            float a = s0[qi], bb = s1[qi];
            if (needmask) {
                if (k0 + tx * 2 + 0 > qg) a = -1e30f;
                if (k0 + tx * 2 + 1 > qg) bb = -1e30f;
            }
            float tmax = fmaxf(a, bb);
#pragma unroll
            for (int off = 8; off > 0; off >>= 1)
                tmax = fmaxf(tmax, __shfl_xor_sync(0xffffffffu, tmax, off, 16));
            float mnew = fmaxf(m[qi], tmax);
            float corr = __expf(m[qi] - mnew);
            float p0 = __expf(a - mnew);
            float p1 = __expf(bb - mnew);
            float psum = p0 + p1;
#pragma unroll
            for (int off = 8; off > 0; off >>= 1)
                psum += __shfl_xor_sync(0xffffffffu, psum, off, 16);
            l[qi] = l[qi] * corr + psum;
            m[qi] = mnew;
#pragma unroll
            for (int dj = 0; dj < 16; dj++) acc[qi][dj] *= corr;
            Ps[(ty * 4 + qi) * PSTR + tx * 2 + 0] = p0;
            Ps[(ty * 4 + qi) * PSTR + tx * 2 + 1] = p1;
        }
        __syncthreads();

#pragma unroll 2
        for (int kk = 0; kk < 32; kk++) {
            float p[4];
#pragma unroll
            for (int qi = 0; qi < 4; qi++) p[qi] = Ps[(ty * 4 + qi) * PSTR + kk];
#pragma unroll
            for (int dj = 0; dj < 16; dj++) {
                float v = Vs[kk * QSTR + dj * 16 + tx];
#pragma unroll
                for (int qi = 0; qi < 4; qi++)
                    acc[qi][dj] = fmaf(p[qi], v, acc[qi][dj]);
            }
        }
    }

#pragma unroll
    for (int qi = 0; qi < 4; qi++) {
        float inv = 1.f / l[qi];
        int s = q0 + ty * 4 + qi;
        float* dst = Og + ((size_t)(b * NS + s)) * EMBED + h * HD;
#pragma unroll
        for (int dj = 0; dj < 16; dj++) dst[dj * 16 + tx] = acc[qi][dj] * inv;
    }
}

// ---------------------------------------------------------------------------
extern "C" void kernel_launch(void* const* d_in, const int* in_sizes, int n_in,
                              void* d_out, int out_size) {
    const float* hs = (const float*)d_in[0];
    const int* pid = (const int*)d_in[1];
    const float* qw = (const float*)d_in[2];
    const float* kw = (const float*)d_in[3];
    const float* vw = (const float*)d_in[4];
    const float* ow = (const float*)d_in[5];
    const float* emb = (const float*)d_in[6];
    float* out = (float*)d_out;

    float *gq, *gk, *gv, *ga;
    cudaGetSymbolAddress((void**)&gq, g_q);
    cudaGetSymbolAddress((void**)&gk, g_k);
    cudaGetSymbolAddress((void**)&gv, g_v);
    cudaGetSymbolAddress((void**)&ga, g_att);

    cudaFuncSetAttribute(gemm_tc, cudaFuncAttributeMaxDynamicSharedMemorySize, GEMM_SMEM);
    cudaFuncSetAttribute(flash_attn, cudaFuncAttributeMaxDynamicSharedMemorySize, FL_SMEM);

    dim3 gg(32, 32);
    gemm_tc<<<gg, 256, GEMM_SMEM>>>(hs, qw, gq);
    gemm_tc<<<gg, 256, GEMM_SMEM>>>(hs, kw, gk);
    gemm_tc<<<gg, 256, GEMM_SMEM>>>(hs, vw, gv);

    rotary_kernel<<<(2 * 16 * 2048 * 32) / 256, 256>>>(pid, emb, gq, gk);

    flash_attn<<<dim3(32, 32), 256, FL_SMEM>>>(gq, gk, gv, ga);

    gemm_tc<<<gg, 256, GEMM_SMEM>>>(ga, ow, out);
}

// round 4
// speedup vs baseline: 2.2971x; 1.0008x over previous
#include <cuda_runtime.h>
#include <cstdint>
#include <math.h>

#define EMBED 4096
#define NH 16
#define HD 256
#define NB 2
#define NS 2048
#define NTOK (NB * NS)

// Scratch (allocation-free rule: __device__ globals), token-major [B,S,E]
__device__ float g_q[(size_t)NTOK * EMBED];
__device__ float g_k[(size_t)NTOK * EMBED];
__device__ float g_v[(size_t)NTOK * EMBED];
__device__ float g_att[(size_t)NTOK * EMBED];

// ---------------------------------------------------------------------------
// helpers
// ---------------------------------------------------------------------------
__device__ __forceinline__ uint32_t smem_u32(const void* p) {
    uint32_t a;
    asm("{ .reg .u64 t; cvta.to.shared.u64 t, %1; cvt.u32.u64 %0, t; }"
        : "=r"(a) : "l"(p));
    return a;
}
__device__ __forceinline__ void cp16(uint32_t s, const void* g) {
    asm volatile("cp.async.cg.shared.global [%0], [%1], 16;\n" ::"r"(s), "l"(g));
}
#define CP_COMMIT() asm volatile("cp.async.commit_group;\n" ::: "memory")
template <int N>
__device__ __forceinline__ void cp_wait() {
    asm volatile("cp.async.wait_group %0;\n" ::"n"(N) : "memory");
}
__device__ __forceinline__ uint32_t f2tf(float f) {
    uint32_t r;
    asm("cvt.rna.tf32.f32 %0, %1;" : "=r"(r) : "f"(f));
    return r;
}
__device__ __forceinline__ void mma8(float* d, const uint32_t* a, const uint32_t* b) {
    asm volatile(
        "mma.sync.aligned.m16n8k8.row.col.f32.tf32.tf32.f32 "
        "{%0,%1,%2,%3}, {%4,%5,%6,%7}, {%8,%9}, {%0,%1,%2,%3};"
        : "+f"(d[0]), "+f"(d[1]), "+f"(d[2]), "+f"(d[3])
        : "r"(a[0]), "r"(a[1]), "r"(a[2]), "r"(a[3]), "r"(b[0]), "r"(b[1]));
}

// ---------------------------------------------------------------------------
// tf32 mma.sync NT GEMM: C[4096,4096] = A[4096,4096] * B[4096,4096]^T
// CTA 128x128, 256 thr (8 warps = 2x4, warp tile 64x32), KC=32, 3 stages.
// ---------------------------------------------------------------------------
#define GKC 32
#define AROW 36                       // 32 + 4 pad floats
#define TILEF (128 * AROW)            // floats per A (or B) tile
#define STAGEF (2 * TILEF)            // floats per stage (A+B)
#define GSTG 3
#define GEMM_SMEM (GSTG * STAGEF * 4) // 110592 bytes

__global__ void __launch_bounds__(256) gemm_tc(const float* __restrict__ A,
                                               const float* __restrict__ B,
                                               float* __restrict__ C) {
    extern __shared__ float sm[];
    const uint32_t smb = smem_u32(sm);

    int tid = threadIdx.x;
    int wid = tid >> 5, lane = tid & 31;
    int gid = lane >> 2, tig = lane & 3;
    int wm = (wid >> 2) * 64, wn = (wid & 3) * 32;
    int m0 = blockIdx.y * 128, n0 = blockIdx.x * 128;

    const float* Ab = A + (size_t)m0 * EMBED;
    const float* Bb = B + (size_t)n0 * EMBED;

    int pr = tid >> 3;         // 0..31 (row group)
    int pc = (tid & 7) * 4;    // 0..28 (float col of 16B chunk)

    float acc[4][4][4];
#pragma unroll
    for (int mi = 0; mi < 4; mi++)
#pragma unroll
        for (int ni = 0; ni < 4; ni++)
#pragma unroll
            for (int q = 0; q < 4; q++) acc[mi][ni][q] = 0.f;

    // producer: load chunk k-index 'c' into stage s
    auto load_tile = [&](int s, int c) {
        uint32_t abase = smb + (s * STAGEF) * 4;
        uint32_t bbase = abase + TILEF * 4;
        int k0 = c * GKC;
#pragma unroll
        for (int i = 0; i < 4; i++) {
            int r = pr + i * 32;
            cp16(abase + (r * AROW + pc) * 4, Ab + (size_t)r * EMBED + k0 + pc);
            cp16(bbase + (r * AROW + pc) * 4, Bb + (size_t)r * EMBED + k0 + pc);
        }
    };

    // prologue: stages 0..GSTG-2
#pragma unroll
    for (int c = 0; c < GSTG - 1; c++) {
        load_tile(c, c);
        CP_COMMIT();
    }

    const int CHUNKS = EMBED / GKC;  // 128
    int s = 0;
    for (int c = 0; c < CHUNKS; c++) {
        cp_wait<GSTG - 2>();
        __syncthreads();

        int nxt = c + GSTG - 1;
        if (nxt < CHUNKS) {
            int sn = s + GSTG - 1;
            if (sn >= GSTG) sn -= GSTG;
            load_tile(sn, nxt);
        }
        CP_COMMIT();

        const float* as = sm + s * STAGEF;
        const float* bs = as + TILEF;
#pragma unroll
        for (int kk = 0; kk < 4; kk++) {
            uint32_t af[4][4], bf[4][2];
#pragma unroll
            for (int mi = 0; mi < 4; mi++) {
                const float* ap = as + (wm + mi * 16 + gid) * AROW + kk * 8 + tig;
                af[mi][0] = f2tf(ap[0]);
                af[mi][1] = f2tf(ap[8 * AROW]);
                af[mi][2] = f2tf(ap[4]);
                af[mi][3] = f2tf(ap[8 * AROW + 4]);
            }
#pragma unroll
            for (int ni = 0; ni < 4; ni++) {
                const float* bp = bs + (wn + ni * 8 + gid) * AROW + kk * 8 + tig;
                bf[ni][0] = f2tf(bp[0]);
                bf[ni][1] = f2tf(bp[4]);
            }
#pragma unroll
            for (int mi = 0; mi < 4; mi++)
#pragma unroll
                for (int ni = 0; ni < 4; ni++)
                    mma8(acc[mi][ni], af[mi], bf[ni]);
        }
        if (++s == GSTG) s = 0;
    }

    // epilogue: float2 stores
#pragma unroll
    for (int mi = 0; mi < 4; mi++) {
        int row = m0 + wm + mi * 16 + gid;
#pragma unroll
        for (int ni = 0; ni < 4; ni++) {
            int col = n0 + wn + ni * 8 + tig * 2;
            float2 v0 = make_float2(acc[mi][ni][0], acc[mi][ni][1]);
            float2 v1 = make_float2(acc[mi][ni][2], acc[mi][ni][3]);
            *reinterpret_cast<float2*>(C + (size_t)row * EMBED + col) = v0;
            *reinterpret_cast<float2*>(C + (size_t)(row + 8) * EMBED + col) = v1;
        }
    }
}

// ---------------------------------------------------------------------------
// Rotary (token-major [B,S,E]): one thread per (b,h,s,pair)
// ---------------------------------------------------------------------------
__global__ void rotary_kernel(const int* __restrict__ pos_ids,
                              const float* __restrict__ emb,
                              float* __restrict__ q, float* __restrict__ k) {
    int idx = blockIdx.x * blockDim.x + threadIdx.x;
    int d = idx & 31;
    int s = (idx >> 5) & 2047;
    int h = (idx >> 16) & 15;
    int b = idx >> 20;
    int pos = pos_ids[b * NS + s];
    float sv = emb[pos * 64 + d];
    float cv = emb[pos * 64 + 32 + d];
    size_t base = ((size_t)(b * NS + s)) * EMBED + h * HD + 2 * d;
    float q1 = q[base], q2 = q[base + 1];
    q[base] = q1 * cv - q2 * sv;
    q[base + 1] = q2 * cv + q1 * sv;
    float k1 = k[base], k2 = k[base + 1];
    k[base] = k1 * cv - k2 * sv;
    k[base + 1] = k2 * cv + k1 * sv;
}

// ---------------------------------------------------------------------------
// Causal flash attention, D=256, BQ=64, BK=32, 256 threads (token-major I/O)
// ---------------------------------------------------------------------------
#define QSTR 257
#define PSTR 33
#define FL_SMEM ((64 * QSTR + 32 * QSTR + 32 * QSTR + 64 * PSTR) * 4)

__global__ void __launch_bounds__(256) flash_attn(const float* __restrict__ Qg,
                                                  const float* __restrict__ Kg,
                                                  const float* __restrict__ Vg,
                                                  float* __restrict__ Og) {
    extern __shared__ float sm[];
    float* Qs = sm;
    float* Ks = Qs + 64 * QSTR;
    float* Vs = Ks + 32 * QSTR;
    float* Ps = Vs + 32 * QSTR;

    int tid = threadIdx.x;
    int ty = tid >> 4, tx = tid & 15;
    int bh = blockIdx.y;
    int b = bh >> 4, h = bh & 15;
    int q0 = blockIdx.x * 64;
    const float* Qb = Qg + (size_t)b * NS * EMBED + h * HD;
    const float* Kb = Kg + (size_t)b * NS * EMBED + h * HD;
    const float* Vb = Vg + (size_t)b * NS * EMBED + h * HD;

    for (int i = tid; i < 64 * 256; i += 256) {
        int q = i >> 8, d = i & 255;
        Qs[q * QSTR + d] = Qb[(size_t)(q0 + q) * EMBED + d] * 0.0625f;
    }

    float m[4], l[4], acc[4][16];
#pragma unroll
    for (int qi = 0; qi < 4; qi++) {
        m[qi] = -1e30f; l[qi] = 0.f;
#pragma unroll
        for (int dj = 0; dj < 16; dj++) acc[qi][dj] = 0.f;
    }

    for (int k0 = 0; k0 < q0 + 64; k0 += 32) {
        __syncthreads();
        for (int i = tid; i < 32 * 256; i += 256) {
            int kk = i >> 8, d = i & 255;
            Ks[kk * QSTR + d] = Kb[(size_t)(k0 + kk) * EMBED + d];
            Vs[kk * QSTR + d] = Vb[(size_t)(k0 + kk) * EMBED + d];
        }
        __syncthreads();

        float s0[4] = {0.f, 0.f, 0.f, 0.f};
        float s1[4] = {0.f, 0.f, 0.f, 0.f};
#pragma unroll 4
        for (int d = 0; d < 256; d++) {
            float kv0 = Ks[(tx * 2 + 0) * QSTR + d];
            float kv1 = Ks[(tx * 2 + 1) * QSTR + d];
#pragma unroll
            for (int qi = 0; qi < 4; qi++) {
                float qv = Qs[(ty * 4 + qi) * QSTR + d];
                s0[qi] = fmaf(qv, kv0, s0[qi]);
                s1[qi] = fmaf(qv, kv1, s1[qi]);
            }
        }

        bool needmask = (k0 + 32 > q0);
#pragma unroll
        for (int qi = 0; qi < 4; qi++) {
            int qg = q0 + ty * 4 + qi;
            float a = s0[qi], bb = s1[qi];
            if (needmask) {
                if (k0 + tx * 2 + 0 > qg) a = -1e30f;
                if (k0 + tx * 2 + 1 > qg) bb = -1e30f;
            }
            float tmax = fmaxf(a, bb);
#pragma unroll
            for (int off = 8; off > 0; off >>= 1)
                tmax = fmaxf(tmax, __shfl_xor_sync(0xffffffffu, tmax, off, 16));
            float mnew = fmaxf(m[qi], tmax);
            float corr = __expf(m[qi] - mnew);
            float p0 = __expf(a - mnew);
            float p1 = __expf(bb - mnew);
            float psum = p0 + p1;
#pragma unroll
            for (int off = 8; off > 0; off >>= 1)
                psum += __shfl_xor_sync(0xffffffffu, psum, off, 16);
            l[qi] = l[qi] * corr + psum;
            m[qi] = mnew;
#pragma unroll
            for (int dj = 0; dj < 16; dj++) acc[qi][dj] *= corr;
            Ps[(ty * 4 + qi) * PSTR + tx * 2 + 0] = p0;
            Ps[(ty * 4 + qi) * PSTR + tx * 2 + 1] = p1;
        }
        __syncthreads();

#pragma unroll 2
        for (int kk = 0; kk < 32; kk++) {
            float p[4];
#pragma unroll
            for (int qi = 0; qi < 4; qi++) p[qi] = Ps[(ty * 4 + qi) * PSTR + kk];
#pragma unroll
            for (int dj = 0; dj < 16; dj++) {
                float v = Vs[kk * QSTR + dj * 16 + tx];
#pragma unroll
                for (int qi = 0; qi < 4; qi++)
                    acc[qi][dj] = fmaf(p[qi], v, acc[qi][dj]);
            }
        }
    }

#pragma unroll
    for (int qi = 0; qi < 4; qi++) {
        float inv = 1.f / l[qi];
        int s = q0 + ty * 4 + qi;
        float* dst = Og + ((size_t)(b * NS + s)) * EMBED + h * HD;
#pragma unroll
        for (int dj = 0; dj < 16; dj++) dst[dj * 16 + tx] = acc[qi][dj] * inv;
    }
}

// ---------------------------------------------------------------------------
extern "C" void kernel_launch(void* const* d_in, const int* in_sizes, int n_in,
                              void* d_out, int out_size) {
    const float* hs = (const float*)d_in[0];
    const int* pid = (const int*)d_in[1];
    const float* qw = (const float*)d_in[2];
    const float* kw = (const float*)d_in[3];
    const float* vw = (const float*)d_in[4];
    const float* ow = (const float*)d_in[5];
    const float* emb = (const float*)d_in[6];
    float* out = (float*)d_out;

    float *gq, *gk, *gv, *ga;
    cudaGetSymbolAddress((void**)&gq, g_q);
    cudaGetSymbolAddress((void**)&gk, g_k);
    cudaGetSymbolAddress((void**)&gv, g_v);
    cudaGetSymbolAddress((void**)&ga, g_att);

    cudaFuncSetAttribute(gemm_tc, cudaFuncAttributeMaxDynamicSharedMemorySize, GEMM_SMEM);
    cudaFuncSetAttribute(flash_attn, cudaFuncAttributeMaxDynamicSharedMemorySize, FL_SMEM);

    dim3 gg(32, 32);
    gemm_tc<<<gg, 256, GEMM_SMEM>>>(hs, qw, gq);
    gemm_tc<<<gg, 256, GEMM_SMEM>>>(hs, kw, gk);
    gemm_tc<<<gg, 256, GEMM_SMEM>>>(hs, vw, gv);

    rotary_kernel<<<(2 * 16 * 2048 * 32) / 256, 256>>>(pid, emb, gq, gk);

    flash_attn<<<dim3(32, 32), 256, FL_SMEM>>>(gq, gk, gv, ga);

    gemm_tc<<<gg, 256, GEMM_SMEM>>>(ga, ow, out);
}

// round 5
// speedup vs baseline: 9.1593x; 3.9872x over previous
#include <cuda_runtime.h>
#include <cuda_fp16.h>
#include <cstdint>
#include <math.h>

#define EMBED 4096
#define NH 16
#define HD 256
#define NB 2
#define NS 2048
#define NTOK (NB * NS)
#define NELEM ((size_t)NTOK * EMBED)

__device__ __half g_hs_h[NELEM];
__device__ __half g_wq_h[NELEM];
__device__ __half g_wk_h[NELEM];
__device__ __half g_wv_h[NELEM];
__device__ __half g_wo_h[NELEM];
__device__ float  g_qf[NELEM];
__device__ float  g_kf[NELEM];
__device__ __half g_qhi[NELEM];
__device__ __half g_qlo[NELEM];
__device__ __half g_khi[NELEM];
__device__ __half g_klo[NELEM];
__device__ __half g_v[NELEM];
__device__ __half g_att[NELEM];

// ---------------- PTX helpers (baseline ISA; tcgen05 is sm_103a-gated) ------
__device__ __forceinline__ uint32_t smem_u32(const void* p) {
    uint32_t a;
    asm("{ .reg .u64 t; cvta.to.shared.u64 t, %1; cvt.u32.u64 %0, t; }"
        : "=r"(a) : "l"(p));
    return a;
}
__device__ __forceinline__ void cp16(uint32_t s, const void* g) {
    asm volatile("cp.async.cg.shared.global [%0], [%1], 16;\n" ::"r"(s), "l"(g));
}
#define CP_COMMIT() asm volatile("cp.async.commit_group;\n" ::: "memory")
template <int N>
__device__ __forceinline__ void cp_wait() {
    asm volatile("cp.async.wait_group %0;\n" ::"n"(N) : "memory");
}
__device__ __forceinline__ void ldsm4(uint32_t* r, uint32_t a) {
    asm volatile("ldmatrix.sync.aligned.m8n8.x4.shared.b16 {%0,%1,%2,%3}, [%4];"
                 : "=r"(r[0]), "=r"(r[1]), "=r"(r[2]), "=r"(r[3]) : "r"(a));
}
__device__ __forceinline__ void ldsm4t(uint32_t* r, uint32_t a) {
    asm volatile("ldmatrix.sync.aligned.m8n8.x4.trans.shared.b16 {%0,%1,%2,%3}, [%4];"
                 : "=r"(r[0]), "=r"(r[1]), "=r"(r[2]), "=r"(r[3]) : "r"(a));
}
__device__ __forceinline__ void mma16(float* c, const uint32_t* a, const uint32_t* b) {
    asm volatile(
        "mma.sync.aligned.m16n8k16.row.col.f32.f16.f16.f32 "
        "{%0,%1,%2,%3}, {%4,%5,%6,%7}, {%8,%9}, {%0,%1,%2,%3};"
        : "+f"(c[0]), "+f"(c[1]), "+f"(c[2]), "+f"(c[3])
        : "r"(a[0]), "r"(a[1]), "r"(a[2]), "r"(a[3]), "r"(b[0]), "r"(b[1]));
}
__device__ __forceinline__ uint32_t swz128(int r, int c) {  // row = 64 halves
    return (uint32_t)(r * 128 + ((((c >> 3) ^ r) & 7) << 4) + ((c & 7) << 1));
}
__device__ __forceinline__ uint32_t swz512(int r, int c) {  // row = 256 halves
    int g = c >> 3;
    return (uint32_t)(r * 512 + (((g & 24) | ((g ^ r) & 7)) << 4) + ((c & 7) << 1));
}

// ---------------- fp32 -> fp16 ---------------------------------------------
__global__ void f2h(const float* __restrict__ s, __half* __restrict__ d, int n2) {
    int i = blockIdx.x * blockDim.x + threadIdx.x;
    if (i < n2) {
        float2 v = reinterpret_cast<const float2*>(s)[i];
        reinterpret_cast<__half2*>(d)[i] = __floats2half2_rn(v.x, v.y);
    }
}

// ---------------- fp16 HMMA NT GEMM: C = A * B^T, 4096^3 --------------------
// CTA 128x128, 8 warps (2x4), warp 64x32, BK=64, 3 stages.
#define G_STAGE_B 32768
#define GEMM_SMEM (3 * G_STAGE_B)

template <typename OUTT>
__global__ void __launch_bounds__(256, 2) gemm_h(const __half* __restrict__ A,
                                                 const __half* __restrict__ B,
                                                 OUTT* __restrict__ C) {
    extern __shared__ char smraw[];
    uint32_t smb = smem_u32(smraw);
    int tid = threadIdx.x;
    int wid = tid >> 5, lane = tid & 31;
    int gid = lane >> 2, tig = lane & 3;
    int wm = (wid >> 2) * 64, wn = (wid & 3) * 32;
    int m0 = blockIdx.y * 128, n0 = blockIdx.x * 128;
    int a_r = lane & 15, a_c = (lane >> 4) << 3;
    int b_r = ((lane >> 4) << 3) + (lane & 7), b_c = ((lane >> 3) & 1) << 3;

    float acc[4][4][4];
#pragma unroll
    for (int i = 0; i < 4; i++)
#pragma unroll
        for (int j = 0; j < 4; j++)
#pragma unroll
            for (int q = 0; q < 4; q++) acc[i][j][q] = 0.f;

    auto loadst = [&](int st, int k0) {
        uint32_t ab = smb + st * G_STAGE_B, bb = ab + 16384;
#pragma unroll
        for (int i = 0; i < 4; i++) {
            int gi = tid + i * 256;
            int r = gi >> 3, g = gi & 7;
            uint32_t off = r * 128 + (((g ^ r) & 7) << 4);
            cp16(ab + off, A + (size_t)(m0 + r) * EMBED + k0 + g * 8);
            cp16(bb + off, B + (size_t)(n0 + r) * EMBED + k0 + g * 8);
        }
    };

    loadst(0, 0); CP_COMMIT();
    loadst(1, 64); CP_COMMIT();

    int s = 0;
    for (int c = 0; c < 64; c++) {
        cp_wait<1>();
        __syncthreads();
        if (c + 2 < 64) loadst((s + 2) % 3, (c + 2) * 64);
        CP_COMMIT();

        uint32_t ab = smb + s * G_STAGE_B, bb = ab + 16384;
#pragma unroll
        for (int kc = 0; kc < 4; kc++) {
            int kk = kc * 16;
            uint32_t af[4][4], bf[2][4];
#pragma unroll
            for (int mi = 0; mi < 4; mi++)
                ldsm4(af[mi], ab + swz128(wm + mi * 16 + a_r, kk + a_c));
#pragma unroll
            for (int np = 0; np < 2; np++)
                ldsm4(bf[np], bb + swz128(wn + np * 16 + b_r, kk + b_c));
#pragma unroll
            for (int mi = 0; mi < 4; mi++)
#pragma unroll
                for (int ni = 0; ni < 4; ni++)
                    mma16(acc[mi][ni], af[mi], &bf[ni >> 1][(ni & 1) * 2]);
        }
        __syncthreads();
        if (++s == 3) s = 0;
    }

#pragma unroll
    for (int mi = 0; mi < 4; mi++) {
        int r0 = m0 + wm + mi * 16 + gid;
#pragma unroll
        for (int ni = 0; ni < 4; ni++) {
            int col = n0 + wn + ni * 8 + tig * 2;
            if (sizeof(OUTT) == 4) {
                *reinterpret_cast<float2*>((float*)C + (size_t)r0 * EMBED + col) =
                    make_float2(acc[mi][ni][0], acc[mi][ni][1]);
                *reinterpret_cast<float2*>((float*)C + (size_t)(r0 + 8) * EMBED + col) =
                    make_float2(acc[mi][ni][2], acc[mi][ni][3]);
            } else {
                *reinterpret_cast<__half2*>((__half*)C + (size_t)r0 * EMBED + col) =
                    __floats2half2_rn(acc[mi][ni][0], acc[mi][ni][1]);
                *reinterpret_cast<__half2*>((__half*)C + (size_t)(r0 + 8) * EMBED + col) =
                    __floats2half2_rn(acc[mi][ni][2], acc[mi][ni][3]);
            }
        }
    }
}

// ---------------- rotary + hi/lo split --------------------------------------
__global__ void rot_split(const int* __restrict__ pid, const float* __restrict__ emb,
                          const float* __restrict__ qf, const float* __restrict__ kf,
                          __half* __restrict__ qhi, __half* __restrict__ qlo,
                          __half* __restrict__ khi, __half* __restrict__ klo) {
    int idx = blockIdx.x * blockDim.x + threadIdx.x;  // NTOK*16*128
    int p = idx & 127;
    int hh = (idx >> 7) & 15;
    int tok = idx >> 11;
    size_t base = (size_t)tok * EMBED + hh * HD + 2 * p;
    float q0 = qf[base], q1 = qf[base + 1];
    float k0 = kf[base], k1 = kf[base + 1];
    if (p < 32) {
        int pos = pid[tok];
        float sv = emb[pos * 64 + p], cv = emb[pos * 64 + 32 + p];
        float a = q0 * cv - q1 * sv, b = q1 * cv + q0 * sv;
        q0 = a; q1 = b;
        a = k0 * cv - k1 * sv; b = k1 * cv + k0 * sv;
        k0 = a; k1 = b;
    }
    __half h;
    h = __float2half_rn(q0); qhi[base] = h; qlo[base] = __float2half_rn(q0 - __half2float(h));
    h = __float2half_rn(q1); qhi[base + 1] = h; qlo[base + 1] = __float2half_rn(q1 - __half2float(h));
    h = __float2half_rn(k0); khi[base] = h; klo[base] = __float2half_rn(k0 - __half2float(h));
    h = __float2half_rn(k1); khi[base + 1] = h; klo[base + 1] = __float2half_rn(k1 - __half2float(h));
}

// ---------------- fp16 HMMA causal flash attention --------------------------
// BQ=64 (4 warps x 16 rows), BK=32, D=256. QK: 3-term compensated hi/lo.
#define FL_Q_B 32768
#define FL_KV_ST 49152
#define FL_SMEM (2 * FL_Q_B + 2 * FL_KV_ST)  // 163840

__global__ void __launch_bounds__(128) flash_h(const __half* __restrict__ Qhi,
                                               const __half* __restrict__ Qlo,
                                               const __half* __restrict__ Khi,
                                               const __half* __restrict__ Klo,
                                               const __half* __restrict__ Vg,
                                               __half* __restrict__ Og) {
    extern __shared__ char smraw[];
    uint32_t smb = smem_u32(smraw);
    const uint32_t QHI = smb, QLO = smb + FL_Q_B, KV0 = smb + 2 * FL_Q_B;

    int tid = threadIdx.x;
    int wid = tid >> 5, lane = tid & 31;
    int gid = lane >> 2, tig = lane & 3;
    int rw0 = wid * 16;

    int bh = blockIdx.x & 31;
    int qb = 31 - (blockIdx.x >> 5);  // big tiles first
    int b = bh >> 4, h = bh & 15;
    int q0 = qb * 64;
    int nkt = 2 * qb + 2;
    size_t tok0 = (size_t)b * NS;

    int a_r = lane & 15, a_c = (lane >> 4) << 3;
    int b_r = ((lane >> 4) << 3) + (lane & 7), b_c = ((lane >> 3) & 1) << 3;

#pragma unroll
    for (int i = 0; i < 16; i++) {  // Q hi+lo: 64 rows x 256
        int gi = tid + i * 128;
        int r = gi >> 5, g = gi & 31;
        uint32_t off = r * 512 + (((g & 24) | ((g ^ r) & 7)) << 4);
        size_t src = (tok0 + q0 + r) * EMBED + h * HD + g * 8;
        cp16(QHI + off, Qhi + src);
        cp16(QLO + off, Qlo + src);
    }
    auto loadkv = [&](int st, int kt) {
        uint32_t kb = KV0 + st * FL_KV_ST;
        int k0 = kt * 32;
#pragma unroll
        for (int i = 0; i < 8; i++) {
            int gi = tid + i * 128;
            int r = gi >> 5, g = gi & 31;
            uint32_t off = r * 512 + (((g & 24) | ((g ^ r) & 7)) << 4);
            size_t src = (tok0 + k0 + r) * EMBED + h * HD + g * 8;
            cp16(kb + off, Khi + src);
            cp16(kb + 16384 + off, Klo + src);
            cp16(kb + 32768 + off, Vg + src);
        }
    };
    loadkv(0, 0);
    CP_COMMIT();

    float o[32][4];
#pragma unroll
    for (int nt = 0; nt < 32; nt++)
#pragma unroll
        for (int q = 0; q < 4; q++) o[nt][q] = 0.f;
    float m0v = -1e30f, m1v = -1e30f, l0v = 0.f, l1v = 0.f;
    int rg0 = q0 + rw0 + gid;

    for (int kt = 0; kt < nkt; kt++) {
        bool have_next = (kt + 1 < nkt);
        if (have_next) { loadkv((kt + 1) & 1, kt + 1); CP_COMMIT(); cp_wait<1>(); }
        else cp_wait<0>();
        __syncthreads();

        int k0 = kt * 32;
        if (k0 <= q0 + rw0 + 15) {
            uint32_t kb = KV0 + (kt & 1) * FL_KV_ST;
            uint32_t klb = kb + 16384, vb = kb + 32768;

            float s4[4][4];
#pragma unroll
            for (int nt = 0; nt < 4; nt++)
#pragma unroll
                for (int q = 0; q < 4; q++) s4[nt][q] = 0.f;

#pragma unroll
            for (int kc = 0; kc < 16; kc++) {
                int kk = kc * 16;
                uint32_t ah[4], al[4], bh4[2][4], bl4[2][4];
                ldsm4(ah, QHI + swz512(rw0 + a_r, kk + a_c));
                ldsm4(al, QLO + swz512(rw0 + a_r, kk + a_c));
#pragma unroll
                for (int np = 0; np < 2; np++) {
                    ldsm4(bh4[np], kb + swz512(np * 16 + b_r, kk + b_c));
                    ldsm4(bl4[np], klb + swz512(np * 16 + b_r, kk + b_c));
                }
#pragma unroll
                for (int np = 0; np < 2; np++) {
                    mma16(s4[2 * np], ah, &bh4[np][0]);
                    mma16(s4[2 * np], ah, &bl4[np][0]);
                    mma16(s4[2 * np], al, &bh4[np][0]);
                    mma16(s4[2 * np + 1], ah, &bh4[np][2]);
                    mma16(s4[2 * np + 1], ah, &bl4[np][2]);
                    mma16(s4[2 * np + 1], al, &bh4[np][2]);
                }
            }

            bool needmask = (k0 + 31 > q0 + rw0);
#pragma unroll
            for (int nt = 0; nt < 4; nt++) {
#pragma unroll
                for (int q = 0; q < 4; q++) s4[nt][q] *= 0.0625f;
                if (needmask) {
                    int c0 = k0 + nt * 8 + 2 * tig;
                    if (c0 > rg0) s4[nt][0] = -1e30f;
                    if (c0 + 1 > rg0) s4[nt][1] = -1e30f;
                    if (c0 > rg0 + 8) s4[nt][2] = -1e30f;
                    if (c0 + 1 > rg0 + 8) s4[nt][3] = -1e30f;
                }
            }

            float mx0 = -1e30f, mx1 = -1e30f;
#pragma unroll
            for (int nt = 0; nt < 4; nt++) {
                mx0 = fmaxf(mx0, fmaxf(s4[nt][0], s4[nt][1]));
                mx1 = fmaxf(mx1, fmaxf(s4[nt][2], s4[nt][3]));
            }
            mx0 = fmaxf(mx0, __shfl_xor_sync(0xffffffffu, mx0, 1));
            mx0 = fmaxf(mx0, __shfl_xor_sync(0xffffffffu, mx0, 2));
            mx1 = fmaxf(mx1, __shfl_xor_sync(0xffffffffu, mx1, 1));
            mx1 = fmaxf(mx1, __shfl_xor_sync(0xffffffffu, mx1, 2));
            float mn0 = fmaxf(m0v, mx0), mn1 = fmaxf(m1v, mx1);
            float cor0 = __expf(m0v - mn0), cor1 = __expf(m1v - mn1);
            m0v = mn0; m1v = mn1;

            float sum0 = 0.f, sum1 = 0.f;
            uint32_t ph[4][2];
#pragma unroll
            for (int nt = 0; nt < 4; nt++) {
                float p0 = __expf(s4[nt][0] - mn0);
                float p1 = __expf(s4[nt][1] - mn0);
                float p2 = __expf(s4[nt][2] - mn1);
                float p3 = __expf(s4[nt][3] - mn1);
                sum0 += p0 + p1; sum1 += p2 + p3;
                __half2 h01 = __floats2half2_rn(p0, p1);
                __half2 h23 = __floats2half2_rn(p2, p3);
                ph[nt][0] = *reinterpret_cast<uint32_t*>(&h01);
                ph[nt][1] = *reinterpret_cast<uint32_t*>(&h23);
            }
            sum0 += __shfl_xor_sync(0xffffffffu, sum0, 1);
            sum0 += __shfl_xor_sync(0xffffffffu, sum0, 2);
            sum1 += __shfl_xor_sync(0xffffffffu, sum1, 1);
            sum1 += __shfl_xor_sync(0xffffffffu, sum1, 2);
            l0v = l0v * cor0 + sum0;
            l1v = l1v * cor1 + sum1;

#pragma unroll
            for (int nt = 0; nt < 32; nt++) {
                o[nt][0] *= cor0; o[nt][1] *= cor0;
                o[nt][2] *= cor1; o[nt][3] *= cor1;
            }

#pragma unroll
            for (int kc = 0; kc < 2; kc++) {
                uint32_t a4[4] = {ph[2 * kc][0], ph[2 * kc][1],
                                  ph[2 * kc + 1][0], ph[2 * kc + 1][1]};
#pragma unroll
                for (int dp = 0; dp < 16; dp++) {
                    uint32_t b4[4];
                    ldsm4t(b4, vb + swz512(kc * 16 + a_r, dp * 16 + a_c));
                    mma16(o[2 * dp], a4, &b4[0]);
                    mma16(o[2 * dp + 1], a4, &b4[2]);
                }
            }
        }
        __syncthreads();
    }

    float inv0 = 1.f / l0v, inv1 = 1.f / l1v;
    __half* r0p = Og + (tok0 + rg0) * EMBED + h * HD;
    __half* r1p = Og + (tok0 + rg0 + 8) * EMBED + h * HD;
#pragma unroll
    for (int nt = 0; nt < 32; nt++) {
        int col = nt * 8 + 2 * tig;
        *reinterpret_cast<__half2*>(r0p + col) =
            __floats2half2_rn(o[nt][0] * inv0, o[nt][1] * inv0);
        *reinterpret_cast<__half2*>(r1p + col) =
            __floats2half2_rn(o[nt][2] * inv1, o[nt][3] * inv1);
    }
}

// ---------------------------------------------------------------------------
extern "C" void kernel_launch(void* const* d_in, const int* in_sizes, int n_in,
                              void* d_out, int out_size) {
    const float* hs = (const float*)d_in[0];
    const int* pid = (const int*)d_in[1];
    const float* qw = (const float*)d_in[2];
    const float* kw = (const float*)d_in[3];
    const float* vw = (const float*)d_in[4];
    const float* ow = (const float*)d_in[5];
    const float* emb = (const float*)d_in[6];
    float* out = (float*)d_out;

    __half *hs_h, *wq_h, *wk_h, *wv_h, *wo_h, *qhi, *qlo, *khi, *klo, *vh, *att;
    float *qf, *kf;
    cudaGetSymbolAddress((void**)&hs_h, g_hs_h);
    cudaGetSymbolAddress((void**)&wq_h, g_wq_h);
    cudaGetSymbolAddress((void**)&wk_h, g_wk_h);
    cudaGetSymbolAddress((void**)&wv_h, g_wv_h);
    cudaGetSymbolAddress((void**)&wo_h, g_wo_h);
    cudaGetSymbolAddress((void**)&qhi, g_qhi);
    cudaGetSymbolAddress((void**)&qlo, g_qlo);
    cudaGetSymbolAddress((void**)&khi, g_khi);
    cudaGetSymbolAddress((void**)&klo, g_klo);
    cudaGetSymbolAddress((void**)&vh, g_v);
    cudaGetSymbolAddress((void**)&att, g_att);
    cudaGetSymbolAddress((void**)&qf, g_qf);
    cudaGetSymbolAddress((void**)&kf, g_kf);

    cudaFuncSetAttribute(gemm_h<float>, cudaFuncAttributeMaxDynamicSharedMemorySize, GEMM_SMEM);
    cudaFuncSetAttribute(gemm_h<__half>, cudaFuncAttributeMaxDynamicSharedMemorySize, GEMM_SMEM);
    cudaFuncSetAttribute(flash_h, cudaFuncAttributeMaxDynamicSharedMemorySize, FL_SMEM);

    int cb = (int)(NELEM / 2 / 256);
    f2h<<<cb, 256>>>(hs, hs_h, (int)(NELEM / 2));
    f2h<<<cb, 256>>>(qw, wq_h, (int)(NELEM / 2));
    f2h<<<cb, 256>>>(kw, wk_h, (int)(NELEM / 2));
    f2h<<<cb, 256>>>(vw, wv_h, (int)(NELEM / 2));
    f2h<<<cb, 256>>>(ow, wo_h, (int)(NELEM / 2));

    dim3 gg(32, 32);
    gemm_h<float><<<gg, 256, GEMM_SMEM>>>(hs_h, wq_h, qf);
    gemm_h<float><<<gg, 256, GEMM_SMEM>>>(hs_h, wk_h, kf);
    gemm_h<__half><<<gg, 256, GEMM_SMEM>>>(hs_h, wv_h, vh);

    rot_split<<<(NTOK * 16 * 128) / 256, 256>>>(pid, emb, qf, kf, qhi, qlo, khi, klo);

    flash_h<<<1024, 128, FL_SMEM>>>(qhi, qlo, khi, klo, vh, att);

    gemm_h<float><<<gg, 256, GEMM_SMEM>>>(att, wo_h, out);
}

// round 6
// speedup vs baseline: 9.6101x; 1.0492x over previous
#include <cuda_runtime.h>
#include <cuda_fp16.h>
#include <cstdint>
#include <math.h>

#define EMBED 4096
#define NH 16
#define HD 256
#define NB 2
#define NS 2048
#define NTOK (NB * NS)
#define NELEM ((size_t)NTOK * EMBED)

__device__ __half g_hs_h[NELEM];
__device__ __half g_wq_h[NELEM];
__device__ __half g_wk_h[NELEM];
__device__ __half g_wv_h[NELEM];
__device__ __half g_wo_h[NELEM];
__device__ float  g_qf[NELEM];
__device__ float  g_kf[NELEM];
__device__ __half g_qhi[NELEM];
__device__ __half g_qlo[NELEM];
__device__ __half g_khi[NELEM];
__device__ __half g_klo[NELEM];
__device__ __half g_v[NELEM];
__device__ __half g_att[NELEM];

// ---------------- PTX helpers (baseline ISA; tcgen05 is sm_103a-gated) ------
__device__ __forceinline__ uint32_t smem_u32(const void* p) {
    uint32_t a;
    asm("{ .reg .u64 t; cvta.to.shared.u64 t, %1; cvt.u32.u64 %0, t; }"
        : "=r"(a) : "l"(p));
    return a;
}
__device__ __forceinline__ void cp16(uint32_t s, const void* g) {
    asm volatile("cp.async.cg.shared.global [%0], [%1], 16;\n" ::"r"(s), "l"(g));
}
#define CP_COMMIT() asm volatile("cp.async.commit_group;\n" ::: "memory")
template <int N>
__device__ __forceinline__ void cp_wait() {
    asm volatile("cp.async.wait_group %0;\n" ::"n"(N) : "memory");
}
__device__ __forceinline__ void ldsm4(uint32_t* r, uint32_t a) {
    asm volatile("ldmatrix.sync.aligned.m8n8.x4.shared.b16 {%0,%1,%2,%3}, [%4];"
                 : "=r"(r[0]), "=r"(r[1]), "=r"(r[2]), "=r"(r[3]) : "r"(a));
}
__device__ __forceinline__ void ldsm4t(uint32_t* r, uint32_t a) {
    asm volatile("ldmatrix.sync.aligned.m8n8.x4.trans.shared.b16 {%0,%1,%2,%3}, [%4];"
                 : "=r"(r[0]), "=r"(r[1]), "=r"(r[2]), "=r"(r[3]) : "r"(a));
}
__device__ __forceinline__ void mma16(float* c, const uint32_t* a, const uint32_t* b) {
    asm volatile(
        "mma.sync.aligned.m16n8k16.row.col.f32.f16.f16.f32 "
        "{%0,%1,%2,%3}, {%4,%5,%6,%7}, {%8,%9}, {%0,%1,%2,%3};"
        : "+f"(c[0]), "+f"(c[1]), "+f"(c[2]), "+f"(c[3])
        : "r"(a[0]), "r"(a[1]), "r"(a[2]), "r"(a[3]), "r"(b[0]), "r"(b[1]));
}
__device__ __forceinline__ uint32_t swz128(int r, int c) {  // row = 64 halves
    return (uint32_t)(r * 128 + ((((c >> 3) ^ r) & 7) << 4) + ((c & 7) << 1));
}
__device__ __forceinline__ uint32_t swz512(int r, int c) {  // row = 256 halves
    int g = c >> 3;
    return (uint32_t)(r * 512 + (((g & 24) | ((g ^ r) & 7)) << 4) + ((c & 7) << 1));
}

// ---------------- fp32 -> fp16 (32B read / 16B write per thread) ------------
__global__ void f2h4(const float4* __restrict__ s, uint4* __restrict__ d, int n8) {
    int i = blockIdx.x * blockDim.x + threadIdx.x;
    if (i < n8) {
        float4 a = s[2 * i], b = s[2 * i + 1];
        __half2 h0 = __floats2half2_rn(a.x, a.y);
        __half2 h1 = __floats2half2_rn(a.z, a.w);
        __half2 h2 = __floats2half2_rn(b.x, b.y);
        __half2 h3 = __floats2half2_rn(b.z, b.w);
        uint4 o;
        o.x = *reinterpret_cast<uint32_t*>(&h0);
        o.y = *reinterpret_cast<uint32_t*>(&h1);
        o.z = *reinterpret_cast<uint32_t*>(&h2);
        o.w = *reinterpret_cast<uint32_t*>(&h3);
        d[i] = o;
    }
}

// ---------------- fp16 HMMA NT GEMM core (128x128 CTA, BK=64, 3 stages) -----
#define G_STAGE_B 32768
#define GEMM_SMEM (3 * G_STAGE_B)

// Fused QKV: gridDim (32,32,3); z selects weight and destination.
__global__ void __launch_bounds__(256, 2) gemm_qkv(const __half* __restrict__ A,
                                                   const __half* __restrict__ Wq,
                                                   const __half* __restrict__ Wk,
                                                   const __half* __restrict__ Wv,
                                                   float* __restrict__ Cq,
                                                   float* __restrict__ Ck,
                                                   __half* __restrict__ Cv) {
    extern __shared__ char smraw[];
    uint32_t smb = smem_u32(smraw);
    int z = blockIdx.z;
    const __half* B = (z == 0) ? Wq : (z == 1) ? Wk : Wv;

    int tid = threadIdx.x;
    int wid = tid >> 5, lane = tid & 31;
    int gid = lane >> 2, tig = lane & 3;
    int wm = (wid >> 2) * 64, wn = (wid & 3) * 32;
    int m0 = blockIdx.y * 128, n0 = blockIdx.x * 128;
    int a_r = lane & 15, a_c = (lane >> 4) << 3;
    int b_r = ((lane >> 4) << 3) + (lane & 7), b_c = ((lane >> 3) & 1) << 3;

    float acc[4][4][4];
#pragma unroll
    for (int i = 0; i < 4; i++)
#pragma unroll
        for (int j = 0; j < 4; j++)
#pragma unroll
            for (int q = 0; q < 4; q++) acc[i][j][q] = 0.f;

    auto loadst = [&](int st, int k0) {
        uint32_t ab = smb + st * G_STAGE_B, bb = ab + 16384;
#pragma unroll
        for (int i = 0; i < 4; i++) {
            int gi = tid + i * 256;
            int r = gi >> 3, g = gi & 7;
            uint32_t off = r * 128 + (((g ^ r) & 7) << 4);
            cp16(ab + off, A + (size_t)(m0 + r) * EMBED + k0 + g * 8);
            cp16(bb + off, B + (size_t)(n0 + r) * EMBED + k0 + g * 8);
        }
    };

    loadst(0, 0); CP_COMMIT();
    loadst(1, 64); CP_COMMIT();

    int s = 0;
    for (int c = 0; c < 64; c++) {
        cp_wait<1>();
        __syncthreads();
        if (c + 2 < 64) loadst((s + 2) % 3, (c + 2) * 64);
        CP_COMMIT();

        uint32_t ab = smb + s * G_STAGE_B, bb = ab + 16384;
#pragma unroll
        for (int kc = 0; kc < 4; kc++) {
            int kk = kc * 16;
            uint32_t af[4][4], bf[2][4];
#pragma unroll
            for (int mi = 0; mi < 4; mi++)
                ldsm4(af[mi], ab + swz128(wm + mi * 16 + a_r, kk + a_c));
#pragma unroll
            for (int np = 0; np < 2; np++)
                ldsm4(bf[np], bb + swz128(wn + np * 16 + b_r, kk + b_c));
#pragma unroll
            for (int mi = 0; mi < 4; mi++)
#pragma unroll
                for (int ni = 0; ni < 4; ni++)
                    mma16(acc[mi][ni], af[mi], &bf[ni >> 1][(ni & 1) * 2]);
        }
        __syncthreads();
        if (++s == 3) s = 0;
    }

    if (z < 2) {
        float* C = (z == 0) ? Cq : Ck;
#pragma unroll
        for (int mi = 0; mi < 4; mi++) {
            int r0 = m0 + wm + mi * 16 + gid;
#pragma unroll
            for (int ni = 0; ni < 4; ni++) {
                int col = n0 + wn + ni * 8 + tig * 2;
                *reinterpret_cast<float2*>(C + (size_t)r0 * EMBED + col) =
                    make_float2(acc[mi][ni][0], acc[mi][ni][1]);
                *reinterpret_cast<float2*>(C + (size_t)(r0 + 8) * EMBED + col) =
                    make_float2(acc[mi][ni][2], acc[mi][ni][3]);
            }
        }
    } else {
#pragma unroll
        for (int mi = 0; mi < 4; mi++) {
            int r0 = m0 + wm + mi * 16 + gid;
#pragma unroll
            for (int ni = 0; ni < 4; ni++) {
                int col = n0 + wn + ni * 8 + tig * 2;
                *reinterpret_cast<__half2*>(Cv + (size_t)r0 * EMBED + col) =
                    __floats2half2_rn(acc[mi][ni][0], acc[mi][ni][1]);
                *reinterpret_cast<__half2*>(Cv + (size_t)(r0 + 8) * EMBED + col) =
                    __floats2half2_rn(acc[mi][ni][2], acc[mi][ni][3]);
            }
        }
    }
}

// Single GEMM (out projection): half in, float out.
__global__ void __launch_bounds__(256, 2) gemm_h(const __half* __restrict__ A,
                                                 const __half* __restrict__ B,
                                                 float* __restrict__ C) {
    extern __shared__ char smraw[];
    uint32_t smb = smem_u32(smraw);
    int tid = threadIdx.x;
    int wid = tid >> 5, lane = tid & 31;
    int gid = lane >> 2, tig = lane & 3;
    int wm = (wid >> 2) * 64, wn = (wid & 3) * 32;
    int m0 = blockIdx.y * 128, n0 = blockIdx.x * 128;
    int a_r = lane & 15, a_c = (lane >> 4) << 3;
    int b_r = ((lane >> 4) << 3) + (lane & 7), b_c = ((lane >> 3) & 1) << 3;

    float acc[4][4][4];
#pragma unroll
    for (int i = 0; i < 4; i++)
#pragma unroll
        for (int j = 0; j < 4; j++)
#pragma unroll
            for (int q = 0; q < 4; q++) acc[i][j][q] = 0.f;

    auto loadst = [&](int st, int k0) {
        uint32_t ab = smb + st * G_STAGE_B, bb = ab + 16384;
#pragma unroll
        for (int i = 0; i < 4; i++) {
            int gi = tid + i * 256;
            int r = gi >> 3, g = gi & 7;
            uint32_t off = r * 128 + (((g ^ r) & 7) << 4);
            cp16(ab + off, A + (size_t)(m0 + r) * EMBED + k0 + g * 8);
            cp16(bb + off, B + (size_t)(n0 + r) * EMBED + k0 + g * 8);
        }
    };

    loadst(0, 0); CP_COMMIT();
    loadst(1, 64); CP_COMMIT();

    int s = 0;
    for (int c = 0; c < 64; c++) {
        cp_wait<1>();
        __syncthreads();
        if (c + 2 < 64) loadst((s + 2) % 3, (c + 2) * 64);
        CP_COMMIT();

        uint32_t ab = smb + s * G_STAGE_B, bb = ab + 16384;
#pragma unroll
        for (int kc = 0; kc < 4; kc++) {
            int kk = kc * 16;
            uint32_t af[4][4], bf[2][4];
#pragma unroll
            for (int mi = 0; mi < 4; mi++)
                ldsm4(af[mi], ab + swz128(wm + mi * 16 + a_r, kk + a_c));
#pragma unroll
            for (int np = 0; np < 2; np++)
                ldsm4(bf[np], bb + swz128(wn + np * 16 + b_r, kk + b_c));
#pragma unroll
            for (int mi = 0; mi < 4; mi++)
#pragma unroll
                for (int ni = 0; ni < 4; ni++)
                    mma16(acc[mi][ni], af[mi], &bf[ni >> 1][(ni & 1) * 2]);
        }
        __syncthreads();
        if (++s == 3) s = 0;
    }

#pragma unroll
    for (int mi = 0; mi < 4; mi++) {
        int r0 = m0 + wm + mi * 16 + gid;
#pragma unroll
        for (int ni = 0; ni < 4; ni++) {
            int col = n0 + wn + ni * 8 + tig * 2;
            *reinterpret_cast<float2*>(C + (size_t)r0 * EMBED + col) =
                make_float2(acc[mi][ni][0], acc[mi][ni][1]);
            *reinterpret_cast<float2*>(C + (size_t)(r0 + 8) * EMBED + col) =
                make_float2(acc[mi][ni][2], acc[mi][ni][3]);
        }
    }
}

// ---------------- rotary + hi/lo split --------------------------------------
__global__ void rot_split(const int* __restrict__ pid, const float* __restrict__ emb,
                          const float* __restrict__ qf, const float* __restrict__ kf,
                          __half* __restrict__ qhi, __half* __restrict__ qlo,
                          __half* __restrict__ khi, __half* __restrict__ klo) {
    int idx = blockIdx.x * blockDim.x + threadIdx.x;  // NTOK*16*128
    int p = idx & 127;
    int hh = (idx >> 7) & 15;
    int tok = idx >> 11;
    size_t base = (size_t)tok * EMBED + hh * HD + 2 * p;
    float q0 = qf[base], q1 = qf[base + 1];
    float k0 = kf[base], k1 = kf[base + 1];
    if (p < 32) {
        int pos = pid[tok];
        float sv = emb[pos * 64 + p], cv = emb[pos * 64 + 32 + p];
        float a = q0 * cv - q1 * sv, b = q1 * cv + q0 * sv;
        q0 = a; q1 = b;
        a = k0 * cv - k1 * sv; b = k1 * cv + k0 * sv;
        k0 = a; k1 = b;
    }
    __half h;
    h = __float2half_rn(q0); qhi[base] = h; qlo[base] = __float2half_rn(q0 - __half2float(h));
    h = __float2half_rn(q1); qhi[base + 1] = h; qlo[base + 1] = __float2half_rn(q1 - __half2float(h));
    h = __float2half_rn(k0); khi[base] = h; klo[base] = __float2half_rn(k0 - __half2float(h));
    h = __float2half_rn(k1); khi[base + 1] = h; klo[base + 1] = __float2half_rn(k1 - __half2float(h));
}

// ---------------- fp16 HMMA causal flash attention, BQ=128 ------------------
// 8 warps (16 q-rows each), BK=32, D=256. QK: 3-term compensated hi/lo.
#define FL_Q_B 65536
#define FL_KV_ST 49152
#define FL_SMEM (2 * FL_Q_B + 2 * FL_KV_ST)  // 229376

__global__ void __launch_bounds__(256) flash_h(const __half* __restrict__ Qhi,
                                               const __half* __restrict__ Qlo,
                                               const __half* __restrict__ Khi,
                                               const __half* __restrict__ Klo,
                                               const __half* __restrict__ Vg,
                                               __half* __restrict__ Og) {
    extern __shared__ char smraw[];
    uint32_t smb = smem_u32(smraw);
    const uint32_t QHI = smb, QLO = smb + FL_Q_B, KV0 = smb + 2 * FL_Q_B;

    int tid = threadIdx.x;
    int wid = tid >> 5, lane = tid & 31;
    int gid = lane >> 2, tig = lane & 3;
    int rw0 = wid * 16;

    int bh = blockIdx.x & 31;
    int qb = 15 - (blockIdx.x >> 5);  // big tiles first
    int b = bh >> 4, h = bh & 15;
    int q0 = qb * 128;
    int nkt = 4 * qb + 4;
    size_t tok0 = (size_t)b * NS;

    int a_r = lane & 15, a_c = (lane >> 4) << 3;
    int b_r = ((lane >> 4) << 3) + (lane & 7), b_c = ((lane >> 3) & 1) << 3;

#pragma unroll
    for (int i = 0; i < 16; i++) {  // Q hi+lo: 128 rows x 256 (4096 cp16 each)
        int gi = tid + i * 256;
        int r = gi >> 5, g = gi & 31;
        uint32_t off = r * 512 + (((g & 24) | ((g ^ r) & 7)) << 4);
        size_t src = (tok0 + q0 + r) * EMBED + h * HD + g * 8;
        cp16(QHI + off, Qhi + src);
        cp16(QLO + off, Qlo + src);
    }
    auto loadkv = [&](int st, int kt) {
        uint32_t kb = KV0 + st * FL_KV_ST;
        int k0 = kt * 32;
#pragma unroll
        for (int i = 0; i < 4; i++) {
            int gi = tid + i * 256;
            int r = gi >> 5, g = gi & 31;
            uint32_t off = r * 512 + (((g & 24) | ((g ^ r) & 7)) << 4);
            size_t src = (tok0 + k0 + r) * EMBED + h * HD + g * 8;
            cp16(kb + off, Khi + src);
            cp16(kb + 16384 + off, Klo + src);
            cp16(kb + 32768 + off, Vg + src);
        }
    };
    loadkv(0, 0);
    CP_COMMIT();

    float o[32][4];
#pragma unroll
    for (int nt = 0; nt < 32; nt++)
#pragma unroll
        for (int q = 0; q < 4; q++) o[nt][q] = 0.f;
    float m0v = -1e30f, m1v = -1e30f, l0v = 0.f, l1v = 0.f;
    int rg0 = q0 + rw0 + gid;

    for (int kt = 0; kt < nkt; kt++) {
        bool have_next = (kt + 1 < nkt);
        if (have_next) { loadkv((kt + 1) & 1, kt + 1); CP_COMMIT(); cp_wait<1>(); }
        else cp_wait<0>();
        __syncthreads();

        int k0 = kt * 32;
        if (k0 <= q0 + rw0 + 15) {
            uint32_t kb = KV0 + (kt & 1) * FL_KV_ST;
            uint32_t klb = kb + 16384, vb = kb + 32768;

            float s4[4][4];
#pragma unroll
            for (int nt = 0; nt < 4; nt++)
#pragma unroll
                for (int q = 0; q < 4; q++) s4[nt][q] = 0.f;

#pragma unroll
            for (int kc = 0; kc < 16; kc++) {
                int kk = kc * 16;
                uint32_t ah[4], al[4], bh4[2][4], bl4[2][4];
                ldsm4(ah, QHI + swz512(rw0 + a_r, kk + a_c));
                ldsm4(al, QLO + swz512(rw0 + a_r, kk + a_c));
#pragma unroll
                for (int np = 0; np < 2; np++) {
                    ldsm4(bh4[np], kb + swz512(np * 16 + b_r, kk + b_c));
                    ldsm4(bl4[np], klb + swz512(np * 16 + b_r, kk + b_c));
                }
#pragma unroll
                for (int np = 0; np < 2; np++) {
                    mma16(s4[2 * np], ah, &bh4[np][0]);
                    mma16(s4[2 * np], ah, &bl4[np][0]);
                    mma16(s4[2 * np], al, &bh4[np][0]);
                    mma16(s4[2 * np + 1], ah, &bh4[np][2]);
                    mma16(s4[2 * np + 1], ah, &bl4[np][2]);
                    mma16(s4[2 * np + 1], al, &bh4[np][2]);
                }
            }

            bool needmask = (k0 + 31 > q0 + rw0);
#pragma unroll
            for (int nt = 0; nt < 4; nt++) {
#pragma unroll
                for (int q = 0; q < 4; q++) s4[nt][q] *= 0.0625f;
                if (needmask) {
                    int c0 = k0 + nt * 8 + 2 * tig;
                    if (c0 > rg0) s4[nt][0] = -1e30f;
                    if (c0 + 1 > rg0) s4[nt][1] = -1e30f;
                    if (c0 > rg0 + 8) s4[nt][2] = -1e30f;
                    if (c0 + 1 > rg0 + 8) s4[nt][3] = -1e30f;
                }
            }

            float mx0 = -1e30f, mx1 = -1e30f;
#pragma unroll
            for (int nt = 0; nt < 4; nt++) {
                mx0 = fmaxf(mx0, fmaxf(s4[nt][0], s4[nt][1]));
                mx1 = fmaxf(mx1, fmaxf(s4[nt][2], s4[nt][3]));
            }
            mx0 = fmaxf(mx0, __shfl_xor_sync(0xffffffffu, mx0, 1));
            mx0 = fmaxf(mx0, __shfl_xor_sync(0xffffffffu, mx0, 2));
            mx1 = fmaxf(mx1, __shfl_xor_sync(0xffffffffu, mx1, 1));
            mx1 = fmaxf(mx1, __shfl_xor_sync(0xffffffffu, mx1, 2));
            float mn0 = fmaxf(m0v, mx0), mn1 = fmaxf(m1v, mx1);
            float cor0 = __expf(m0v - mn0), cor1 = __expf(m1v - mn1);
            m0v = mn0; m1v = mn1;

            float sum0 = 0.f, sum1 = 0.f;
            uint32_t ph[4][2];
#pragma unroll
            for (int nt = 0; nt < 4; nt++) {
                float p0 = __expf(s4[nt][0] - mn0);
                float p1 = __expf(s4[nt][1] - mn0);
                float p2 = __expf(s4[nt][2] - mn1);
                float p3 = __expf(s4[nt][3] - mn1);
                sum0 += p0 + p1; sum1 += p2 + p3;
                __half2 h01 = __floats2half2_rn(p0, p1);
                __half2 h23 = __floats2half2_rn(p2, p3);
                ph[nt][0] = *reinterpret_cast<uint32_t*>(&h01);
                ph[nt][1] = *reinterpret_cast<uint32_t*>(&h23);
            }
            sum0 += __shfl_xor_sync(0xffffffffu, sum0, 1);
            sum0 += __shfl_xor_sync(0xffffffffu, sum0, 2);
            sum1 += __shfl_xor_sync(0xffffffffu, sum1, 1);
            sum1 += __shfl_xor_sync(0xffffffffu, sum1, 2);
            l0v = l0v * cor0 + sum0;
            l1v = l1v * cor1 + sum1;

#pragma unroll
            for (int nt = 0; nt < 32; nt++) {
                o[nt][0] *= cor0; o[nt][1] *= cor0;
                o[nt][2] *= cor1; o[nt][3] *= cor1;
            }

#pragma unroll
            for (int kc = 0; kc < 2; kc++) {
                uint32_t a4[4] = {ph[2 * kc][0], ph[2 * kc][1],
                                  ph[2 * kc + 1][0], ph[2 * kc + 1][1]};
#pragma unroll
                for (int dp = 0; dp < 16; dp++) {
                    uint32_t b4[4];
                    ldsm4t(b4, vb + swz512(kc * 16 + a_r, dp * 16 + a_c));
                    mma16(o[2 * dp], a4, &b4[0]);
                    mma16(o[2 * dp + 1], a4, &b4[2]);
                }
            }
        }
        __syncthreads();
    }

    float inv0 = 1.f / l0v, inv1 = 1.f / l1v;
    __half* r0p = Og + (tok0 + rg0) * EMBED + h * HD;
    __half* r1p = Og + (tok0 + rg0 + 8) * EMBED + h * HD;
#pragma unroll
    for (int nt = 0; nt < 32; nt++) {
        int col = nt * 8 + 2 * tig;
        *reinterpret_cast<__half2*>(r0p + col) =
            __floats2half2_rn(o[nt][0] * inv0, o[nt][1] * inv0);
        *reinterpret_cast<__half2*>(r1p + col) =
            __floats2half2_rn(o[nt][2] * inv1, o[nt][3] * inv1);
    }
}

// ---------------------------------------------------------------------------
extern "C" void kernel_launch(void* const* d_in, const int* in_sizes, int n_in,
                              void* d_out, int out_size) {
    const float* hs = (const float*)d_in[0];
    const int* pid = (const int*)d_in[1];
    const float* qw = (const float*)d_in[2];
    const float* kw = (const float*)d_in[3];
    const float* vw = (const float*)d_in[4];
    const float* ow = (const float*)d_in[5];
    const float* emb = (const float*)d_in[6];
    float* out = (float*)d_out;

    __half *hs_h, *wq_h, *wk_h, *wv_h, *wo_h, *qhi, *qlo, *khi, *klo, *vh, *att;
    float *qf, *kf;
    cudaGetSymbolAddress((void**)&hs_h, g_hs_h);
    cudaGetSymbolAddress((void**)&wq_h, g_wq_h);
    cudaGetSymbolAddress((void**)&wk_h, g_wk_h);
    cudaGetSymbolAddress((void**)&wv_h, g_wv_h);
    cudaGetSymbolAddress((void**)&wo_h, g_wo_h);
    cudaGetSymbolAddress((void**)&qhi, g_qhi);
    cudaGetSymbolAddress((void**)&qlo, g_qlo);
    cudaGetSymbolAddress((void**)&khi, g_khi);
    cudaGetSymbolAddress((void**)&klo, g_klo);
    cudaGetSymbolAddress((void**)&vh, g_v);
    cudaGetSymbolAddress((void**)&att, g_att);
    cudaGetSymbolAddress((void**)&qf, g_qf);
    cudaGetSymbolAddress((void**)&kf, g_kf);

    cudaFuncSetAttribute(gemm_qkv, cudaFuncAttributeMaxDynamicSharedMemorySize, GEMM_SMEM);
    cudaFuncSetAttribute(gemm_h, cudaFuncAttributeMaxDynamicSharedMemorySize, GEMM_SMEM);
    cudaFuncSetAttribute(flash_h, cudaFuncAttributeMaxDynamicSharedMemorySize, FL_SMEM);

    int n8 = (int)(NELEM / 8);
    int cb = n8 / 256;
    f2h4<<<cb, 256>>>((const float4*)hs, (uint4*)hs_h, n8);
    f2h4<<<cb, 256>>>((const float4*)qw, (uint4*)wq_h, n8);
    f2h4<<<cb, 256>>>((const float4*)kw, (uint4*)wk_h, n8);
    f2h4<<<cb, 256>>>((const float4*)vw, (uint4*)wv_h, n8);
    f2h4<<<cb, 256>>>((const float4*)ow, (uint4*)wo_h, n8);

    gemm_qkv<<<dim3(32, 32, 3), 256, GEMM_SMEM>>>(hs_h, wq_h, wk_h, wv_h, qf, kf, vh);

    rot_split<<<(NTOK * 16 * 128) / 256, 256>>>(pid, emb, qf, kf, qhi, qlo, khi, klo);

    flash_h<<<512, 256, FL_SMEM>>>(qhi, qlo, khi, klo, vh, att);

    gemm_h<<<dim3(32, 32), 256, GEMM_SMEM>>>(att, wo_h, out);
}

// round 7
// speedup vs baseline: 9.8517x; 1.0251x over previous
#include <cuda_runtime.h>
#include <cuda_fp16.h>
#include <cstdint>
#include <math.h>

#define EMBED 4096
#define NH 16
#define HD 256
#define NB 2
#define NS 2048
#define NTOK (NB * NS)
#define NELEM ((size_t)NTOK * EMBED)

__device__ __half g_hs_h[NELEM];
__device__ __half g_wq_h[NELEM];
__device__ __half g_wk_h[NELEM];
__device__ __half g_wv_h[NELEM];
__device__ __half g_wo_h[NELEM];
__device__ __half g_qhi[NELEM];
__device__ __half g_qlo[NELEM];
__device__ __half g_khi[NELEM];
__device__ __half g_klo[NELEM];
__device__ __half g_v[NELEM];
__device__ __half g_att[NELEM];

// ---------------- PTX helpers (baseline ISA; tcgen05 is sm_103a-gated) ------
__device__ __forceinline__ uint32_t smem_u32(const void* p) {
    uint32_t a;
    asm("{ .reg .u64 t; cvta.to.shared.u64 t, %1; cvt.u32.u64 %0, t; }"
        : "=r"(a) : "l"(p));
    return a;
}
__device__ __forceinline__ void cp16(uint32_t s, const void* g) {
    asm volatile("cp.async.cg.shared.global [%0], [%1], 16;\n" ::"r"(s), "l"(g));
}
#define CP_COMMIT() asm volatile("cp.async.commit_group;\n" ::: "memory")
template <int N>
__device__ __forceinline__ void cp_wait() {
    asm volatile("cp.async.wait_group %0;\n" ::"n"(N) : "memory");
}
__device__ __forceinline__ void ldsm4(uint32_t* r, uint32_t a) {
    asm volatile("ldmatrix.sync.aligned.m8n8.x4.shared.b16 {%0,%1,%2,%3}, [%4];"
                 : "=r"(r[0]), "=r"(r[1]), "=r"(r[2]), "=r"(r[3]) : "r"(a));
}
__device__ __forceinline__ void ldsm4t(uint32_t* r, uint32_t a) {
    asm volatile("ldmatrix.sync.aligned.m8n8.x4.trans.shared.b16 {%0,%1,%2,%3}, [%4];"
                 : "=r"(r[0]), "=r"(r[1]), "=r"(r[2]), "=r"(r[3]) : "r"(a));
}
__device__ __forceinline__ void mma16(float* c, const uint32_t* a, const uint32_t* b) {
    asm volatile(
        "mma.sync.aligned.m16n8k16.row.col.f32.f16.f16.f32 "
        "{%0,%1,%2,%3}, {%4,%5,%6,%7}, {%8,%9}, {%0,%1,%2,%3};"
        : "+f"(c[0]), "+f"(c[1]), "+f"(c[2]), "+f"(c[3])
        : "r"(a[0]), "r"(a[1]), "r"(a[2]), "r"(a[3]), "r"(b[0]), "r"(b[1]));
}
__device__ __forceinline__ uint32_t swz128(int r, int c) {  // row = 64 halves
    return (uint32_t)(r * 128 + ((((c >> 3) ^ r) & 7) << 4) + ((c & 7) << 1));
}
__device__ __forceinline__ uint32_t swz512(int r, int c) {  // row = 256 halves
    int g = c >> 3;
    return (uint32_t)(r * 512 + (((g & 24) | ((g ^ r) & 7)) << 4) + ((c & 7) << 1));
}
__device__ __forceinline__ __half2 split_pair(float v0, float v1, __half2* lo) {
    __half h0 = __float2half_rn(v0), h1 = __float2half_rn(v1);
    *lo = __halves2half2(__float2half_rn(v0 - __half2float(h0)),
                         __float2half_rn(v1 - __half2float(h1)));
    return __halves2half2(h0, h1);
}

// ---------------- fp32 -> fp16, 5 arrays in one launch ----------------------
__global__ void f2h5(const float4* __restrict__ s0, const float4* __restrict__ s1,
                     const float4* __restrict__ s2, const float4* __restrict__ s3,
                     const float4* __restrict__ s4,
                     uint4* __restrict__ d0, uint4* __restrict__ d1,
                     uint4* __restrict__ d2, uint4* __restrict__ d3,
                     uint4* __restrict__ d4, int n8) {
    int z = blockIdx.y;
    const float4* s = (z == 0) ? s0 : (z == 1) ? s1 : (z == 2) ? s2 : (z == 3) ? s3 : s4;
    uint4* d = (z == 0) ? d0 : (z == 1) ? d1 : (z == 2) ? d2 : (z == 3) ? d3 : d4;
    int i = blockIdx.x * blockDim.x + threadIdx.x;
    if (i < n8) {
        float4 a = s[2 * i], b = s[2 * i + 1];
        __half2 h0 = __floats2half2_rn(a.x, a.y);
        __half2 h1 = __floats2half2_rn(a.z, a.w);
        __half2 h2 = __floats2half2_rn(b.x, b.y);
        __half2 h3 = __floats2half2_rn(b.z, b.w);
        uint4 o;
        o.x = *reinterpret_cast<uint32_t*>(&h0);
        o.y = *reinterpret_cast<uint32_t*>(&h1);
        o.z = *reinterpret_cast<uint32_t*>(&h2);
        o.w = *reinterpret_cast<uint32_t*>(&h3);
        d[i] = o;
    }
}

// ---------------- fp16 HMMA NT GEMM core (128x128 CTA, BK=64, 3 stages) -----
#define G_STAGE_B 32768
#define GEMM_SMEM (3 * G_STAGE_B)

#define GEMM_MAIN(Bptr)                                                         \
    float acc[4][4][4];                                                         \
    _Pragma("unroll") for (int i = 0; i < 4; i++)                               \
        _Pragma("unroll") for (int j = 0; j < 4; j++)                           \
            _Pragma("unroll") for (int q = 0; q < 4; q++) acc[i][j][q] = 0.f;   \
    auto loadst = [&](int st, int k0) {                                         \
        uint32_t ab = smb + st * G_STAGE_B, bb = ab + 16384;                    \
        _Pragma("unroll") for (int i = 0; i < 4; i++) {                         \
            int gi = tid + i * 256;                                             \
            int r = gi >> 3, g = gi & 7;                                        \
            uint32_t off = r * 128 + (((g ^ r) & 7) << 4);                      \
            cp16(ab + off, A + (size_t)(m0 + r) * EMBED + k0 + g * 8);          \
            cp16(bb + off, Bptr + (size_t)(n0 + r) * EMBED + k0 + g * 8);       \
        }                                                                       \
    };                                                                          \
    loadst(0, 0); CP_COMMIT();                                                  \
    loadst(1, 64); CP_COMMIT();                                                 \
    int s = 0;                                                                  \
    for (int c = 0; c < 64; c++) {                                              \
        cp_wait<1>();                                                           \
        __syncthreads();                                                        \
        if (c + 2 < 64) loadst((s + 2) % 3, (c + 2) * 64);                      \
        CP_COMMIT();                                                            \
        uint32_t ab = smb + s * G_STAGE_B, bb = ab + 16384;                     \
        _Pragma("unroll") for (int kc = 0; kc < 4; kc++) {                      \
            int kk = kc * 16;                                                   \
            uint32_t af[4][4], bf[2][4];                                        \
            _Pragma("unroll") for (int mi = 0; mi < 4; mi++)                    \
                ldsm4(af[mi], ab + swz128(wm + mi * 16 + a_r, kk + a_c));       \
            _Pragma("unroll") for (int np = 0; np < 2; np++)                    \
                ldsm4(bf[np], bb + swz128(wn + np * 16 + b_r, kk + b_c));       \
            _Pragma("unroll") for (int mi = 0; mi < 4; mi++)                    \
                _Pragma("unroll") for (int ni = 0; ni < 4; ni++)                \
                    mma16(acc[mi][ni], af[mi], &bf[ni >> 1][(ni & 1) * 2]);     \
        }                                                                       \
        __syncthreads();                                                        \
        if (++s == 3) s = 0;                                                    \
    }

// Fused QKV with rotary + hi/lo split in epilogue. grid (32,32,3).
__global__ void __launch_bounds__(256, 2) gemm_qkv(const __half* __restrict__ A,
                                                   const __half* __restrict__ Wq,
                                                   const __half* __restrict__ Wk,
                                                   const __half* __restrict__ Wv,
                                                   const int* __restrict__ pid,
                                                   const float* __restrict__ emb,
                                                   __half* __restrict__ Qhi,
                                                   __half* __restrict__ Qlo,
                                                   __half* __restrict__ Khi,
                                                   __half* __restrict__ Klo,
                                                   __half* __restrict__ Cv) {
    extern __shared__ char smraw[];
    uint32_t smb = smem_u32(smraw);
    int z = blockIdx.z;
    const __half* B = (z == 0) ? Wq : (z == 1) ? Wk : Wv;

    int tid = threadIdx.x;
    int wid = tid >> 5, lane = tid & 31;
    int gid = lane >> 2, tig = lane & 3;
    int wm = (wid >> 2) * 64, wn = (wid & 3) * 32;
    int m0 = blockIdx.y * 128, n0 = blockIdx.x * 128;
    int a_r = lane & 15, a_c = (lane >> 4) << 3;
    int b_r = ((lane >> 4) << 3) + (lane & 7), b_c = ((lane >> 3) & 1) << 3;

    GEMM_MAIN(B)

    if (z == 2) {
#pragma unroll
        for (int mi = 0; mi < 4; mi++) {
            int r0 = m0 + wm + mi * 16 + gid;
#pragma unroll
            for (int ni = 0; ni < 4; ni++) {
                int col = n0 + wn + ni * 8 + tig * 2;
                *reinterpret_cast<__half2*>(Cv + (size_t)r0 * EMBED + col) =
                    __floats2half2_rn(acc[mi][ni][0], acc[mi][ni][1]);
                *reinterpret_cast<__half2*>(Cv + (size_t)(r0 + 8) * EMBED + col) =
                    __floats2half2_rn(acc[mi][ni][2], acc[mi][ni][3]);
            }
        }
    } else {
        __half* Hi = (z == 0) ? Qhi : Khi;
        __half* Lo = (z == 0) ? Qlo : Klo;
#pragma unroll
        for (int mi = 0; mi < 4; mi++) {
            int r0 = m0 + wm + mi * 16 + gid;
            int p0 = pid[r0], p1 = pid[r0 + 8];
#pragma unroll
            for (int ni = 0; ni < 4; ni++) {
                int col = n0 + wn + ni * 8 + tig * 2;
                float v0 = acc[mi][ni][0], v1 = acc[mi][ni][1];
                float v2 = acc[mi][ni][2], v3 = acc[mi][ni][3];
                int c = col & 255;
                if (c < 64) {
                    int pr = c >> 1;
                    float sv0 = emb[p0 * 64 + pr], cv0 = emb[p0 * 64 + 32 + pr];
                    float sv1 = emb[p1 * 64 + pr], cv1 = emb[p1 * 64 + 32 + pr];
                    float a0 = v0 * cv0 - v1 * sv0, b0 = v1 * cv0 + v0 * sv0;
                    v0 = a0; v1 = b0;
                    float a1 = v2 * cv1 - v3 * sv1, b1 = v3 * cv1 + v2 * sv1;
                    v2 = a1; v3 = b1;
                }
                __half2 lo0, lo1;
                __half2 hi0 = split_pair(v0, v1, &lo0);
                __half2 hi1 = split_pair(v2, v3, &lo1);
                size_t o0 = (size_t)r0 * EMBED + col;
                size_t o1 = (size_t)(r0 + 8) * EMBED + col;
                *reinterpret_cast<__half2*>(Hi + o0) = hi0;
                *reinterpret_cast<__half2*>(Lo + o0) = lo0;
                *reinterpret_cast<__half2*>(Hi + o1) = hi1;
                *reinterpret_cast<__half2*>(Lo + o1) = lo1;
            }
        }
    }
}

// Out projection: half in, float out.
__global__ void __launch_bounds__(256, 2) gemm_h(const __half* __restrict__ A,
                                                 const __half* __restrict__ Bw,
                                                 float* __restrict__ C) {
    extern __shared__ char smraw[];
    uint32_t smb = smem_u32(smraw);
    int tid = threadIdx.x;
    int wid = tid >> 5, lane = tid & 31;
    int gid = lane >> 2, tig = lane & 3;
    int wm = (wid >> 2) * 64, wn = (wid & 3) * 32;
    int m0 = blockIdx.y * 128, n0 = blockIdx.x * 128;
    int a_r = lane & 15, a_c = (lane >> 4) << 3;
    int b_r = ((lane >> 4) << 3) + (lane & 7), b_c = ((lane >> 3) & 1) << 3;

    GEMM_MAIN(Bw)

#pragma unroll
    for (int mi = 0; mi < 4; mi++) {
        int r0 = m0 + wm + mi * 16 + gid;
#pragma unroll
        for (int ni = 0; ni < 4; ni++) {
            int col = n0 + wn + ni * 8 + tig * 2;
            *reinterpret_cast<float2*>(C + (size_t)r0 * EMBED + col) =
                make_float2(acc[mi][ni][0], acc[mi][ni][1]);
            *reinterpret_cast<float2*>(C + (size_t)(r0 + 8) * EMBED + col) =
                make_float2(acc[mi][ni][2], acc[mi][ni][3]);
        }
    }
}

// ---------------- fp16 HMMA causal flash attention, BQ=128 ------------------
#define FL_Q_B 65536
#define FL_KV_ST 49152
#define FL_SMEM (2 * FL_Q_B + 2 * FL_KV_ST)  // 229376

__global__ void __launch_bounds__(256) flash_h(const __half* __restrict__ Qhi,
                                               const __half* __restrict__ Qlo,
                                               const __half* __restrict__ Khi,
                                               const __half* __restrict__ Klo,
                                               const __half* __restrict__ Vg,
                                               __half* __restrict__ Og) {
    extern __shared__ char smraw[];
    uint32_t smb = smem_u32(smraw);
    const uint32_t QHI = smb, QLO = smb + FL_Q_B, KV0 = smb + 2 * FL_Q_B;

    int tid = threadIdx.x;
    int wid = tid >> 5, lane = tid & 31;
    int gid = lane >> 2, tig = lane & 3;
    int rw0 = wid * 16;

    int bh = blockIdx.x & 31;
    int qb = 15 - (blockIdx.x >> 5);  // big tiles first
    int b = bh >> 4, h = bh & 15;
    int q0 = qb * 128;
    int nkt = 4 * qb + 4;
    size_t tok0 = (size_t)b * NS;

    int a_r = lane & 15, a_c = (lane >> 4) << 3;
    int b_r = ((lane >> 4) << 3) + (lane & 7), b_c = ((lane >> 3) & 1) << 3;

#pragma unroll
    for (int i = 0; i < 16; i++) {
        int gi = tid + i * 256;
        int r = gi >> 5, g = gi & 31;
        uint32_t off = r * 512 + (((g & 24) | ((g ^ r) & 7)) << 4);
        size_t src = (tok0 + q0 + r) * EMBED + h * HD + g * 8;
        cp16(QHI + off, Qhi + src);
        cp16(QLO + off, Qlo + src);
    }
    auto loadkv = [&](int st, int kt) {
        uint32_t kb = KV0 + st * FL_KV_ST;
        int k0 = kt * 32;
#pragma unroll
        for (int i = 0; i < 4; i++) {
            int gi = tid + i * 256;
            int r = gi >> 5, g = gi & 31;
            uint32_t off = r * 512 + (((g & 24) | ((g ^ r) & 7)) << 4);
            size_t src = (tok0 + k0 + r) * EMBED + h * HD + g * 8;
            cp16(kb + off, Khi + src);
            cp16(kb + 16384 + off, Klo + src);
            cp16(kb + 32768 + off, Vg + src);
        }
    };
    loadkv(0, 0);
    CP_COMMIT();

    float o[32][4];
#pragma unroll
    for (int nt = 0; nt < 32; nt++)
#pragma unroll
        for (int q = 0; q < 4; q++) o[nt][q] = 0.f;
    float m0v = -1e30f, m1v = -1e30f, l0v = 0.f, l1v = 0.f;
    int rg0 = q0 + rw0 + gid;

    for (int kt = 0; kt < nkt; kt++) {
        bool have_next = (kt + 1 < nkt);
        if (have_next) { loadkv((kt + 1) & 1, kt + 1); CP_COMMIT(); cp_wait<1>(); }
        else cp_wait<0>();
        __syncthreads();

        int k0 = kt * 32;
        if (k0 <= q0 + rw0 + 15) {
            uint32_t kb = KV0 + (kt & 1) * FL_KV_ST;
            uint32_t klb = kb + 16384, vb = kb + 32768;

            float s4[4][4];
#pragma unroll
            for (int nt = 0; nt < 4; nt++)
#pragma unroll
                for (int q = 0; q < 4; q++) s4[nt][q] = 0.f;

#pragma unroll
            for (int kc = 0; kc < 16; kc++) {
                int kk = kc * 16;
                uint32_t ah[4], al[4], bh4[2][4], bl4[2][4];
                ldsm4(ah, QHI + swz512(rw0 + a_r, kk + a_c));
                ldsm4(al, QLO + swz512(rw0 + a_r, kk + a_c));
#pragma unroll
                for (int np = 0; np < 2; np++) {
                    ldsm4(bh4[np], kb + swz512(np * 16 + b_r, kk + b_c));
                    ldsm4(bl4[np], klb + swz512(np * 16 + b_r, kk + b_c));
                }
#pragma unroll
                for (int np = 0; np < 2; np++) {
                    mma16(s4[2 * np], ah, &bh4[np][0]);
                    mma16(s4[2 * np], ah, &bl4[np][0]);
                    mma16(s4[2 * np], al, &bh4[np][0]);
                    mma16(s4[2 * np + 1], ah, &bh4[np][2]);
                    mma16(s4[2 * np + 1], ah, &bl4[np][2]);
                    mma16(s4[2 * np + 1], al, &bh4[np][2]);
                }
            }

            bool needmask = (k0 + 31 > q0 + rw0);
#pragma unroll
            for (int nt = 0; nt < 4; nt++) {
#pragma unroll
                for (int q = 0; q < 4; q++) s4[nt][q] *= 0.0625f;
                if (needmask) {
                    int c0 = k0 + nt * 8 + 2 * tig;
                    if (c0 > rg0) s4[nt][0] = -1e30f;
                    if (c0 + 1 > rg0) s4[nt][1] = -1e30f;
                    if (c0 > rg0 + 8) s4[nt][2] = -1e30f;
                    if (c0 + 1 > rg0 + 8) s4[nt][3] = -1e30f;
                }
            }

            float mx0 = -1e30f, mx1 = -1e30f;
#pragma unroll
            for (int nt = 0; nt < 4; nt++) {
                mx0 = fmaxf(mx0, fmaxf(s4[nt][0], s4[nt][1]));
                mx1 = fmaxf(mx1, fmaxf(s4[nt][2], s4[nt][3]));
            }
            mx0 = fmaxf(mx0, __shfl_xor_sync(0xffffffffu, mx0, 1));
            mx0 = fmaxf(mx0, __shfl_xor_sync(0xffffffffu, mx0, 2));
            mx1 = fmaxf(mx1, __shfl_xor_sync(0xffffffffu, mx1, 1));
            mx1 = fmaxf(mx1, __shfl_xor_sync(0xffffffffu, mx1, 2));
            float mn0 = fmaxf(m0v, mx0), mn1 = fmaxf(m1v, mx1);
            float cor0 = __expf(m0v - mn0), cor1 = __expf(m1v - mn1);
            m0v = mn0; m1v = mn1;

            float sum0 = 0.f, sum1 = 0.f;
            uint32_t ph[4][2];
#pragma unroll
            for (int nt = 0; nt < 4; nt++) {
                float p0 = __expf(s4[nt][0] - mn0);
                float p1 = __expf(s4[nt][1] - mn0);
                float p2 = __expf(s4[nt][2] - mn1);
                float p3 = __expf(s4[nt][3] - mn1);
                sum0 += p0 + p1; sum1 += p2 + p3;
                __half2 h01 = __floats2half2_rn(p0, p1);
                __half2 h23 = __floats2half2_rn(p2, p3);
                ph[nt][0] = *reinterpret_cast<uint32_t*>(&h01);
                ph[nt][1] = *reinterpret_cast<uint32_t*>(&h23);
            }
            sum0 += __shfl_xor_sync(0xffffffffu, sum0, 1);
            sum0 += __shfl_xor_sync(0xffffffffu, sum0, 2);
            sum1 += __shfl_xor_sync(0xffffffffu, sum1, 1);
            sum1 += __shfl_xor_sync(0xffffffffu, sum1, 2);
            l0v = l0v * cor0 + sum0;
            l1v = l1v * cor1 + sum1;

#pragma unroll
            for (int nt = 0; nt < 32; nt++) {
                o[nt][0] *= cor0; o[nt][1] *= cor0;
                o[nt][2] *= cor1; o[nt][3] *= cor1;
            }

#pragma unroll
            for (int kc = 0; kc < 2; kc++) {
                uint32_t a4[4] = {ph[2 * kc][0], ph[2 * kc][1],
                                  ph[2 * kc + 1][0], ph[2 * kc + 1][1]};
#pragma unroll
                for (int dp = 0; dp < 16; dp++) {
                    uint32_t b4[4];
                    ldsm4t(b4, vb + swz512(kc * 16 + a_r, dp * 16 + a_c));
                    mma16(o[2 * dp], a4, &b4[0]);
                    mma16(o[2 * dp + 1], a4, &b4[2]);
                }
            }
        }
        __syncthreads();
    }

    float inv0 = 1.f / l0v, inv1 = 1.f / l1v;
    __half* r0p = Og + (tok0 + rg0) * EMBED + h * HD;
    __half* r1p = Og + (tok0 + rg0 + 8) * EMBED + h * HD;
#pragma unroll
    for (int nt = 0; nt < 32; nt++) {
        int col = nt * 8 + 2 * tig;
        *reinterpret_cast<__half2*>(r0p + col) =
            __floats2half2_rn(o[nt][0] * inv0, o[nt][1] * inv0);
        *reinterpret_cast<__half2*>(r1p + col) =
            __floats2half2_rn(o[nt][2] * inv1, o[nt][3] * inv1);
    }
}

// ---------------------------------------------------------------------------
extern "C" void kernel_launch(void* const* d_in, const int* in_sizes, int n_in,
                              void* d_out, int out_size) {
    const float* hs = (const float*)d_in[0];
    const int* pid = (const int*)d_in[1];
    const float* qw = (const float*)d_in[2];
    const float* kw = (const float*)d_in[3];
    const float* vw = (const float*)d_in[4];
    const float* ow = (const float*)d_in[5];
    const float* emb = (const float*)d_in[6];
    float* out = (float*)d_out;

    __half *hs_h, *wq_h, *wk_h, *wv_h, *wo_h, *qhi, *qlo, *khi, *klo, *vh, *att;
    cudaGetSymbolAddress((void**)&hs_h, g_hs_h);
    cudaGetSymbolAddress((void**)&wq_h, g_wq_h);
    cudaGetSymbolAddress((void**)&wk_h, g_wk_h);
    cudaGetSymbolAddress((void**)&wv_h, g_wv_h);
    cudaGetSymbolAddress((void**)&wo_h, g_wo_h);
    cudaGetSymbolAddress((void**)&qhi, g_qhi);
    cudaGetSymbolAddress((void**)&qlo, g_qlo);
    cudaGetSymbolAddress((void**)&khi, g_khi);
    cudaGetSymbolAddress((void**)&klo, g_klo);
    cudaGetSymbolAddress((void**)&vh, g_v);
    cudaGetSymbolAddress((void**)&att, g_att);

    cudaFuncSetAttribute(gemm_qkv, cudaFuncAttributeMaxDynamicSharedMemorySize, GEMM_SMEM);
    cudaFuncSetAttribute(gemm_h, cudaFuncAttributeMaxDynamicSharedMemorySize, GEMM_SMEM);
    cudaFuncSetAttribute(flash_h, cudaFuncAttributeMaxDynamicSharedMemorySize, FL_SMEM);

    int n8 = (int)(NELEM / 8);
    f2h5<<<dim3(n8 / 256, 5), 256>>>((const float4*)hs, (const float4*)qw,
                                     (const float4*)kw, (const float4*)vw,
                                     (const float4*)ow, (uint4*)hs_h, (uint4*)wq_h,
                                     (uint4*)wk_h, (uint4*)wv_h, (uint4*)wo_h, n8);

    gemm_qkv<<<dim3(32, 32, 3), 256, GEMM_SMEM>>>(hs_h, wq_h, wk_h, wv_h, pid, emb,
                                                  qhi, qlo, khi, klo, vh);

    flash_h<<<512, 256, FL_SMEM>>>(qhi, qlo, khi, klo, vh, att);

    gemm_h<<<dim3(32, 32), 256, GEMM_SMEM>>>(att, wo_h, out);
}

// round 8
// speedup vs baseline: 10.6152x; 1.0775x over previous
#include <cuda_runtime.h>
#include <cuda_fp16.h>
#include <cstdint>
#include <math.h>

#define EMBED 4096
#define NH 16
#define HD 256
#define NB 2
#define NS 2048
#define NTOK (NB * NS)
#define NELEM ((size_t)NTOK * EMBED)

__device__ __half g_hs_h[NELEM];
__device__ __half g_wq_h[NELEM];
__device__ __half g_wk_h[NELEM];
__device__ __half g_wv_h[NELEM];
__device__ __half g_wo_h[NELEM];
__device__ __half g_qh[NELEM];
__device__ __half g_kh[NELEM];
__device__ __half g_v[NELEM];
__device__ __half g_att[NELEM];

// ---------------- PTX helpers (baseline ISA; tcgen05 is sm_103a-gated) ------
__device__ __forceinline__ uint32_t smem_u32(const void* p) {
    uint32_t a;
    asm("{ .reg .u64 t; cvta.to.shared.u64 t, %1; cvt.u32.u64 %0, t; }"
        : "=r"(a) : "l"(p));
    return a;
}
__device__ __forceinline__ void cp16(uint32_t s, const void* g) {
    asm volatile("cp.async.cg.shared.global [%0], [%1], 16;\n" ::"r"(s), "l"(g));
}
#define CP_COMMIT() asm volatile("cp.async.commit_group;\n" ::: "memory")
template <int N>
__device__ __forceinline__ void cp_wait() {
    asm volatile("cp.async.wait_group %0;\n" ::"n"(N) : "memory");
}
__device__ __forceinline__ void ldsm4(uint32_t* r, uint32_t a) {
    asm volatile("ldmatrix.sync.aligned.m8n8.x4.shared.b16 {%0,%1,%2,%3}, [%4];"
                 : "=r"(r[0]), "=r"(r[1]), "=r"(r[2]), "=r"(r[3]) : "r"(a));
}
__device__ __forceinline__ void ldsm4t(uint32_t* r, uint32_t a) {
    asm volatile("ldmatrix.sync.aligned.m8n8.x4.trans.shared.b16 {%0,%1,%2,%3}, [%4];"
                 : "=r"(r[0]), "=r"(r[1]), "=r"(r[2]), "=r"(r[3]) : "r"(a));
}
__device__ __forceinline__ void mma16(float* c, const uint32_t* a, const uint32_t* b) {
    asm volatile(
        "mma.sync.aligned.m16n8k16.row.col.f32.f16.f16.f32 "
        "{%0,%1,%2,%3}, {%4,%5,%6,%7}, {%8,%9}, {%0,%1,%2,%3};"
        : "+f"(c[0]), "+f"(c[1]), "+f"(c[2]), "+f"(c[3])
        : "r"(a[0]), "r"(a[1]), "r"(a[2]), "r"(a[3]), "r"(b[0]), "r"(b[1]));
}
__device__ __forceinline__ uint32_t swz128(int r, int c) {  // row = 64 halves
    return (uint32_t)(r * 128 + ((((c >> 3) ^ r) & 7) << 4) + ((c & 7) << 1));
}
__device__ __forceinline__ uint32_t swz512(int r, int c) {  // row = 256 halves
    int g = c >> 3;
    return (uint32_t)(r * 512 + (((g & 24) | ((g ^ r) & 7)) << 4) + ((c & 7) << 1));
}

// ---------------- fp32 -> fp16, 5 arrays in one launch ----------------------
__global__ void f2h5(const float4* __restrict__ s0, const float4* __restrict__ s1,
                     const float4* __restrict__ s2, const float4* __restrict__ s3,
                     const float4* __restrict__ s4,
                     uint4* __restrict__ d0, uint4* __restrict__ d1,
                     uint4* __restrict__ d2, uint4* __restrict__ d3,
                     uint4* __restrict__ d4, int n8) {
    int z = blockIdx.y;
    const float4* s = (z == 0) ? s0 : (z == 1) ? s1 : (z == 2) ? s2 : (z == 3) ? s3 : s4;
    uint4* d = (z == 0) ? d0 : (z == 1) ? d1 : (z == 2) ? d2 : (z == 3) ? d3 : d4;
    int i = blockIdx.x * blockDim.x + threadIdx.x;
    if (i < n8) {
        float4 a = s[2 * i], b = s[2 * i + 1];
        __half2 h0 = __floats2half2_rn(a.x, a.y);
        __half2 h1 = __floats2half2_rn(a.z, a.w);
        __half2 h2 = __floats2half2_rn(b.x, b.y);
        __half2 h3 = __floats2half2_rn(b.z, b.w);
        uint4 o;
        o.x = *reinterpret_cast<uint32_t*>(&h0);
        o.y = *reinterpret_cast<uint32_t*>(&h1);
        o.z = *reinterpret_cast<uint32_t*>(&h2);
        o.w = *reinterpret_cast<uint32_t*>(&h3);
        d[i] = o;
    }
}

// ---------------- fp16 HMMA NT GEMM core (128x128 CTA, BK=64, 3 stages) -----
#define G_STAGE_B 32768
#define GEMM_SMEM (3 * G_STAGE_B)

#define GEMM_MAIN(Bptr)                                                         \
    float acc[4][4][4];                                                         \
    _Pragma("unroll") for (int i = 0; i < 4; i++)                               \
        _Pragma("unroll") for (int j = 0; j < 4; j++)                           \
            _Pragma("unroll") for (int q = 0; q < 4; q++) acc[i][j][q] = 0.f;   \
    auto loadst = [&](int st, int k0) {                                         \
        uint32_t ab = smb + st * G_STAGE_B, bb = ab + 16384;                    \
        _Pragma("unroll") for (int i = 0; i < 4; i++) {                         \
            int gi = tid + i * 256;                                             \
            int r = gi >> 3, g = gi & 7;                                        \
            uint32_t off = r * 128 + (((g ^ r) & 7) << 4);                      \
            cp16(ab + off, A + (size_t)(m0 + r) * EMBED + k0 + g * 8);          \
            cp16(bb + off, Bptr + (size_t)(n0 + r) * EMBED + k0 + g * 8);       \
        }                                                                       \
    };                                                                          \
    loadst(0, 0); CP_COMMIT();                                                  \
    loadst(1, 64); CP_COMMIT();                                                 \
    int s = 0;                                                                  \
    for (int c = 0; c < 64; c++) {                                              \
        cp_wait<1>();                                                           \
        __syncthreads();                                                        \
        if (c + 2 < 64) loadst((s + 2) % 3, (c + 2) * 64);                      \
        CP_COMMIT();                                                            \
        uint32_t ab = smb + s * G_STAGE_B, bb = ab + 16384;                     \
        _Pragma("unroll") for (int kc = 0; kc < 4; kc++) {                      \
            int kk = kc * 16;                                                   \
            uint32_t af[4][4], bf[2][4];                                        \
            _Pragma("unroll") for (int mi = 0; mi < 4; mi++)                    \
                ldsm4(af[mi], ab + swz128(wm + mi * 16 + a_r, kk + a_c));       \
            _Pragma("unroll") for (int np = 0; np < 2; np++)                    \
                ldsm4(bf[np], bb + swz128(wn + np * 16 + b_r, kk + b_c));       \
            _Pragma("unroll") for (int mi = 0; mi < 4; mi++)                    \
                _Pragma("unroll") for (int ni = 0; ni < 4; ni++)                \
                    mma16(acc[mi][ni], af[mi], &bf[ni >> 1][(ni & 1) * 2]);     \
        }                                                                       \
        __syncthreads();                                                        \
        if (++s == 3) s = 0;                                                    \
    }

// Fused QKV with rotary in epilogue, plain fp16 outputs. grid (32,32,3).
__global__ void __launch_bounds__(256, 2) gemm_qkv(const __half* __restrict__ A,
                                                   const __half* __restrict__ Wq,
                                                   const __half* __restrict__ Wk,
                                                   const __half* __restrict__ Wv,
                                                   const int* __restrict__ pid,
                                                   const float* __restrict__ emb,
                                                   __half* __restrict__ Qh,
                                                   __half* __restrict__ Kh,
                                                   __half* __restrict__ Cv) {
    extern __shared__ char smraw[];
    uint32_t smb = smem_u32(smraw);
    int z = blockIdx.z;
    const __half* B = (z == 0) ? Wq : (z == 1) ? Wk : Wv;

    int tid = threadIdx.x;
    int wid = tid >> 5, lane = tid & 31;
    int gid = lane >> 2, tig = lane & 3;
    int wm = (wid >> 2) * 64, wn = (wid & 3) * 32;
    int m0 = blockIdx.y * 128, n0 = blockIdx.x * 128;
    int a_r = lane & 15, a_c = (lane >> 4) << 3;
    int b_r = ((lane >> 4) << 3) + (lane & 7), b_c = ((lane >> 3) & 1) << 3;

    GEMM_MAIN(B)

    if (z == 2) {
#pragma unroll
        for (int mi = 0; mi < 4; mi++) {
            int r0 = m0 + wm + mi * 16 + gid;
#pragma unroll
            for (int ni = 0; ni < 4; ni++) {
                int col = n0 + wn + ni * 8 + tig * 2;
                *reinterpret_cast<__half2*>(Cv + (size_t)r0 * EMBED + col) =
                    __floats2half2_rn(acc[mi][ni][0], acc[mi][ni][1]);
                *reinterpret_cast<__half2*>(Cv + (size_t)(r0 + 8) * EMBED + col) =
                    __floats2half2_rn(acc[mi][ni][2], acc[mi][ni][3]);
            }
        }
    } else {
        __half* Hi = (z == 0) ? Qh : Kh;
#pragma unroll
        for (int mi = 0; mi < 4; mi++) {
            int r0 = m0 + wm + mi * 16 + gid;
            int p0 = pid[r0], p1 = pid[r0 + 8];
#pragma unroll
            for (int ni = 0; ni < 4; ni++) {
                int col = n0 + wn + ni * 8 + tig * 2;
                float v0 = acc[mi][ni][0], v1 = acc[mi][ni][1];
                float v2 = acc[mi][ni][2], v3 = acc[mi][ni][3];
                int c = col & 255;
                if (c < 64) {
                    int pr = c >> 1;
                    float sv0 = emb[p0 * 64 + pr], cv0 = emb[p0 * 64 + 32 + pr];
                    float sv1 = emb[p1 * 64 + pr], cv1 = emb[p1 * 64 + 32 + pr];
                    float a0 = v0 * cv0 - v1 * sv0, b0 = v1 * cv0 + v0 * sv0;
                    v0 = a0; v1 = b0;
                    float a1 = v2 * cv1 - v3 * sv1, b1 = v3 * cv1 + v2 * sv1;
                    v2 = a1; v3 = b1;
                }
                size_t o0 = (size_t)r0 * EMBED + col;
                size_t o1 = (size_t)(r0 + 8) * EMBED + col;
                *reinterpret_cast<__half2*>(Hi + o0) = __floats2half2_rn(v0, v1);
                *reinterpret_cast<__half2*>(Hi + o1) = __floats2half2_rn(v2, v3);
            }
        }
    }
}

// Out projection: half in, float out.
__global__ void __launch_bounds__(256, 2) gemm_h(const __half* __restrict__ A,
                                                 const __half* __restrict__ Bw,
                                                 float* __restrict__ C) {
    extern __shared__ char smraw[];
    uint32_t smb = smem_u32(smraw);
    int tid = threadIdx.x;
    int wid = tid >> 5, lane = tid & 31;
    int gid = lane >> 2, tig = lane & 3;
    int wm = (wid >> 2) * 64, wn = (wid & 3) * 32;
    int m0 = blockIdx.y * 128, n0 = blockIdx.x * 128;
    int a_r = lane & 15, a_c = (lane >> 4) << 3;
    int b_r = ((lane >> 4) << 3) + (lane & 7), b_c = ((lane >> 3) & 1) << 3;

    GEMM_MAIN(Bw)

#pragma unroll
    for (int mi = 0; mi < 4; mi++) {
        int r0 = m0 + wm + mi * 16 + gid;
#pragma unroll
        for (int ni = 0; ni < 4; ni++) {
            int col = n0 + wn + ni * 8 + tig * 2;
            *reinterpret_cast<float2*>(C + (size_t)r0 * EMBED + col) =
                make_float2(acc[mi][ni][0], acc[mi][ni][1]);
            *reinterpret_cast<float2*>(C + (size_t)(r0 + 8) * EMBED + col) =
                make_float2(acc[mi][ni][2], acc[mi][ni][3]);
        }
    }
}

// ---------------- fp16 HMMA causal flash attention, BQ=128, plain QK --------
#define FL_Q_B 65536
#define FL_KV_ST 32768
#define FL_SMEM (FL_Q_B + 2 * FL_KV_ST)  // 131072

__global__ void __launch_bounds__(256) flash_h(const __half* __restrict__ Qg,
                                               const __half* __restrict__ Kg,
                                               const __half* __restrict__ Vg,
                                               __half* __restrict__ Og) {
    extern __shared__ char smraw[];
    uint32_t smb = smem_u32(smraw);
    const uint32_t QS = smb, KV0 = smb + FL_Q_B;

    int tid = threadIdx.x;
    int wid = tid >> 5, lane = tid & 31;
    int gid = lane >> 2, tig = lane & 3;
    int rw0 = wid * 16;

    int bh = blockIdx.x & 31;
    int qb = 15 - (blockIdx.x >> 5);  // big tiles first
    int b = bh >> 4, h = bh & 15;
    int q0 = qb * 128;
    int nkt = 4 * qb + 4;
    size_t tok0 = (size_t)b * NS;

    int a_r = lane & 15, a_c = (lane >> 4) << 3;
    int b_r = ((lane >> 4) << 3) + (lane & 7), b_c = ((lane >> 3) & 1) << 3;

#pragma unroll
    for (int i = 0; i < 16; i++) {  // Q: 128 rows x 256 halves
        int gi = tid + i * 256;
        int r = gi >> 5, g = gi & 31;
        uint32_t off = r * 512 + (((g & 24) | ((g ^ r) & 7)) << 4);
        cp16(QS + off, Qg + (tok0 + q0 + r) * EMBED + h * HD + g * 8);
    }
    auto loadkv = [&](int st, int kt) {
        uint32_t kb = KV0 + st * FL_KV_ST;
        int k0 = kt * 32;
#pragma unroll
        for (int i = 0; i < 4; i++) {
            int gi = tid + i * 256;
            int r = gi >> 5, g = gi & 31;
            uint32_t off = r * 512 + (((g & 24) | ((g ^ r) & 7)) << 4);
            size_t src = (tok0 + k0 + r) * EMBED + h * HD + g * 8;
            cp16(kb + off, Kg + src);
            cp16(kb + 16384 + off, Vg + src);
        }
    };
    loadkv(0, 0);
    CP_COMMIT();

    float o[32][4];
#pragma unroll
    for (int nt = 0; nt < 32; nt++)
#pragma unroll
        for (int q = 0; q < 4; q++) o[nt][q] = 0.f;
    float m0v = -1e30f, m1v = -1e30f, l0v = 0.f, l1v = 0.f;
    int rg0 = q0 + rw0 + gid;

    for (int kt = 0; kt < nkt; kt++) {
        bool have_next = (kt + 1 < nkt);
        if (have_next) { loadkv((kt + 1) & 1, kt + 1); CP_COMMIT(); cp_wait<1>(); }
        else cp_wait<0>();
        __syncthreads();

        int k0 = kt * 32;
        if (k0 <= q0 + rw0 + 15) {
            uint32_t kb = KV0 + (kt & 1) * FL_KV_ST;
            uint32_t vb = kb + 16384;

            float s4[4][4];
#pragma unroll
            for (int nt = 0; nt < 4; nt++)
#pragma unroll
                for (int q = 0; q < 4; q++) s4[nt][q] = 0.f;

#pragma unroll
            for (int kc = 0; kc < 16; kc++) {
                int kk = kc * 16;
                uint32_t ah[4], bh4[2][4];
                ldsm4(ah, QS + swz512(rw0 + a_r, kk + a_c));
#pragma unroll
                for (int np = 0; np < 2; np++)
                    ldsm4(bh4[np], kb + swz512(np * 16 + b_r, kk + b_c));
#pragma unroll
                for (int np = 0; np < 2; np++) {
                    mma16(s4[2 * np], ah, &bh4[np][0]);
                    mma16(s4[2 * np + 1], ah, &bh4[np][2]);
                }
            }

            bool needmask = (k0 + 31 > q0 + rw0);
#pragma unroll
            for (int nt = 0; nt < 4; nt++) {
#pragma unroll
                for (int q = 0; q < 4; q++) s4[nt][q] *= 0.0625f;
                if (needmask) {
                    int c0 = k0 + nt * 8 + 2 * tig;
                    if (c0 > rg0) s4[nt][0] = -1e30f;
                    if (c0 + 1 > rg0) s4[nt][1] = -1e30f;
                    if (c0 > rg0 + 8) s4[nt][2] = -1e30f;
                    if (c0 + 1 > rg0 + 8) s4[nt][3] = -1e30f;
                }
            }

            float mx0 = -1e30f, mx1 = -1e30f;
#pragma unroll
            for (int nt = 0; nt < 4; nt++) {
                mx0 = fmaxf(mx0, fmaxf(s4[nt][0], s4[nt][1]));
                mx1 = fmaxf(mx1, fmaxf(s4[nt][2], s4[nt][3]));
            }
            mx0 = fmaxf(mx0, __shfl_xor_sync(0xffffffffu, mx0, 1));
            mx0 = fmaxf(mx0, __shfl_xor_sync(0xffffffffu, mx0, 2));
            mx1 = fmaxf(mx1, __shfl_xor_sync(0xffffffffu, mx1, 1));
            mx1 = fmaxf(mx1, __shfl_xor_sync(0xffffffffu, mx1, 2));
            float mn0 = fmaxf(m0v, mx0), mn1 = fmaxf(m1v, mx1);
            float cor0 = __expf(m0v - mn0), cor1 = __expf(m1v - mn1);
            m0v = mn0; m1v = mn1;

            float sum0 = 0.f, sum1 = 0.f;
            uint32_t ph[4][2];
#pragma unroll
            for (int nt = 0; nt < 4; nt++) {
                float p0 = __expf(s4[nt][0] - mn0);
                float p1 = __expf(s4[nt][1] - mn0);
                float p2 = __expf(s4[nt][2] - mn1);
                float p3 = __expf(s4[nt][3] - mn1);
                sum0 += p0 + p1; sum1 += p2 + p3;
                __half2 h01 = __floats2half2_rn(p0, p1);
                __half2 h23 = __floats2half2_rn(p2, p3);
                ph[nt][0] = *reinterpret_cast<uint32_t*>(&h01);
                ph[nt][1] = *reinterpret_cast<uint32_t*>(&h23);
            }
            sum0 += __shfl_xor_sync(0xffffffffu, sum0, 1);
            sum0 += __shfl_xor_sync(0xffffffffu, sum0, 2);
            sum1 += __shfl_xor_sync(0xffffffffu, sum1, 1);
            sum1 += __shfl_xor_sync(0xffffffffu, sum1, 2);
            l0v = l0v * cor0 + sum0;
            l1v = l1v * cor1 + sum1;

#pragma unroll
            for (int nt = 0; nt < 32; nt++) {
                o[nt][0] *= cor0; o[nt][1] *= cor0;
                o[nt][2] *= cor1; o[nt][3] *= cor1;
            }

#pragma unroll
            for (int kc = 0; kc < 2; kc++) {
                uint32_t a4[4] = {ph[2 * kc][0], ph[2 * kc][1],
                                  ph[2 * kc + 1][0], ph[2 * kc + 1][1]};
#pragma unroll
                for (int dp = 0; dp < 16; dp++) {
                    uint32_t b4[4];
                    ldsm4t(b4, vb + swz512(kc * 16 + a_r, dp * 16 + a_c));
                    mma16(o[2 * dp], a4, &b4[0]);
                    mma16(o[2 * dp + 1], a4, &b4[2]);
                }
            }
        }
        __syncthreads();
    }

    float inv0 = 1.f / l0v, inv1 = 1.f / l1v;
    __half* r0p = Og + (tok0 + rg0) * EMBED + h * HD;
    __half* r1p = Og + (tok0 + rg0 + 8) * EMBED + h * HD;
#pragma unroll
    for (int nt = 0; nt < 32; nt++) {
        int col = nt * 8 + 2 * tig;
        *reinterpret_cast<__half2*>(r0p + col) =
            __floats2half2_rn(o[nt][0] * inv0, o[nt][1] * inv0);
        *reinterpret_cast<__half2*>(r1p + col) =
            __floats2half2_rn(o[nt][2] * inv1, o[nt][3] * inv1);
    }
}

// ---------------------------------------------------------------------------
extern "C" void kernel_launch(void* const* d_in, const int* in_sizes, int n_in,
                              void* d_out, int out_size) {
    const float* hs = (const float*)d_in[0];
    const int* pid = (const int*)d_in[1];
    const float* qw = (const float*)d_in[2];
    const float* kw = (const float*)d_in[3];
    const float* vw = (const float*)d_in[4];
    const float* ow = (const float*)d_in[5];
    const float* emb = (const float*)d_in[6];
    float* out = (float*)d_out;

    __half *hs_h, *wq_h, *wk_h, *wv_h, *wo_h, *qh, *kh, *vh, *att;
    cudaGetSymbolAddress((void**)&hs_h, g_hs_h);
    cudaGetSymbolAddress((void**)&wq_h, g_wq_h);
    cudaGetSymbolAddress((void**)&wk_h, g_wk_h);
    cudaGetSymbolAddress((void**)&wv_h, g_wv_h);
    cudaGetSymbolAddress((void**)&wo_h, g_wo_h);
    cudaGetSymbolAddress((void**)&qh, g_qh);
    cudaGetSymbolAddress((void**)&kh, g_kh);
    cudaGetSymbolAddress((void**)&vh, g_v);
    cudaGetSymbolAddress((void**)&att, g_att);

    cudaFuncSetAttribute(gemm_qkv, cudaFuncAttributeMaxDynamicSharedMemorySize, GEMM_SMEM);
    cudaFuncSetAttribute(gemm_h, cudaFuncAttributeMaxDynamicSharedMemorySize, GEMM_SMEM);
    cudaFuncSetAttribute(flash_h, cudaFuncAttributeMaxDynamicSharedMemorySize, FL_SMEM);

    int n8 = (int)(NELEM / 8);
    f2h5<<<dim3(n8 / 256, 5), 256>>>((const float4*)hs, (const float4*)qw,
                                     (const float4*)kw, (const float4*)vw,
                                     (const float4*)ow, (uint4*)hs_h, (uint4*)wq_h,
                                     (uint4*)wk_h, (uint4*)wv_h, (uint4*)wo_h, n8);

    gemm_qkv<<<dim3(32, 32, 3), 256, GEMM_SMEM>>>(hs_h, wq_h, wk_h, wv_h, pid, emb,
                                                  qh, kh, vh);

    flash_h<<<512, 256, FL_SMEM>>>(qh, kh, vh, att);

    gemm_h<<<dim3(32, 32), 256, GEMM_SMEM>>>(att, wo_h, out);
}

// round 10
// speedup vs baseline: 10.7261x; 1.0104x over previous
#include <cuda_runtime.h>
#include <cuda_fp16.h>
#include <cstdint>
#include <math.h>

#define EMBED 4096
#define NH 16
#define HD 256
#define NB 2
#define NS 2048
#define NTOK (NB * NS)
#define NELEM ((size_t)NTOK * EMBED)

__device__ __half g_hs_h[NELEM];
__device__ __half g_wq_h[NELEM];
__device__ __half g_wk_h[NELEM];
__device__ __half g_wv_h[NELEM];
__device__ __half g_wo_h[NELEM];
__device__ __half g_qh[NELEM];
__device__ __half g_kh[NELEM];
__device__ __half g_v[NELEM];
__device__ __half g_att[NELEM];

// ---------------- PTX helpers (baseline ISA; tcgen05 is sm_103a-gated) ------
__device__ __forceinline__ uint32_t smem_u32(const void* p) {
    uint32_t a;
    asm("{ .reg .u64 t; cvta.to.shared.u64 t, %1; cvt.u32.u64 %0, t; }"
        : "=r"(a) : "l"(p));
    return a;
}
__device__ __forceinline__ void cp16(uint32_t s, const void* g) {
    asm volatile("cp.async.cg.shared.global [%0], [%1], 16;\n" ::"r"(s), "l"(g));
}
#define CP_COMMIT() asm volatile("cp.async.commit_group;\n" ::: "memory")
template <int N>
__device__ __forceinline__ void cp_wait() {
    asm volatile("cp.async.wait_group %0;\n" ::"n"(N) : "memory");
}
__device__ __forceinline__ void ldsm4(uint32_t* r, uint32_t a) {
    asm volatile("ldmatrix.sync.aligned.m8n8.x4.shared.b16 {%0,%1,%2,%3}, [%4];"
                 : "=r"(r[0]), "=r"(r[1]), "=r"(r[2]), "=r"(r[3]) : "r"(a));
}
__device__ __forceinline__ void ldsm4t(uint32_t* r, uint32_t a) {
    asm volatile("ldmatrix.sync.aligned.m8n8.x4.trans.shared.b16 {%0,%1,%2,%3}, [%4];"
                 : "=r"(r[0]), "=r"(r[1]), "=r"(r[2]), "=r"(r[3]) : "r"(a));
}
__device__ __forceinline__ void mma16(float* c, const uint32_t* a, const uint32_t* b) {
    asm volatile(
        "mma.sync.aligned.m16n8k16.row.col.f32.f16.f16.f32 "
        "{%0,%1,%2,%3}, {%4,%5,%6,%7}, {%8,%9}, {%0,%1,%2,%3};"
        : "+f"(c[0]), "+f"(c[1]), "+f"(c[2]), "+f"(c[3])
        : "r"(a[0]), "r"(a[1]), "r"(a[2]), "r"(a[3]), "r"(b[0]), "r"(b[1]));
}
__device__ __forceinline__ uint32_t swz128(int r, int c) {  // row = 64 halves
    return (uint32_t)(r * 128 + ((((c >> 3) ^ r) & 7) << 4) + ((c & 7) << 1));
}
__device__ __forceinline__ uint32_t swz512(int r, int c) {  // row = 256 halves
    int g = c >> 3;
    return (uint32_t)(r * 512 + (((g & 24) | ((g ^ r) & 7)) << 4) + ((c & 7) << 1));
}

// ---------------- fp32 -> fp16, 5 arrays in one launch ----------------------
__global__ void f2h5(const float4* __restrict__ s0, const float4* __restrict__ s1,
                     const float4* __restrict__ s2, const float4* __restrict__ s3,
                     const float4* __restrict__ s4,
                     uint4* __restrict__ d0, uint4* __restrict__ d1,
                     uint4* __restrict__ d2, uint4* __restrict__ d3,
                     uint4* __restrict__ d4, int n8) {
    int z = blockIdx.y;
    const float4* s = (z == 0) ? s0 : (z == 1) ? s1 : (z == 2) ? s2 : (z == 3) ? s3 : s4;
    uint4* d = (z == 0) ? d0 : (z == 1) ? d1 : (z == 2) ? d2 : (z == 3) ? d3 : d4;
    int i = blockIdx.x * blockDim.x + threadIdx.x;
    if (i < n8) {
        float4 a = s[2 * i], b = s[2 * i + 1];
        __half2 h0 = __floats2half2_rn(a.x, a.y);
        __half2 h1 = __floats2half2_rn(a.z, a.w);
        __half2 h2 = __floats2half2_rn(b.x, b.y);
        __half2 h3 = __floats2half2_rn(b.z, b.w);
        uint4 o;
        o.x = *reinterpret_cast<uint32_t*>(&h0);
        o.y = *reinterpret_cast<uint32_t*>(&h1);
        o.z = *reinterpret_cast<uint32_t*>(&h2);
        o.w = *reinterpret_cast<uint32_t*>(&h3);
        d[i] = o;
    }
}

// ------- fp16 HMMA NT GEMM core: 128x128 CTA, 4 warps (2x2 of 64x64), BK=64 -
#define G_STAGE_B 32768
#define GEMM_SMEM (3 * G_STAGE_B)

#define GEMM_MAIN(Bptr)                                                         \
    float acc[4][8][4];                                                         \
    _Pragma("unroll") for (int i = 0; i < 4; i++)                               \
        _Pragma("unroll") for (int j = 0; j < 8; j++)                           \
            _Pragma("unroll") for (int q = 0; q < 4; q++) acc[i][j][q] = 0.f;   \
    auto loadst = [&](int st, int k0) {                                         \
        uint32_t ab = smb + st * G_STAGE_B, bb = ab + 16384;                    \
        _Pragma("unroll") for (int i = 0; i < 8; i++) {                         \
            int gi = tid + i * 128;                                             \
            int r = gi >> 3, g = gi & 7;                                        \
            uint32_t off = r * 128 + (((g ^ r) & 7) << 4);                      \
            cp16(ab + off, A + (size_t)(m0 + r) * EMBED + k0 + g * 8);          \
            cp16(bb + off, Bptr + (size_t)(n0 + r) * EMBED + k0 + g * 8);       \
        }                                                                       \
    };                                                                          \
    loadst(0, 0); CP_COMMIT();                                                  \
    loadst(1, 64); CP_COMMIT();                                                 \
    int s = 0;                                                                  \
    for (int c = 0; c < 64; c++) {                                              \
        cp_wait<1>();                                                           \
        __syncthreads();                                                        \
        if (c + 2 < 64) loadst((s + 2) % 3, (c + 2) * 64);                      \
        CP_COMMIT();                                                            \
        uint32_t ab = smb + s * G_STAGE_B, bb = ab + 16384;                     \
        _Pragma("unroll") for (int kc = 0; kc < 4; kc++) {                      \
            int kk = kc * 16;                                                   \
            uint32_t af[4][4], bf[4][4];                                        \
            _Pragma("unroll") for (int mi = 0; mi < 4; mi++)                    \
                ldsm4(af[mi], ab + swz128(wm + mi * 16 + a_r, kk + a_c));       \
            _Pragma("unroll") for (int np = 0; np < 4; np++)                    \
                ldsm4(bf[np], bb + swz128(wn + np * 16 + b_r, kk + b_c));       \
            _Pragma("unroll") for (int mi = 0; mi < 4; mi++)                    \
                _Pragma("unroll") for (int ni = 0; ni < 8; ni++)                \
                    mma16(acc[mi][ni], af[mi], &bf[ni >> 1][(ni & 1) * 2]);     \
        }                                                                       \
        __syncthreads();                                                        \
        if (++s == 3) s = 0;                                                    \
    }

// Fused QKV with rotary in epilogue, plain fp16 outputs. grid (32,32,3).
__global__ void __launch_bounds__(128, 2) gemm_qkv(const __half* __restrict__ A,
                                                   const __half* __restrict__ Wq,
                                                   const __half* __restrict__ Wk,
                                                   const __half* __restrict__ Wv,
                                                   const int* __restrict__ pid,
                                                   const float* __restrict__ emb,
                                                   __half* __restrict__ Qh,
                                                   __half* __restrict__ Kh,
                                                   __half* __restrict__ Cv) {
    extern __shared__ char smraw[];
    uint32_t smb = smem_u32(smraw);
    int z = blockIdx.z;
    const __half* B = (z == 0) ? Wq : (z == 1) ? Wk : Wv;

    int tid = threadIdx.x;
    int wid = tid >> 5, lane = tid & 31;
    int gid = lane >> 2, tig = lane & 3;
    int wm = (wid >> 1) * 64, wn = (wid & 1) * 64;
    int m0 = blockIdx.y * 128, n0 = blockIdx.x * 128;
    int a_r = lane & 15, a_c = (lane >> 4) << 3;
    int b_r = ((lane >> 4) << 3) + (lane & 7), b_c = ((lane >> 3) & 1) << 3;

    GEMM_MAIN(B)

    if (z == 2) {
#pragma unroll
        for (int mi = 0; mi < 4; mi++) {
            int r0 = m0 + wm + mi * 16 + gid;
#pragma unroll
            for (int ni = 0; ni < 8; ni++) {
                int col = n0 + wn + ni * 8 + tig * 2;
                *reinterpret_cast<__half2*>(Cv + (size_t)r0 * EMBED + col) =
                    __floats2half2_rn(acc[mi][ni][0], acc[mi][ni][1]);
                *reinterpret_cast<__half2*>(Cv + (size_t)(r0 + 8) * EMBED + col) =
                    __floats2half2_rn(acc[mi][ni][2], acc[mi][ni][3]);
            }
        }
    } else {
        __half* Hi = (z == 0) ? Qh : Kh;
#pragma unroll
        for (int mi = 0; mi < 4; mi++) {
            int r0 = m0 + wm + mi * 16 + gid;
            int p0 = pid[r0], p1 = pid[r0 + 8];
#pragma unroll
            for (int ni = 0; ni < 8; ni++) {
                int col = n0 + wn + ni * 8 + tig * 2;
                float v0 = acc[mi][ni][0], v1 = acc[mi][ni][1];
                float v2 = acc[mi][ni][2], v3 = acc[mi][ni][3];
                int c = col & 255;
                if (c < 64) {
                    int pr = c >> 1;
                    float sv0 = emb[p0 * 64 + pr], cv0 = emb[p0 * 64 + 32 + pr];
                    float sv1 = emb[p1 * 64 + pr], cv1 = emb[p1 * 64 + 32 + pr];
                    float a0 = v0 * cv0 - v1 * sv0, b0 = v1 * cv0 + v0 * sv0;
                    v0 = a0; v1 = b0;
                    float a1 = v2 * cv1 - v3 * sv1, b1 = v3 * cv1 + v2 * sv1;
                    v2 = a1; v3 = b1;
                }
                size_t o0 = (size_t)r0 * EMBED + col;
                size_t o1 = (size_t)(r0 + 8) * EMBED + col;
                *reinterpret_cast<__half2*>(Hi + o0) = __floats2half2_rn(v0, v1);
                *reinterpret_cast<__half2*>(Hi + o1) = __floats2half2_rn(v2, v3);
            }
        }
    }
}

// Out projection: half in, float out.
__global__ void __launch_bounds__(128, 2) gemm_h(const __half* __restrict__ A,
                                                 const __half* __restrict__ Bw,
                                                 float* __restrict__ C) {
    extern __shared__ char smraw[];
    uint32_t smb = smem_u32(smraw);
    int tid = threadIdx.x;
    int wid = tid >> 5, lane = tid & 31;
    int gid = lane >> 2, tig = lane & 3;
    int wm = (wid >> 1) * 64, wn = (wid & 1) * 64;
    int m0 = blockIdx.y * 128, n0 = blockIdx.x * 128;
    int a_r = lane & 15, a_c = (lane >> 4) << 3;
    int b_r = ((lane >> 4) << 3) + (lane & 7), b_c = ((lane >> 3) & 1) << 3;

    GEMM_MAIN(Bw)

#pragma unroll
    for (int mi = 0; mi < 4; mi++) {
        int r0 = m0 + wm + mi * 16 + gid;
#pragma unroll
        for (int ni = 0; ni < 8; ni++) {
            int col = n0 + wn + ni * 8 + tig * 2;
            *reinterpret_cast<float2*>(C + (size_t)r0 * EMBED + col) =
                make_float2(acc[mi][ni][0], acc[mi][ni][1]);
            *reinterpret_cast<float2*>(C + (size_t)(r0 + 8) * EMBED + col) =
                make_float2(acc[mi][ni][2], acc[mi][ni][3]);
        }
    }
}

// ---------------- fp16 HMMA causal flash attention, BQ=128, plain QK --------
#define FL_Q_B 65536
#define FL_KV_ST 32768
#define FL_SMEM (FL_Q_B + 2 * FL_KV_ST)  // 131072

__global__ void __launch_bounds__(256) flash_h(const __half* __restrict__ Qg,
                                               const __half* __restrict__ Kg,
                                               const __half* __restrict__ Vg,
                                               __half* __restrict__ Og) {
    extern __shared__ char smraw[];
    uint32_t smb = smem_u32(smraw);
    const uint32_t QS = smb, KV0 = smb + FL_Q_B;

    int tid = threadIdx.x;
    int wid = tid >> 5, lane = tid & 31;
    int gid = lane >> 2, tig = lane & 3;
    int rw0 = wid * 16;

    int bh = blockIdx.x & 31;
    int qb = 15 - (blockIdx.x >> 5);  // big tiles first
    int b = bh >> 4, h = bh & 15;
    int q0 = qb * 128;
    int nkt = 4 * qb + 4;
    size_t tok0 = (size_t)b * NS;

    int a_r = lane & 15, a_c = (lane >> 4) << 3;
    int b_r = ((lane >> 4) << 3) + (lane & 7), b_c = ((lane >> 3) & 1) << 3;

#pragma unroll
    for (int i = 0; i < 16; i++) {  // Q: 128 rows x 256 halves
        int gi = tid + i * 256;
        int r = gi >> 5, g = gi & 31;
        uint32_t off = r * 512 + (((g & 24) | ((g ^ r) & 7)) << 4);
        cp16(QS + off, Qg + (tok0 + q0 + r) * EMBED + h * HD + g * 8);
    }
    auto loadkv = [&](int st, int kt) {
        uint32_t kb = KV0 + st * FL_KV_ST;
        int k0 = kt * 32;
#pragma unroll
        for (int i = 0; i < 4; i++) {
            int gi = tid + i * 256;
            int r = gi >> 5, g = gi & 31;
            uint32_t off = r * 512 + (((g & 24) | ((g ^ r) & 7)) << 4);
            size_t src = (tok0 + k0 + r) * EMBED + h * HD + g * 8;
            cp16(kb + off, Kg + src);
            cp16(kb + 16384 + off, Vg + src);
        }
    };
    loadkv(0, 0);
    CP_COMMIT();

    float o[32][4];
#pragma unroll
    for (int nt = 0; nt < 32; nt++)
#pragma unroll
        for (int q = 0; q < 4; q++) o[nt][q] = 0.f;
    float m0v = -1e30f, m1v = -1e30f, l0v = 0.f, l1v = 0.f;
    int rg0 = q0 + rw0 + gid;

    for (int kt = 0; kt < nkt; kt++) {
        bool have_next = (kt + 1 < nkt);
        if (have_next) { loadkv((kt + 1) & 1, kt + 1); CP_COMMIT(); cp_wait<1>(); }
        else cp_wait<0>();
        __syncthreads();

        int k0 = kt * 32;
        if (k0 <= q0 + rw0 + 15) {
            uint32_t kb = KV0 + (kt & 1) * FL_KV_ST;
            uint32_t vb = kb + 16384;

            float s4[4][4];
#pragma unroll
            for (int nt = 0; nt < 4; nt++)
#pragma unroll
                for (int q = 0; q < 4; q++) s4[nt][q] = 0.f;

#pragma unroll
            for (int kc = 0; kc < 16; kc++) {
                int kk = kc * 16;
                uint32_t ah[4], bh4[2][4];
                ldsm4(ah, QS + swz512(rw0 + a_r, kk + a_c));
#pragma unroll
                for (int np = 0; np < 2; np++)
                    ldsm4(bh4[np], kb + swz512(np * 16 + b_r, kk + b_c));
#pragma unroll
                for (int np = 0; np < 2; np++) {
                    mma16(s4[2 * np], ah, &bh4[np][0]);
                    mma16(s4[2 * np + 1], ah, &bh4[np][2]);
                }
            }

            bool needmask = (k0 + 31 > q0 + rw0);
#pragma unroll
            for (int nt = 0; nt < 4; nt++) {
#pragma unroll
                for (int q = 0; q < 4; q++) s4[nt][q] *= 0.0625f;
                if (needmask) {
                    int c0 = k0 + nt * 8 + 2 * tig;
                    if (c0 > rg0) s4[nt][0] = -1e30f;
                    if (c0 + 1 > rg0) s4[nt][1] = -1e30f;
                    if (c0 > rg0 + 8) s4[nt][2] = -1e30f;
                    if (c0 + 1 > rg0 + 8) s4[nt][3] = -1e30f;
                }
            }

            float mx0 = -1e30f, mx1 = -1e30f;
#pragma unroll
            for (int nt = 0; nt < 4; nt++) {
                mx0 = fmaxf(mx0, fmaxf(s4[nt][0], s4[nt][1]));
                mx1 = fmaxf(mx1, fmaxf(s4[nt][2], s4[nt][3]));
            }
            mx0 = fmaxf(mx0, __shfl_xor_sync(0xffffffffu, mx0, 1));
            mx0 = fmaxf(mx0, __shfl_xor_sync(0xffffffffu, mx0, 2));
            mx1 = fmaxf(mx1, __shfl_xor_sync(0xffffffffu, mx1, 1));
            mx1 = fmaxf(mx1, __shfl_xor_sync(0xffffffffu, mx1, 2));
            float mn0 = fmaxf(m0v, mx0), mn1 = fmaxf(m1v, mx1);
            float cor0 = __expf(m0v - mn0), cor1 = __expf(m1v - mn1);
            m0v = mn0; m1v = mn1;

            float sum0 = 0.f, sum1 = 0.f;
            uint32_t ph[4][2];
#pragma unroll
            for (int nt = 0; nt < 4; nt++) {
                float p0 = __expf(s4[nt][0] - mn0);
                float p1 = __expf(s4[nt][1] - mn0);
                float p2 = __expf(s4[nt][2] - mn1);
                float p3 = __expf(s4[nt][3] - mn1);
                sum0 += p0 + p1; sum1 += p2 + p3;
                __half2 h01 = __floats2half2_rn(p0, p1);
                __half2 h23 = __floats2half2_rn(p2, p3);
                ph[nt][0] = *reinterpret_cast<uint32_t*>(&h01);
                ph[nt][1] = *reinterpret_cast<uint32_t*>(&h23);
            }
            sum0 += __shfl_xor_sync(0xffffffffu, sum0, 1);
            sum0 += __shfl_xor_sync(0xffffffffu, sum0, 2);
            sum1 += __shfl_xor_sync(0xffffffffu, sum1, 1);
            sum1 += __shfl_xor_sync(0xffffffffu, sum1, 2);
            l0v = l0v * cor0 + sum0;
            l1v = l1v * cor1 + sum1;

#pragma unroll
            for (int nt = 0; nt < 32; nt++) {
                o[nt][0] *= cor0; o[nt][1] *= cor0;
                o[nt][2] *= cor1; o[nt][3] *= cor1;
            }

#pragma unroll
            for (int kc = 0; kc < 2; kc++) {
                uint32_t a4[4] = {ph[2 * kc][0], ph[2 * kc][1],
                                  ph[2 * kc + 1][0], ph[2 * kc + 1][1]};
#pragma unroll
                for (int dp = 0; dp < 16; dp++) {
                    uint32_t b4[4];
                    ldsm4t(b4, vb + swz512(kc * 16 + a_r, dp * 16 + a_c));
                    mma16(o[2 * dp], a4, &b4[0]);
                    mma16(o[2 * dp + 1], a4, &b4[2]);
                }
            }
        }
        __syncthreads();
    }

    float inv0 = 1.f / l0v, inv1 = 1.f / l1v;
    __half* r0p = Og + (tok0 + rg0) * EMBED + h * HD;
    __half* r1p = Og + (tok0 + rg0 + 8) * EMBED + h * HD;
#pragma unroll
    for (int nt = 0; nt < 32; nt++) {
        int col = nt * 8 + 2 * tig;
        *reinterpret_cast<__half2*>(r0p + col) =
            __floats2half2_rn(o[nt][0] * inv0, o[nt][1] * inv0);
        *reinterpret_cast<__half2*>(r1p + col) =
            __floats2half2_rn(o[nt][2] * inv1, o[nt][3] * inv1);
    }
}

// ---------------------------------------------------------------------------
extern "C" void kernel_launch(void* const* d_in, const int* in_sizes, int n_in,
                              void* d_out, int out_size) {
    const float* hs = (const float*)d_in[0];
    const int* pid = (const int*)d_in[1];
    const float* qw = (const float*)d_in[2];
    const float* kw = (const float*)d_in[3];
    const float* vw = (const float*)d_in[4];
    const float* ow = (const float*)d_in[5];
    const float* emb = (const float*)d_in[6];
    float* out = (float*)d_out;

    __half *hs_h, *wq_h, *wk_h, *wv_h, *wo_h, *qh, *kh, *vh, *att;
    cudaGetSymbolAddress((void**)&hs_h, g_hs_h);
    cudaGetSymbolAddress((void**)&wq_h, g_wq_h);
    cudaGetSymbolAddress((void**)&wk_h, g_wk_h);
    cudaGetSymbolAddress((void**)&wv_h, g_wv_h);
    cudaGetSymbolAddress((void**)&wo_h, g_wo_h);
    cudaGetSymbolAddress((void**)&qh, g_qh);
    cudaGetSymbolAddress((void**)&kh, g_kh);
    cudaGetSymbolAddress((void**)&vh, g_v);
    cudaGetSymbolAddress((void**)&att, g_att);

    cudaFuncSetAttribute(gemm_qkv, cudaFuncAttributeMaxDynamicSharedMemorySize, GEMM_SMEM);
    cudaFuncSetAttribute(gemm_h, cudaFuncAttributeMaxDynamicSharedMemorySize, GEMM_SMEM);
    cudaFuncSetAttribute(flash_h, cudaFuncAttributeMaxDynamicSharedMemorySize, FL_SMEM);

    int n8 = (int)(NELEM / 8);
    f2h5<<<dim3(n8 / 256, 5), 256>>>((const float4*)hs, (const float4*)qw,
                                     (const float4*)kw, (const float4*)vw,
                                     (const float4*)ow, (uint4*)hs_h, (uint4*)wq_h,
                                     (uint4*)wk_h, (uint4*)wv_h, (uint4*)wo_h, n8);

    gemm_qkv<<<dim3(32, 32, 3), 128, GEMM_SMEM>>>(hs_h, wq_h, wk_h, wv_h, pid, emb,
                                                  qh, kh, vh);

    flash_h<<<512, 256, FL_SMEM>>>(qh, kh, vh, att);

    gemm_h<<<dim3(32, 32), 128, GEMM_SMEM>>>(att, wo_h, out);
}

// round 11
// speedup vs baseline: 10.7960x; 1.0065x over previous
#include <cuda_runtime.h>
#include <cuda_fp16.h>
#include <cstdint>
#include <math.h>

#define EMBED 4096
#define NH 16
#define HD 256
#define NB 2
#define NS 2048
#define NTOK (NB * NS)
#define NELEM ((size_t)NTOK * EMBED)

__device__ __half g_hs_h[NELEM];
__device__ __half g_wq_h[NELEM];
__device__ __half g_wk_h[NELEM];
__device__ __half g_wv_h[NELEM];
__device__ __half g_wo_h[NELEM];
__device__ __half g_qh[NELEM];
__device__ __half g_kh[NELEM];
__device__ __half g_v[NELEM];
__device__ __half g_att[NELEM];

// ---------------- PTX helpers (baseline ISA; tcgen05 is sm_103a-gated) ------
__device__ __forceinline__ uint32_t smem_u32(const void* p) {
    uint32_t a;
    asm("{ .reg .u64 t; cvta.to.shared.u64 t, %1; cvt.u32.u64 %0, t; }"
        : "=r"(a) : "l"(p));
    return a;
}
__device__ __forceinline__ void cp16(uint32_t s, const void* g) {
    asm volatile("cp.async.cg.shared.global [%0], [%1], 16;\n" ::"r"(s), "l"(g));
}
#define CP_COMMIT() asm volatile("cp.async.commit_group;\n" ::: "memory")
template <int N>
__device__ __forceinline__ void cp_wait() {
    asm volatile("cp.async.wait_group %0;\n" ::"n"(N) : "memory");
}
__device__ __forceinline__ void ldsm4(uint32_t* r, uint32_t a) {
    asm volatile("ldmatrix.sync.aligned.m8n8.x4.shared.b16 {%0,%1,%2,%3}, [%4];"
                 : "=r"(r[0]), "=r"(r[1]), "=r"(r[2]), "=r"(r[3]) : "r"(a));
}
__device__ __forceinline__ void ldsm4t(uint32_t* r, uint32_t a) {
    asm volatile("ldmatrix.sync.aligned.m8n8.x4.trans.shared.b16 {%0,%1,%2,%3}, [%4];"
                 : "=r"(r[0]), "=r"(r[1]), "=r"(r[2]), "=r"(r[3]) : "r"(a));
}
__device__ __forceinline__ void mma16(float* c, const uint32_t* a, const uint32_t* b) {
    asm volatile(
        "mma.sync.aligned.m16n8k16.row.col.f32.f16.f16.f32 "
        "{%0,%1,%2,%3}, {%4,%5,%6,%7}, {%8,%9}, {%0,%1,%2,%3};"
        : "+f"(c[0]), "+f"(c[1]), "+f"(c[2]), "+f"(c[3])
        : "r"(a[0]), "r"(a[1]), "r"(a[2]), "r"(a[3]), "r"(b[0]), "r"(b[1]));
}
__device__ __forceinline__ uint32_t swz128(int r, int c) {  // row = 64 halves
    return (uint32_t)(r * 128 + ((((c >> 3) ^ r) & 7) << 4) + ((c & 7) << 1));
}
__device__ __forceinline__ uint32_t swz512(int r, int c) {  // row = 256 halves
    int g = c >> 3;
    return (uint32_t)(r * 512 + (((g & 24) | ((g ^ r) & 7)) << 4) + ((c & 7) << 1));
}

// ---------------- fp32 -> fp16, 5 arrays in one launch ----------------------
__global__ void f2h5(const float4* __restrict__ s0, const float4* __restrict__ s1,
                     const float4* __restrict__ s2, const float4* __restrict__ s3,
                     const float4* __restrict__ s4,
                     uint4* __restrict__ d0, uint4* __restrict__ d1,
                     uint4* __restrict__ d2, uint4* __restrict__ d3,
                     uint4* __restrict__ d4, int n8) {
    int z = blockIdx.y;
    const float4* s = (z == 0) ? s0 : (z == 1) ? s1 : (z == 2) ? s2 : (z == 3) ? s3 : s4;
    uint4* d = (z == 0) ? d0 : (z == 1) ? d1 : (z == 2) ? d2 : (z == 3) ? d3 : d4;
    int i = blockIdx.x * blockDim.x + threadIdx.x;
    if (i < n8) {
        float4 a = s[2 * i], b = s[2 * i + 1];
        __half2 h0 = __floats2half2_rn(a.x, a.y);
        __half2 h1 = __floats2half2_rn(a.z, a.w);
        __half2 h2 = __floats2half2_rn(b.x, b.y);
        __half2 h3 = __floats2half2_rn(b.z, b.w);
        uint4 o;
        o.x = *reinterpret_cast<uint32_t*>(&h0);
        o.y = *reinterpret_cast<uint32_t*>(&h1);
        o.z = *reinterpret_cast<uint32_t*>(&h2);
        o.w = *reinterpret_cast<uint32_t*>(&h3);
        d[i] = o;
    }
}

#define G_STAGE_B 32768
#define GEMM_SMEM (3 * G_STAGE_B)

// ---- variant A: 8 warps (2x4), warp tile 64x32, 256 threads (for gemm_h) ---
#define GEMM_MAIN_A(Bptr)                                                       \
    float acc[4][4][4];                                                         \
    _Pragma("unroll") for (int i = 0; i < 4; i++)                               \
        _Pragma("unroll") for (int j = 0; j < 4; j++)                           \
            _Pragma("unroll") for (int q = 0; q < 4; q++) acc[i][j][q] = 0.f;   \
    auto loadst = [&](int st, int k0) {                                         \
        uint32_t ab = smb + st * G_STAGE_B, bb = ab + 16384;                    \
        _Pragma("unroll") for (int i = 0; i < 4; i++) {                         \
            int gi = tid + i * 256;                                             \
            int r = gi >> 3, g = gi & 7;                                        \
            uint32_t off = r * 128 + (((g ^ r) & 7) << 4);                      \
            cp16(ab + off, A + (size_t)(m0 + r) * EMBED + k0 + g * 8);          \
            cp16(bb + off, Bptr + (size_t)(n0 + r) * EMBED + k0 + g * 8);       \
        }                                                                       \
    };                                                                          \
    loadst(0, 0); CP_COMMIT();                                                  \
    loadst(1, 64); CP_COMMIT();                                                 \
    int s = 0;                                                                  \
    for (int c = 0; c < 64; c++) {                                              \
        cp_wait<1>();                                                           \
        __syncthreads();                                                        \
        if (c + 2 < 64) loadst((s + 2) % 3, (c + 2) * 64);                      \
        CP_COMMIT();                                                            \
        uint32_t ab = smb + s * G_STAGE_B, bb = ab + 16384;                     \
        _Pragma("unroll") for (int kc = 0; kc < 4; kc++) {                      \
            int kk = kc * 16;                                                   \
            uint32_t af[4][4], bf[2][4];                                        \
            _Pragma("unroll") for (int mi = 0; mi < 4; mi++)                    \
                ldsm4(af[mi], ab + swz128(wm + mi * 16 + a_r, kk + a_c));       \
            _Pragma("unroll") for (int np = 0; np < 2; np++)                    \
                ldsm4(bf[np], bb + swz128(wn + np * 16 + b_r, kk + b_c));       \
            _Pragma("unroll") for (int mi = 0; mi < 4; mi++)                    \
                _Pragma("unroll") for (int ni = 0; ni < 4; ni++)                \
                    mma16(acc[mi][ni], af[mi], &bf[ni >> 1][(ni & 1) * 2]);     \
        }                                                                       \
        __syncthreads();                                                        \
        if (++s == 3) s = 0;                                                    \
    }

// ---- variant B: 4 warps (2x2), warp tile 64x64, 128 threads (for gemm_qkv) -
#define GEMM_MAIN_B(Bptr)                                                       \
    float acc[4][8][4];                                                         \
    _Pragma("unroll") for (int i = 0; i < 4; i++)                               \
        _Pragma("unroll") for (int j = 0; j < 8; j++)                           \
            _Pragma("unroll") for (int q = 0; q < 4; q++) acc[i][j][q] = 0.f;   \
    auto loadst = [&](int st, int k0) {                                         \
        uint32_t ab = smb + st * G_STAGE_B, bb = ab + 16384;                    \
        _Pragma("unroll") for (int i = 0; i < 8; i++) {                         \
            int gi = tid + i * 128;                                             \
            int r = gi >> 3, g = gi & 7;                                        \
            uint32_t off = r * 128 + (((g ^ r) & 7) << 4);                      \
            cp16(ab + off, A + (size_t)(m0 + r) * EMBED + k0 + g * 8);          \
            cp16(bb + off, Bptr + (size_t)(n0 + r) * EMBED + k0 + g * 8);       \
        }                                                                       \
    };                                                                          \
    loadst(0, 0); CP_COMMIT();                                                  \
    loadst(1, 64); CP_COMMIT();                                                 \
    int s = 0;                                                                  \
    for (int c = 0; c < 64; c++) {                                              \
        cp_wait<1>();                                                           \
        __syncthreads();                                                        \
        if (c + 2 < 64) loadst((s + 2) % 3, (c + 2) * 64);                      \
        CP_COMMIT();                                                            \
        uint32_t ab = smb + s * G_STAGE_B, bb = ab + 16384;                     \
        _Pragma("unroll") for (int kc = 0; kc < 4; kc++) {                      \
            int kk = kc * 16;                                                   \
            uint32_t af[4][4], bf[4][4];                                        \
            _Pragma("unroll") for (int mi = 0; mi < 4; mi++)                    \
                ldsm4(af[mi], ab + swz128(wm + mi * 16 + a_r, kk + a_c));       \
            _Pragma("unroll") for (int np = 0; np < 4; np++)                    \
                ldsm4(bf[np], bb + swz128(wn + np * 16 + b_r, kk + b_c));       \
            _Pragma("unroll") for (int mi = 0; mi < 4; mi++)                    \
                _Pragma("unroll") for (int ni = 0; ni < 8; ni++)                \
                    mma16(acc[mi][ni], af[mi], &bf[ni >> 1][(ni & 1) * 2]);     \
        }                                                                       \
        __syncthreads();                                                        \
        if (++s == 3) s = 0;                                                    \
    }

// Fused QKV with rotary in epilogue, plain fp16 outputs. grid (32,32,3), 128thr.
__global__ void __launch_bounds__(128, 2) gemm_qkv(const __half* __restrict__ A,
                                                   const __half* __restrict__ Wq,
                                                   const __half* __restrict__ Wk,
                                                   const __half* __restrict__ Wv,
                                                   const int* __restrict__ pid,
                                                   const float* __restrict__ emb,
                                                   __half* __restrict__ Qh,
                                                   __half* __restrict__ Kh,
                                                   __half* __restrict__ Cv) {
    extern __shared__ char smraw[];
    uint32_t smb = smem_u32(smraw);
    int z = blockIdx.z;
    const __half* B = (z == 0) ? Wq : (z == 1) ? Wk : Wv;

    int tid = threadIdx.x;
    int wid = tid >> 5, lane = tid & 31;
    int gid = lane >> 2, tig = lane & 3;
    int wm = (wid >> 1) * 64, wn = (wid & 1) * 64;
    int m0 = blockIdx.y * 128, n0 = blockIdx.x * 128;
    int a_r = lane & 15, a_c = (lane >> 4) << 3;
    int b_r = ((lane >> 4) << 3) + (lane & 7), b_c = ((lane >> 3) & 1) << 3;

    GEMM_MAIN_B(B)

    if (z == 2) {
#pragma unroll
        for (int mi = 0; mi < 4; mi++) {
            int r0 = m0 + wm + mi * 16 + gid;
#pragma unroll
            for (int ni = 0; ni < 8; ni++) {
                int col = n0 + wn + ni * 8 + tig * 2;
                *reinterpret_cast<__half2*>(Cv + (size_t)r0 * EMBED + col) =
                    __floats2half2_rn(acc[mi][ni][0], acc[mi][ni][1]);
                *reinterpret_cast<__half2*>(Cv + (size_t)(r0 + 8) * EMBED + col) =
                    __floats2half2_rn(acc[mi][ni][2], acc[mi][ni][3]);
            }
        }
    } else {
        __half* Hi = (z == 0) ? Qh : Kh;
#pragma unroll
        for (int mi = 0; mi < 4; mi++) {
            int r0 = m0 + wm + mi * 16 + gid;
            int p0 = pid[r0], p1 = pid[r0 + 8];
#pragma unroll
            for (int ni = 0; ni < 8; ni++) {
                int col = n0 + wn + ni * 8 + tig * 2;
                float v0 = acc[mi][ni][0], v1 = acc[mi][ni][1];
                float v2 = acc[mi][ni][2], v3 = acc[mi][ni][3];
                int c = col & 255;
                if (c < 64) {
                    int pr = c >> 1;
                    float sv0 = emb[p0 * 64 + pr], cv0 = emb[p0 * 64 + 32 + pr];
                    float sv1 = emb[p1 * 64 + pr], cv1 = emb[p1 * 64 + 32 + pr];
                    float a0 = v0 * cv0 - v1 * sv0, b0 = v1 * cv0 + v0 * sv0;
                    v0 = a0; v1 = b0;
                    float a1 = v2 * cv1 - v3 * sv1, b1 = v3 * cv1 + v2 * sv1;
                    v2 = a1; v3 = b1;
                }
                size_t o0 = (size_t)r0 * EMBED + col;
                size_t o1 = (size_t)(r0 + 8) * EMBED + col;
                *reinterpret_cast<__half2*>(Hi + o0) = __floats2half2_rn(v0, v1);
                *reinterpret_cast<__half2*>(Hi + o1) = __floats2half2_rn(v2, v3);
            }
        }
    }
}

// Out projection: half in, float out. 256 threads, 8 warps (round-8 config).
__global__ void __launch_bounds__(256, 2) gemm_h(const __half* __restrict__ A,
                                                 const __half* __restrict__ Bw,
                                                 float* __restrict__ C) {
    extern __shared__ char smraw[];
    uint32_t smb = smem_u32(smraw);
    int tid = threadIdx.x;
    int wid = tid >> 5, lane = tid & 31;
    int gid = lane >> 2, tig = lane & 3;
    int wm = (wid >> 2) * 64, wn = (wid & 3) * 32;
    int m0 = blockIdx.y * 128, n0 = blockIdx.x * 128;
    int a_r = lane & 15, a_c = (lane >> 4) << 3;
    int b_r = ((lane >> 4) << 3) + (lane & 7), b_c = ((lane >> 3) & 1) << 3;

    GEMM_MAIN_A(Bw)

#pragma unroll
    for (int mi = 0; mi < 4; mi++) {
        int r0 = m0 + wm + mi * 16 + gid;
#pragma unroll
        for (int ni = 0; ni < 4; ni++) {
            int col = n0 + wn + ni * 8 + tig * 2;
            *reinterpret_cast<float2*>(C + (size_t)r0 * EMBED + col) =
                make_float2(acc[mi][ni][0], acc[mi][ni][1]);
            *reinterpret_cast<float2*>(C + (size_t)(r0 + 8) * EMBED + col) =
                make_float2(acc[mi][ni][2], acc[mi][ni][3]);
        }
    }
}

// ---------------- fp16 HMMA causal flash attention, BQ=128, plain QK --------
#define FL_Q_B 65536
#define FL_KV_ST 32768
#define FL_SMEM (FL_Q_B + 2 * FL_KV_ST)  // 131072

__global__ void __launch_bounds__(256) flash_h(const __half* __restrict__ Qg,
                                               const __half* __restrict__ Kg,
                                               const __half* __restrict__ Vg,
                                               __half* __restrict__ Og) {
    extern __shared__ char smraw[];
    uint32_t smb = smem_u32(smraw);
    const uint32_t QS = smb, KV0 = smb + FL_Q_B;

    int tid = threadIdx.x;
    int wid = tid >> 5, lane = tid & 31;
    int gid = lane >> 2, tig = lane & 3;
    int rw0 = wid * 16;

    int bh = blockIdx.x & 31;
    int qb = 15 - (blockIdx.x >> 5);  // big tiles first
    int b = bh >> 4, h = bh & 15;
    int q0 = qb * 128;
    int nkt = 4 * qb + 4;
    size_t tok0 = (size_t)b * NS;

    int a_r = lane & 15, a_c = (lane >> 4) << 3;
    int b_r = ((lane >> 4) << 3) + (lane & 7), b_c = ((lane >> 3) & 1) << 3;

#pragma unroll
    for (int i = 0; i < 16; i++) {  // Q: 128 rows x 256 halves
        int gi = tid + i * 256;
        int r = gi >> 5, g = gi & 31;
        uint32_t off = r * 512 + (((g & 24) | ((g ^ r) & 7)) << 4);
        cp16(QS + off, Qg + (tok0 + q0 + r) * EMBED + h * HD + g * 8);
    }
    auto loadkv = [&](int st, int kt) {
        uint32_t kb = KV0 + st * FL_KV_ST;
        int k0 = kt * 32;
#pragma unroll
        for (int i = 0; i < 4; i++) {
            int gi = tid + i * 256;
            int r = gi >> 5, g = gi & 31;
            uint32_t off = r * 512 + (((g & 24) | ((g ^ r) & 7)) << 4);
            size_t src = (tok0 + k0 + r) * EMBED + h * HD + g * 8;
            cp16(kb + off, Kg + src);
            cp16(kb + 16384 + off, Vg + src);
        }
    };
    loadkv(0, 0);
    CP_COMMIT();

    float o[32][4];
#pragma unroll
    for (int nt = 0; nt < 32; nt++)
#pragma unroll
        for (int q = 0; q < 4; q++) o[nt][q] = 0.f;
    float m0v = -1e30f, m1v = -1e30f, l0v = 0.f, l1v = 0.f;
    int rg0 = q0 + rw0 + gid;

    for (int kt = 0; kt < nkt; kt++) {
        bool have_next = (kt + 1 < nkt);
        if (have_next) { loadkv((kt + 1) & 1, kt + 1); CP_COMMIT(); cp_wait<1>(); }
        else cp_wait<0>();
        __syncthreads();

        int k0 = kt * 32;
        if (k0 <= q0 + rw0 + 15) {
            uint32_t kb = KV0 + (kt & 1) * FL_KV_ST;
            uint32_t vb = kb + 16384;

            float s4[4][4];
#pragma unroll
            for (int nt = 0; nt < 4; nt++)
#pragma unroll
                for (int q = 0; q < 4; q++) s4[nt][q] = 0.f;

#pragma unroll
            for (int kc = 0; kc < 16; kc++) {
                int kk = kc * 16;
                uint32_t ah[4], bh4[2][4];
                ldsm4(ah, QS + swz512(rw0 + a_r, kk + a_c));
#pragma unroll
                for (int np = 0; np < 2; np++)
                    ldsm4(bh4[np], kb + swz512(np * 16 + b_r, kk + b_c));
#pragma unroll
                for (int np = 0; np < 2; np++) {
                    mma16(s4[2 * np], ah, &bh4[np][0]);
                    mma16(s4[2 * np + 1], ah, &bh4[np][2]);
                }
            }

            bool needmask = (k0 + 31 > q0 + rw0);
#pragma unroll
            for (int nt = 0; nt < 4; nt++) {
#pragma unroll
                for (int q = 0; q < 4; q++) s4[nt][q] *= 0.0625f;
                if (needmask) {
                    int c0 = k0 + nt * 8 + 2 * tig;
                    if (c0 > rg0) s4[nt][0] = -1e30f;
                    if (c0 + 1 > rg0) s4[nt][1] = -1e30f;
                    if (c0 > rg0 + 8) s4[nt][2] = -1e30f;
                    if (c0 + 1 > rg0 + 8) s4[nt][3] = -1e30f;
                }
            }

            float mx0 = -1e30f, mx1 = -1e30f;
#pragma unroll
            for (int nt = 0; nt < 4; nt++) {
                mx0 = fmaxf(mx0, fmaxf(s4[nt][0], s4[nt][1]));
                mx1 = fmaxf(mx1, fmaxf(s4[nt][2], s4[nt][3]));
            }
            mx0 = fmaxf(mx0, __shfl_xor_sync(0xffffffffu, mx0, 1));
            mx0 = fmaxf(mx0, __shfl_xor_sync(0xffffffffu, mx0, 2));
            mx1 = fmaxf(mx1, __shfl_xor_sync(0xffffffffu, mx1, 1));
            mx1 = fmaxf(mx1, __shfl_xor_sync(0xffffffffu, mx1, 2));
            float mn0 = fmaxf(m0v, mx0), mn1 = fmaxf(m1v, mx1);
            float cor0 = __expf(m0v - mn0), cor1 = __expf(m1v - mn1);
            m0v = mn0; m1v = mn1;

            float sum0 = 0.f, sum1 = 0.f;
            uint32_t ph[4][2];
#pragma unroll
            for (int nt = 0; nt < 4; nt++) {
                float p0 = __expf(s4[nt][0] - mn0);
                float p1 = __expf(s4[nt][1] - mn0);
                float p2 = __expf(s4[nt][2] - mn1);
                float p3 = __expf(s4[nt][3] - mn1);
                sum0 += p0 + p1; sum1 += p2 + p3;
                __half2 h01 = __floats2half2_rn(p0, p1);
                __half2 h23 = __floats2half2_rn(p2, p3);
                ph[nt][0] = *reinterpret_cast<uint32_t*>(&h01);
                ph[nt][1] = *reinterpret_cast<uint32_t*>(&h23);
            }
            sum0 += __shfl_xor_sync(0xffffffffu, sum0, 1);
            sum0 += __shfl_xor_sync(0xffffffffu, sum0, 2);
            sum1 += __shfl_xor_sync(0xffffffffu, sum1, 1);
            sum1 += __shfl_xor_sync(0xffffffffu, sum1, 2);
            l0v = l0v * cor0 + sum0;
            l1v = l1v * cor1 + sum1;

#pragma unroll
            for (int nt = 0; nt < 32; nt++) {
                o[nt][0] *= cor0; o[nt][1] *= cor0;
                o[nt][2] *= cor1; o[nt][3] *= cor1;
            }

#pragma unroll
            for (int kc = 0; kc < 2; kc++) {
                uint32_t a4[4] = {ph[2 * kc][0], ph[2 * kc][1],
                                  ph[2 * kc + 1][0], ph[2 * kc + 1][1]};
#pragma unroll
                for (int dp = 0; dp < 16; dp++) {
                    uint32_t b4[4];
                    ldsm4t(b4, vb + swz512(kc * 16 + a_r, dp * 16 + a_c));
                    mma16(o[2 * dp], a4, &b4[0]);
                    mma16(o[2 * dp + 1], a4, &b4[2]);
                }
            }
        }
        __syncthreads();
    }

    float inv0 = 1.f / l0v, inv1 = 1.f / l1v;
    __half* r0p = Og + (tok0 + rg0) * EMBED + h * HD;
    __half* r1p = Og + (tok0 + rg0 + 8) * EMBED + h * HD;
#pragma unroll
    for (int nt = 0; nt < 32; nt++) {
        int col = nt * 8 + 2 * tig;
        *reinterpret_cast<__half2*>(r0p + col) =
            __floats2half2_rn(o[nt][0] * inv0, o[nt][1] * inv0);
        *reinterpret_cast<__half2*>(r1p + col) =
            __floats2half2_rn(o[nt][2] * inv1, o[nt][3] * inv1);
    }
}

// ---------------------------------------------------------------------------
extern "C" void kernel_launch(void* const* d_in, const int* in_sizes, int n_in,
                              void* d_out, int out_size) {
    const float* hs = (const float*)d_in[0];
    const int* pid = (const int*)d_in[1];
    const float* qw = (const float*)d_in[2];
    const float* kw = (const float*)d_in[3];
    const float* vw = (const float*)d_in[4];
    const float* ow = (const float*)d_in[5];
    const float* emb = (const float*)d_in[6];
    float* out = (float*)d_out;

    __half *hs_h, *wq_h, *wk_h, *wv_h, *wo_h, *qh, *kh, *vh, *att;
    cudaGetSymbolAddress((void**)&hs_h, g_hs_h);
    cudaGetSymbolAddress((void**)&wq_h, g_wq_h);
    cudaGetSymbolAddress((void**)&wk_h, g_wk_h);
    cudaGetSymbolAddress((void**)&wv_h, g_wv_h);
    cudaGetSymbolAddress((void**)&wo_h, g_wo_h);
    cudaGetSymbolAddress((void**)&qh, g_qh);
    cudaGetSymbolAddress((void**)&kh, g_kh);
    cudaGetSymbolAddress((void**)&vh, g_v);
    cudaGetSymbolAddress((void**)&att, g_att);

    cudaFuncSetAttribute(gemm_qkv, cudaFuncAttributeMaxDynamicSharedMemorySize, GEMM_SMEM);
    cudaFuncSetAttribute(gemm_h, cudaFuncAttributeMaxDynamicSharedMemorySize, GEMM_SMEM);
    cudaFuncSetAttribute(flash_h, cudaFuncAttributeMaxDynamicSharedMemorySize, FL_SMEM);

    int n8 = (int)(NELEM / 8);
    f2h5<<<dim3(n8 / 256, 5), 256>>>((const float4*)hs, (const float4*)qw,
                                     (const float4*)kw, (const float4*)vw,
                                     (const float4*)ow, (uint4*)hs_h, (uint4*)wq_h,
                                     (uint4*)wk_h, (uint4*)wv_h, (uint4*)wo_h, n8);

    gemm_qkv<<<dim3(32, 32, 3), 128, GEMM_SMEM>>>(hs_h, wq_h, wk_h, wv_h, pid, emb,
                                                  qh, kh, vh);

    flash_h<<<512, 256, FL_SMEM>>>(qh, kh, vh, att);

    gemm_h<<<dim3(32, 32), 256, GEMM_SMEM>>>(att, wo_h, out);
}

// round 12
// speedup vs baseline: 11.1303x; 1.0310x over previous
#include <cuda_runtime.h>
#include <cuda_fp16.h>
#include <cstdint>
#include <math.h>

#define EMBED 4096
#define NH 16
#define HD 256
#define NB 2
#define NS 2048
#define NTOK (NB * NS)
#define NELEM ((size_t)NTOK * EMBED)

__device__ __half g_hs_h[NELEM];
__device__ __half g_wq_h[NELEM];
__device__ __half g_wk_h[NELEM];
__device__ __half g_wv_h[NELEM];
__device__ __half g_wo_h[NELEM];
__device__ __half g_qh[NELEM];
__device__ __half g_kh[NELEM];
__device__ __half g_v[NELEM];
__device__ __half g_att[NELEM];

// ---------------- PTX helpers (baseline ISA; tcgen05 is sm_103a-gated) ------
__device__ __forceinline__ uint32_t smem_u32(const void* p) {
    uint32_t a;
    asm("{ .reg .u64 t; cvta.to.shared.u64 t, %1; cvt.u32.u64 %0, t; }"
        : "=r"(a) : "l"(p));
    return a;
}
__device__ __forceinline__ void cp16(uint32_t s, const void* g) {
    asm volatile("cp.async.cg.shared.global [%0], [%1], 16;\n" ::"r"(s), "l"(g));
}
#define CP_COMMIT() asm volatile("cp.async.commit_group;\n" ::: "memory")
template <int N>
__device__ __forceinline__ void cp_wait() {
    asm volatile("cp.async.wait_group %0;\n" ::"n"(N) : "memory");
}
__device__ __forceinline__ void ldsm4(uint32_t* r, uint32_t a) {
    asm volatile("ldmatrix.sync.aligned.m8n8.x4.shared.b16 {%0,%1,%2,%3}, [%4];"
                 : "=r"(r[0]), "=r"(r[1]), "=r"(r[2]), "=r"(r[3]) : "r"(a));
}
__device__ __forceinline__ void ldsm4t(uint32_t* r, uint32_t a) {
    asm volatile("ldmatrix.sync.aligned.m8n8.x4.trans.shared.b16 {%0,%1,%2,%3}, [%4];"
                 : "=r"(r[0]), "=r"(r[1]), "=r"(r[2]), "=r"(r[3]) : "r"(a));
}
__device__ __forceinline__ void mma16(float* c, const uint32_t* a, const uint32_t* b) {
    asm volatile(
        "mma.sync.aligned.m16n8k16.row.col.f32.f16.f16.f32 "
        "{%0,%1,%2,%3}, {%4,%5,%6,%7}, {%8,%9}, {%0,%1,%2,%3};"
        : "+f"(c[0]), "+f"(c[1]), "+f"(c[2]), "+f"(c[3])
        : "r"(a[0]), "r"(a[1]), "r"(a[2]), "r"(a[3]), "r"(b[0]), "r"(b[1]));
}
__device__ __forceinline__ uint32_t swz128(int r, int c) {  // row = 64 halves
    return (uint32_t)(r * 128 + ((((c >> 3) ^ r) & 7) << 4) + ((c & 7) << 1));
}
__device__ __forceinline__ uint32_t swz512(int r, int c) {  // row = 256 halves
    int g = c >> 3;
    return (uint32_t)(r * 512 + (((g & 24) | ((g ^ r) & 7)) << 4) + ((c & 7) << 1));
}

// ---------------- fp32 -> fp16, 5 arrays in one launch ----------------------
__global__ void f2h5(const float4* __restrict__ s0, const float4* __restrict__ s1,
                     const float4* __restrict__ s2, const float4* __restrict__ s3,
                     const float4* __restrict__ s4,
                     uint4* __restrict__ d0, uint4* __restrict__ d1,
                     uint4* __restrict__ d2, uint4* __restrict__ d3,
                     uint4* __restrict__ d4, int n8) {
    int z = blockIdx.y;
    const float4* s = (z == 0) ? s0 : (z == 1) ? s1 : (z == 2) ? s2 : (z == 3) ? s3 : s4;
    uint4* d = (z == 0) ? d0 : (z == 1) ? d1 : (z == 2) ? d2 : (z == 3) ? d3 : d4;
    int i = blockIdx.x * blockDim.x + threadIdx.x;
    if (i < n8) {
        float4 a = s[2 * i], b = s[2 * i + 1];
        __half2 h0 = __floats2half2_rn(a.x, a.y);
        __half2 h1 = __floats2half2_rn(a.z, a.w);
        __half2 h2 = __floats2half2_rn(b.x, b.y);
        __half2 h3 = __floats2half2_rn(b.z, b.w);
        uint4 o;
        o.x = *reinterpret_cast<uint32_t*>(&h0);
        o.y = *reinterpret_cast<uint32_t*>(&h1);
        o.z = *reinterpret_cast<uint32_t*>(&h2);
        o.w = *reinterpret_cast<uint32_t*>(&h3);
        d[i] = o;
    }
}

#define G_STAGE_B 32768
#define GEMM_SMEM (3 * G_STAGE_B)

// ---- variant A: 8 warps (2x4), warp tile 64x32, 256 threads (for gemm_h) ---
#define GEMM_MAIN_A(Bptr)                                                       \
    float acc[4][4][4];                                                         \
    _Pragma("unroll") for (int i = 0; i < 4; i++)                               \
        _Pragma("unroll") for (int j = 0; j < 4; j++)                           \
            _Pragma("unroll") for (int q = 0; q < 4; q++) acc[i][j][q] = 0.f;   \
    auto loadst = [&](int st, int k0) {                                         \
        uint32_t ab = smb + st * G_STAGE_B, bb = ab + 16384;                    \
        _Pragma("unroll") for (int i = 0; i < 4; i++) {                         \
            int gi = tid + i * 256;                                             \
            int r = gi >> 3, g = gi & 7;                                        \
            uint32_t off = r * 128 + (((g ^ r) & 7) << 4);                      \
            cp16(ab + off, A + (size_t)(m0 + r) * EMBED + k0 + g * 8);          \
            cp16(bb + off, Bptr + (size_t)(n0 + r) * EMBED + k0 + g * 8);       \
        }                                                                       \
    };                                                                          \
    loadst(0, 0); CP_COMMIT();                                                  \
    loadst(1, 64); CP_COMMIT();                                                 \
    int s = 0;                                                                  \
    for (int c = 0; c < 64; c++) {                                              \
        cp_wait<1>();                                                           \
        __syncthreads();                                                        \
        if (c + 2 < 64) loadst((s + 2) % 3, (c + 2) * 64);                      \
        CP_COMMIT();                                                            \
        uint32_t ab = smb + s * G_STAGE_B, bb = ab + 16384;                     \
        _Pragma("unroll") for (int kc = 0; kc < 4; kc++) {                      \
            int kk = kc * 16;                                                   \
            uint32_t af[4][4], bf[2][4];                                        \
            _Pragma("unroll") for (int mi = 0; mi < 4; mi++)                    \
                ldsm4(af[mi], ab + swz128(wm + mi * 16 + a_r, kk + a_c));       \
            _Pragma("unroll") for (int np = 0; np < 2; np++)                    \
                ldsm4(bf[np], bb + swz128(wn + np * 16 + b_r, kk + b_c));       \
            _Pragma("unroll") for (int mi = 0; mi < 4; mi++)                    \
                _Pragma("unroll") for (int ni = 0; ni < 4; ni++)                \
                    mma16(acc[mi][ni], af[mi], &bf[ni >> 1][(ni & 1) * 2]);     \
        }                                                                       \
        __syncthreads();                                                        \
        if (++s == 3) s = 0;                                                    \
    }

// ---- variant B: 4 warps (2x2), warp tile 64x64, 128 threads (for gemm_qkv) -
#define GEMM_MAIN_B(Bptr)                                                       \
    float acc[4][8][4];                                                         \
    _Pragma("unroll") for (int i = 0; i < 4; i++)                               \
        _Pragma("unroll") for (int j = 0; j < 8; j++)                           \
            _Pragma("unroll") for (int q = 0; q < 4; q++) acc[i][j][q] = 0.f;   \
    auto loadst = [&](int st, int k0) {                                         \
        uint32_t ab = smb + st * G_STAGE_B, bb = ab + 16384;                    \
        _Pragma("unroll") for (int i = 0; i < 8; i++) {                         \
            int gi = tid + i * 128;                                             \
            int r = gi >> 3, g = gi & 7;                                        \
            uint32_t off = r * 128 + (((g ^ r) & 7) << 4);                      \
            cp16(ab + off, A + (size_t)(m0 + r) * EMBED + k0 + g * 8);          \
            cp16(bb + off, Bptr + (size_t)(n0 + r) * EMBED + k0 + g * 8);       \
        }                                                                       \
    };                                                                          \
    loadst(0, 0); CP_COMMIT();                                                  \
    loadst(1, 64); CP_COMMIT();                                                 \
    int s = 0;                                                                  \
    for (int c = 0; c < 64; c++) {                                              \
        cp_wait<1>();                                                           \
        __syncthreads();                                                        \
        if (c + 2 < 64) loadst((s + 2) % 3, (c + 2) * 64);                      \
        CP_COMMIT();                                                            \
        uint32_t ab = smb + s * G_STAGE_B, bb = ab + 16384;                     \
        _Pragma("unroll") for (int kc = 0; kc < 4; kc++) {                      \
            int kk = kc * 16;                                                   \
            uint32_t af[4][4], bf[4][4];                                        \
            _Pragma("unroll") for (int mi = 0; mi < 4; mi++)                    \
                ldsm4(af[mi], ab + swz128(wm + mi * 16 + a_r, kk + a_c));       \
            _Pragma("unroll") for (int np = 0; np < 4; np++)                    \
                ldsm4(bf[np], bb + swz128(wn + np * 16 + b_r, kk + b_c));       \
            _Pragma("unroll") for (int mi = 0; mi < 4; mi++)                    \
                _Pragma("unroll") for (int ni = 0; ni < 8; ni++)                \
                    mma16(acc[mi][ni], af[mi], &bf[ni >> 1][(ni & 1) * 2]);     \
        }                                                                       \
        __syncthreads();                                                        \
        if (++s == 3) s = 0;                                                    \
    }

// Fused QKV with rotary in epilogue, plain fp16 outputs. grid (32,32,3), 128thr.
__global__ void __launch_bounds__(128, 2) gemm_qkv(const __half* __restrict__ A,
                                                   const __half* __restrict__ Wq,
                                                   const __half* __restrict__ Wk,
                                                   const __half* __restrict__ Wv,
                                                   const int* __restrict__ pid,
                                                   const float* __restrict__ emb,
                                                   __half* __restrict__ Qh,
                                                   __half* __restrict__ Kh,
                                                   __half* __restrict__ Cv) {
    extern __shared__ char smraw[];
    uint32_t smb = smem_u32(smraw);
    int z = blockIdx.z;
    const __half* B = (z == 0) ? Wq : (z == 1) ? Wk : Wv;

    int tid = threadIdx.x;
    int wid = tid >> 5, lane = tid & 31;
    int gid = lane >> 2, tig = lane & 3;
    int wm = (wid >> 1) * 64, wn = (wid & 1) * 64;
    int m0 = blockIdx.y * 128, n0 = blockIdx.x * 128;
    int a_r = lane & 15, a_c = (lane >> 4) << 3;
    int b_r = ((lane >> 4) << 3) + (lane & 7), b_c = ((lane >> 3) & 1) << 3;

    GEMM_MAIN_B(B)

    if (z == 2) {
#pragma unroll
        for (int mi = 0; mi < 4; mi++) {
            int r0 = m0 + wm + mi * 16 + gid;
#pragma unroll
            for (int ni = 0; ni < 8; ni++) {
                int col = n0 + wn + ni * 8 + tig * 2;
                *reinterpret_cast<__half2*>(Cv + (size_t)r0 * EMBED + col) =
                    __floats2half2_rn(acc[mi][ni][0], acc[mi][ni][1]);
                *reinterpret_cast<__half2*>(Cv + (size_t)(r0 + 8) * EMBED + col) =
                    __floats2half2_rn(acc[mi][ni][2], acc[mi][ni][3]);
            }
        }
    } else {
        __half* Hi = (z == 0) ? Qh : Kh;
#pragma unroll
        for (int mi = 0; mi < 4; mi++) {
            int r0 = m0 + wm + mi * 16 + gid;
            int p0 = pid[r0], p1 = pid[r0 + 8];
#pragma unroll
            for (int ni = 0; ni < 8; ni++) {
                int col = n0 + wn + ni * 8 + tig * 2;
                float v0 = acc[mi][ni][0], v1 = acc[mi][ni][1];
                float v2 = acc[mi][ni][2], v3 = acc[mi][ni][3];
                int c = col & 255;
                if (c < 64) {
                    int pr = c >> 1;
                    float sv0 = emb[p0 * 64 + pr], cv0 = emb[p0 * 64 + 32 + pr];
                    float sv1 = emb[p1 * 64 + pr], cv1 = emb[p1 * 64 + 32 + pr];
                    float a0 = v0 * cv0 - v1 * sv0, b0 = v1 * cv0 + v0 * sv0;
                    v0 = a0; v1 = b0;
                    float a1 = v2 * cv1 - v3 * sv1, b1 = v3 * cv1 + v2 * sv1;
                    v2 = a1; v3 = b1;
                }
                size_t o0 = (size_t)r0 * EMBED + col;
                size_t o1 = (size_t)(r0 + 8) * EMBED + col;
                *reinterpret_cast<__half2*>(Hi + o0) = __floats2half2_rn(v0, v1);
                *reinterpret_cast<__half2*>(Hi + o1) = __floats2half2_rn(v2, v3);
            }
        }
    }
}

// Out projection: half in, float out. 256 threads, 8 warps (round-8 config).
__global__ void __launch_bounds__(256, 2) gemm_h(const __half* __restrict__ A,
                                                 const __half* __restrict__ Bw,
                                                 float* __restrict__ C) {
    extern __shared__ char smraw[];
    uint32_t smb = smem_u32(smraw);
    int tid = threadIdx.x;
    int wid = tid >> 5, lane = tid & 31;
    int gid = lane >> 2, tig = lane & 3;
    int wm = (wid >> 2) * 64, wn = (wid & 3) * 32;
    int m0 = blockIdx.y * 128, n0 = blockIdx.x * 128;
    int a_r = lane & 15, a_c = (lane >> 4) << 3;
    int b_r = ((lane >> 4) << 3) + (lane & 7), b_c = ((lane >> 3) & 1) << 3;

    GEMM_MAIN_A(Bw)

#pragma unroll
    for (int mi = 0; mi < 4; mi++) {
        int r0 = m0 + wm + mi * 16 + gid;
#pragma unroll
        for (int ni = 0; ni < 4; ni++) {
            int col = n0 + wn + ni * 8 + tig * 2;
            *reinterpret_cast<float2*>(C + (size_t)r0 * EMBED + col) =
                make_float2(acc[mi][ni][0], acc[mi][ni][1]);
            *reinterpret_cast<float2*>(C + (size_t)(r0 + 8) * EMBED + col) =
                make_float2(acc[mi][ni][2], acc[mi][ni][3]);
        }
    }
}

// ---------------- fp16 HMMA causal flash attention, BQ=128, BK=64 -----------
#define FL_Q_B 65536
#define FL_KV_ST 65536
#define FL_SMEM (FL_Q_B + 2 * FL_KV_ST)  // 196608

__global__ void __launch_bounds__(256) flash_h(const __half* __restrict__ Qg,
                                               const __half* __restrict__ Kg,
                                               const __half* __restrict__ Vg,
                                               __half* __restrict__ Og) {
    extern __shared__ char smraw[];
    uint32_t smb = smem_u32(smraw);
    const uint32_t QS = smb, KV0 = smb + FL_Q_B;

    int tid = threadIdx.x;
    int wid = tid >> 5, lane = tid & 31;
    int gid = lane >> 2, tig = lane & 3;
    int rw0 = wid * 16;

    int bh = blockIdx.x & 31;
    int qb = 15 - (blockIdx.x >> 5);  // big tiles first
    int b = bh >> 4, h = bh & 15;
    int q0 = qb * 128;
    int nkt = 2 * qb + 2;             // 64-wide k tiles
    size_t tok0 = (size_t)b * NS;

    int a_r = lane & 15, a_c = (lane >> 4) << 3;
    int b_r = ((lane >> 4) << 3) + (lane & 7), b_c = ((lane >> 3) & 1) << 3;

#pragma unroll
    for (int i = 0; i < 16; i++) {  // Q: 128 rows x 256 halves
        int gi = tid + i * 256;
        int r = gi >> 5, g = gi & 31;
        uint32_t off = r * 512 + (((g & 24) | ((g ^ r) & 7)) << 4);
        cp16(QS + off, Qg + (tok0 + q0 + r) * EMBED + h * HD + g * 8);
    }
    auto loadkv = [&](int st, int kt) {
        uint32_t kb = KV0 + st * FL_KV_ST;
        int k0 = kt * 64;
#pragma unroll
        for (int i = 0; i < 8; i++) {  // 64 rows x 256 halves, K and V
            int gi = tid + i * 256;
            int r = gi >> 5, g = gi & 31;
            uint32_t off = r * 512 + (((g & 24) | ((g ^ r) & 7)) << 4);
            size_t src = (tok0 + k0 + r) * EMBED + h * HD + g * 8;
            cp16(kb + off, Kg + src);
            cp16(kb + 32768 + off, Vg + src);
        }
    };
    loadkv(0, 0);
    CP_COMMIT();

    float o[32][4];
#pragma unroll
    for (int nt = 0; nt < 32; nt++)
#pragma unroll
        for (int q = 0; q < 4; q++) o[nt][q] = 0.f;
    float m0v = -1e30f, m1v = -1e30f, l0v = 0.f, l1v = 0.f;
    int rg0 = q0 + rw0 + gid;

    for (int kt = 0; kt < nkt; kt++) {
        bool have_next = (kt + 1 < nkt);
        if (have_next) { loadkv((kt + 1) & 1, kt + 1); CP_COMMIT(); cp_wait<1>(); }
        else cp_wait<0>();
        __syncthreads();

        int k0 = kt * 64;
        if (k0 <= q0 + rw0 + 15) {
            uint32_t kb = KV0 + (kt & 1) * FL_KV_ST;
            uint32_t vb = kb + 32768;

            float s4[8][4];
#pragma unroll
            for (int nt = 0; nt < 8; nt++)
#pragma unroll
                for (int q = 0; q < 4; q++) s4[nt][q] = 0.f;

#pragma unroll
            for (int kc = 0; kc < 16; kc++) {
                int kk = kc * 16;
                uint32_t ah[4], bh4[4][4];
                ldsm4(ah, QS + swz512(rw0 + a_r, kk + a_c));
#pragma unroll
                for (int np = 0; np < 4; np++)
                    ldsm4(bh4[np], kb + swz512(np * 16 + b_r, kk + b_c));
#pragma unroll
                for (int np = 0; np < 4; np++) {
                    mma16(s4[2 * np], ah, &bh4[np][0]);
                    mma16(s4[2 * np + 1], ah, &bh4[np][2]);
                }
            }

            bool needmask = (k0 + 63 > q0 + rw0);
#pragma unroll
            for (int nt = 0; nt < 8; nt++) {
#pragma unroll
                for (int q = 0; q < 4; q++) s4[nt][q] *= 0.0625f;
                if (needmask) {
                    int c0 = k0 + nt * 8 + 2 * tig;
                    if (c0 > rg0) s4[nt][0] = -1e30f;
                    if (c0 + 1 > rg0) s4[nt][1] = -1e30f;
                    if (c0 > rg0 + 8) s4[nt][2] = -1e30f;
                    if (c0 + 1 > rg0 + 8) s4[nt][3] = -1e30f;
                }
            }

            float mx0 = -1e30f, mx1 = -1e30f;
#pragma unroll
            for (int nt = 0; nt < 8; nt++) {
                mx0 = fmaxf(mx0, fmaxf(s4[nt][0], s4[nt][1]));
                mx1 = fmaxf(mx1, fmaxf(s4[nt][2], s4[nt][3]));
            }
            mx0 = fmaxf(mx0, __shfl_xor_sync(0xffffffffu, mx0, 1));
            mx0 = fmaxf(mx0, __shfl_xor_sync(0xffffffffu, mx0, 2));
            mx1 = fmaxf(mx1, __shfl_xor_sync(0xffffffffu, mx1, 1));
            mx1 = fmaxf(mx1, __shfl_xor_sync(0xffffffffu, mx1, 2));
            float mn0 = fmaxf(m0v, mx0), mn1 = fmaxf(m1v, mx1);
            float cor0 = __expf(m0v - mn0), cor1 = __expf(m1v - mn1);
            m0v = mn0; m1v = mn1;

            float sum0 = 0.f, sum1 = 0.f;
            uint32_t ph[8][2];
#pragma unroll
            for (int nt = 0; nt < 8; nt++) {
                float p0 = __expf(s4[nt][0] - mn0);
                float p1 = __expf(s4[nt][1] - mn0);
                float p2 = __expf(s4[nt][2] - mn1);
                float p3 = __expf(s4[nt][3] - mn1);
                sum0 += p0 + p1; sum1 += p2 + p3;
                __half2 h01 = __floats2half2_rn(p0, p1);
                __half2 h23 = __floats2half2_rn(p2, p3);
                ph[nt][0] = *reinterpret_cast<uint32_t*>(&h01);
                ph[nt][1] = *reinterpret_cast<uint32_t*>(&h23);
            }
            sum0 += __shfl_xor_sync(0xffffffffu, sum0, 1);
            sum0 += __shfl_xor_sync(0xffffffffu, sum0, 2);
            sum1 += __shfl_xor_sync(0xffffffffu, sum1, 1);
            sum1 += __shfl_xor_sync(0xffffffffu, sum1, 2);
            l0v = l0v * cor0 + sum0;
            l1v = l1v * cor1 + sum1;

#pragma unroll
            for (int nt = 0; nt < 32; nt++) {
                o[nt][0] *= cor0; o[nt][1] *= cor0;
                o[nt][2] *= cor1; o[nt][3] *= cor1;
            }

#pragma unroll
            for (int kc = 0; kc < 4; kc++) {
                uint32_t a4[4] = {ph[2 * kc][0], ph[2 * kc][1],
                                  ph[2 * kc + 1][0], ph[2 * kc + 1][1]};
#pragma unroll
                for (int dp = 0; dp < 16; dp++) {
                    uint32_t b4[4];
                    ldsm4t(b4, vb + swz512(kc * 16 + a_r, dp * 16 + a_c));
                    mma16(o[2 * dp], a4, &b4[0]);
                    mma16(o[2 * dp + 1], a4, &b4[2]);
                }
            }
        }
        __syncthreads();
    }

    float inv0 = 1.f / l0v, inv1 = 1.f / l1v;
    __half* r0p = Og + (tok0 + rg0) * EMBED + h * HD;
    __half* r1p = Og + (tok0 + rg0 + 8) * EMBED + h * HD;
#pragma unroll
    for (int nt = 0; nt < 32; nt++) {
        int col = nt * 8 + 2 * tig;
        *reinterpret_cast<__half2*>(r0p + col) =
            __floats2half2_rn(o[nt][0] * inv0, o[nt][1] * inv0);
        *reinterpret_cast<__half2*>(r1p + col) =
            __floats2half2_rn(o[nt][2] * inv1, o[nt][3] * inv1);
    }
}

// ---------------------------------------------------------------------------
extern "C" void kernel_launch(void* const* d_in, const int* in_sizes, int n_in,
                              void* d_out, int out_size) {
    const float* hs = (const float*)d_in[0];
    const int* pid = (const int*)d_in[1];
    const float* qw = (const float*)d_in[2];
    const float* kw = (const float*)d_in[3];
    const float* vw = (const float*)d_in[4];
    const float* ow = (const float*)d_in[5];
    const float* emb = (const float*)d_in[6];
    float* out = (float*)d_out;

    __half *hs_h, *wq_h, *wk_h, *wv_h, *wo_h, *qh, *kh, *vh, *att;
    cudaGetSymbolAddress((void**)&hs_h, g_hs_h);
    cudaGetSymbolAddress((void**)&wq_h, g_wq_h);
    cudaGetSymbolAddress((void**)&wk_h, g_wk_h);
    cudaGetSymbolAddress((void**)&wv_h, g_wv_h);
    cudaGetSymbolAddress((void**)&wo_h, g_wo_h);
    cudaGetSymbolAddress((void**)&qh, g_qh);
    cudaGetSymbolAddress((void**)&kh, g_kh);
    cudaGetSymbolAddress((void**)&vh, g_v);
    cudaGetSymbolAddress((void**)&att, g_att);

    cudaFuncSetAttribute(gemm_qkv, cudaFuncAttributeMaxDynamicSharedMemorySize, GEMM_SMEM);
    cudaFuncSetAttribute(gemm_h, cudaFuncAttributeMaxDynamicSharedMemorySize, GEMM_SMEM);
    cudaFuncSetAttribute(flash_h, cudaFuncAttributeMaxDynamicSharedMemorySize, FL_SMEM);

    int n8 = (int)(NELEM / 8);
    f2h5<<<dim3(n8 / 256, 5), 256>>>((const float4*)hs, (const float4*)qw,
                                     (const float4*)kw, (const float4*)vw,
                                     (const float4*)ow, (uint4*)hs_h, (uint4*)wq_h,
                                     (uint4*)wk_h, (uint4*)wv_h, (uint4*)wo_h, n8);

    gemm_qkv<<<dim3(32, 32, 3), 128, GEMM_SMEM>>>(hs_h, wq_h, wk_h, wv_h, pid, emb,
                                                  qh, kh, vh);

    flash_h<<<512, 256, FL_SMEM>>>(qh, kh, vh, att);

    gemm_h<<<dim3(32, 32), 256, GEMM_SMEM>>>(att, wo_h, out);
}

// round 14
// speedup vs baseline: 11.2097x; 1.0071x over previous
#include <cuda_runtime.h>
#include <cuda_fp16.h>
#include <cstdint>
#include <math.h>

#define EMBED 4096
#define NH 16
#define HD 256
#define NB 2
#define NS 2048
#define NTOK (NB * NS)
#define NELEM ((size_t)NTOK * EMBED)

__device__ __half g_hs_h[NELEM];
__device__ __half g_wq_h[NELEM];
__device__ __half g_wk_h[NELEM];
__device__ __half g_wv_h[NELEM];
__device__ __half g_wo_h[NELEM];
__device__ __half g_qh[NELEM];
__device__ __half g_kh[NELEM];
__device__ __half g_v[NELEM];
__device__ __half g_att[NELEM];

// ---------------- PTX helpers (baseline ISA; tcgen05 is sm_103a-gated) ------
__device__ __forceinline__ uint32_t smem_u32(const void* p) {
    uint32_t a;
    asm("{ .reg .u64 t; cvta.to.shared.u64 t, %1; cvt.u32.u64 %0, t; }"
        : "=r"(a) : "l"(p));
    return a;
}
__device__ __forceinline__ void cp16(uint32_t s, const void* g) {
    asm volatile("cp.async.cg.shared.global [%0], [%1], 16;\n" ::"r"(s), "l"(g));
}
#define CP_COMMIT() asm volatile("cp.async.commit_group;\n" ::: "memory")
template <int N>
__device__ __forceinline__ void cp_wait() {
    asm volatile("cp.async.wait_group %0;\n" ::"n"(N) : "memory");
}
__device__ __forceinline__ void ldsm4(uint32_t* r, uint32_t a) {
    asm volatile("ldmatrix.sync.aligned.m8n8.x4.shared.b16 {%0,%1,%2,%3}, [%4];"
                 : "=r"(r[0]), "=r"(r[1]), "=r"(r[2]), "=r"(r[3]) : "r"(a));
}
__device__ __forceinline__ void ldsm4t(uint32_t* r, uint32_t a) {
    asm volatile("ldmatrix.sync.aligned.m8n8.x4.trans.shared.b16 {%0,%1,%2,%3}, [%4];"
                 : "=r"(r[0]), "=r"(r[1]), "=r"(r[2]), "=r"(r[3]) : "r"(a));
}
__device__ __forceinline__ void mma16(float* c, const uint32_t* a, const uint32_t* b) {
    asm volatile(
        "mma.sync.aligned.m16n8k16.row.col.f32.f16.f16.f32 "
        "{%0,%1,%2,%3}, {%4,%5,%6,%7}, {%8,%9}, {%0,%1,%2,%3};"
        : "+f"(c[0]), "+f"(c[1]), "+f"(c[2]), "+f"(c[3])
        : "r"(a[0]), "r"(a[1]), "r"(a[2]), "r"(a[3]), "r"(b[0]), "r"(b[1]));
}
__device__ __forceinline__ uint32_t swz128(int r, int c) {  // row = 64 halves
    return (uint32_t)(r * 128 + ((((c >> 3) ^ r) & 7) << 4) + ((c & 7) << 1));
}
__device__ __forceinline__ uint32_t swz512(int r, int c) {  // row = 256 halves
    int g = c >> 3;
    return (uint32_t)(r * 512 + (((g & 24) | ((g ^ r) & 7)) << 4) + ((c & 7) << 1));
}

// ---------------- fp32 -> fp16, 5 arrays in one launch ----------------------
__global__ void f2h5(const float4* __restrict__ s0, const float4* __restrict__ s1,
                     const float4* __restrict__ s2, const float4* __restrict__ s3,
                     const float4* __restrict__ s4,
                     uint4* __restrict__ d0, uint4* __restrict__ d1,
                     uint4* __restrict__ d2, uint4* __restrict__ d3,
                     uint4* __restrict__ d4, int n8) {
    int z = blockIdx.y;
    const float4* s = (z == 0) ? s0 : (z == 1) ? s1 : (z == 2) ? s2 : (z == 3) ? s3 : s4;
    uint4* d = (z == 0) ? d0 : (z == 1) ? d1 : (z == 2) ? d2 : (z == 3) ? d3 : d4;
    int i = blockIdx.x * blockDim.x + threadIdx.x;
    if (i < n8) {
        float4 a = s[2 * i], b = s[2 * i + 1];
        __half2 h0 = __floats2half2_rn(a.x, a.y);
        __half2 h1 = __floats2half2_rn(a.z, a.w);
        __half2 h2 = __floats2half2_rn(b.x, b.y);
        __half2 h3 = __floats2half2_rn(b.z, b.w);
        uint4 o;
        o.x = *reinterpret_cast<uint32_t*>(&h0);
        o.y = *reinterpret_cast<uint32_t*>(&h1);
        o.z = *reinterpret_cast<uint32_t*>(&h2);
        o.w = *reinterpret_cast<uint32_t*>(&h3);
        d[i] = o;
    }
}

#define G_STAGE_B 32768
#define GEMM_SMEM (3 * G_STAGE_B)

// ---- variant A: 8 warps (2x4), warp tile 64x32, 256 threads (for gemm_h) ---
// One barrier per chunk: the top sync (after cp_wait) already orders the
// previous chunk's reads before this chunk's producer overwrites that stage.
#define GEMM_MAIN_A(Bptr)                                                       \
    float acc[4][4][4];                                                         \
    _Pragma("unroll") for (int i = 0; i < 4; i++)                               \
        _Pragma("unroll") for (int j = 0; j < 4; j++)                           \
            _Pragma("unroll") for (int q = 0; q < 4; q++) acc[i][j][q] = 0.f;   \
    auto loadst = [&](int st, int k0) {                                         \
        uint32_t ab = smb + st * G_STAGE_B, bb = ab + 16384;                    \
        _Pragma("unroll") for (int i = 0; i < 4; i++) {                         \
            int gi = tid + i * 256;                                             \
            int r = gi >> 3, g = gi & 7;                                        \
            uint32_t off = r * 128 + (((g ^ r) & 7) << 4);                      \
            cp16(ab + off, A + (size_t)(m0 + r) * EMBED + k0 + g * 8);          \
            cp16(bb + off, Bptr + (size_t)(n0 + r) * EMBED + k0 + g * 8);       \
        }                                                                       \
    };                                                                          \
    loadst(0, 0); CP_COMMIT();                                                  \
    loadst(1, 64); CP_COMMIT();                                                 \
    int s = 0;                                                                  \
    for (int c = 0; c < 64; c++) {                                              \
        cp_wait<1>();                                                           \
        __syncthreads();                                                        \
        if (c + 2 < 64) loadst((s + 2) % 3, (c + 2) * 64);                      \
        CP_COMMIT();                                                            \
        uint32_t ab = smb + s * G_STAGE_B, bb = ab + 16384;                     \
        _Pragma("unroll") for (int kc = 0; kc < 4; kc++) {                      \
            int kk = kc * 16;                                                   \
            uint32_t af[4][4], bf[2][4];                                        \
            _Pragma("unroll") for (int mi = 0; mi < 4; mi++)                    \
                ldsm4(af[mi], ab + swz128(wm + mi * 16 + a_r, kk + a_c));       \
            _Pragma("unroll") for (int np = 0; np < 2; np++)                    \
                ldsm4(bf[np], bb + swz128(wn + np * 16 + b_r, kk + b_c));       \
            _Pragma("unroll") for (int mi = 0; mi < 4; mi++)                    \
                _Pragma("unroll") for (int ni = 0; ni < 4; ni++)                \
                    mma16(acc[mi][ni], af[mi], &bf[ni >> 1][(ni & 1) * 2]);     \
        }                                                                       \
        if (++s == 3) s = 0;                                                    \
    }

// ---- variant B: 4 warps (2x2), warp tile 64x64, 128 threads (for gemm_qkv) -
#define GEMM_MAIN_B(Bptr)                                                       \
    float acc[4][8][4];                                                         \
    _Pragma("unroll") for (int i = 0; i < 4; i++)                               \
        _Pragma("unroll") for (int j = 0; j < 8; j++)                           \
            _Pragma("unroll") for (int q = 0; q < 4; q++) acc[i][j][q] = 0.f;   \
    auto loadst = [&](int st, int k0) {                                         \
        uint32_t ab = smb + st * G_STAGE_B, bb = ab + 16384;                    \
        _Pragma("unroll") for (int i = 0; i < 8; i++) {                         \
            int gi = tid + i * 128;                                             \
            int r = gi >> 3, g = gi & 7;                                        \
            uint32_t off = r * 128 + (((g ^ r) & 7) << 4);                      \
            cp16(ab + off, A + (size_t)(m0 + r) * EMBED + k0 + g * 8);          \
            cp16(bb + off, Bptr + (size_t)(n0 + r) * EMBED + k0 + g * 8);       \
        }                                                                       \
    };                                                                          \
    loadst(0, 0); CP_COMMIT();                                                  \
    loadst(1, 64); CP_COMMIT();                                                 \
    int s = 0;                                                                  \
    for (int c = 0; c < 64; c++) {                                              \
        cp_wait<1>();                                                           \
        __syncthreads();                                                        \
        if (c + 2 < 64) loadst((s + 2) % 3, (c + 2) * 64);                      \
        CP_COMMIT();                                                            \
        uint32_t ab = smb + s * G_STAGE_B, bb = ab + 16384;                     \
        _Pragma("unroll") for (int kc = 0; kc < 4; kc++) {                      \
            int kk = kc * 16;                                                   \
            uint32_t af[4][4], bf[4][4];                                        \
            _Pragma("unroll") for (int mi = 0; mi < 4; mi++)                    \
                ldsm4(af[mi], ab + swz128(wm + mi * 16 + a_r, kk + a_c));       \
            _Pragma("unroll") for (int np = 0; np < 4; np++)                    \
                ldsm4(bf[np], bb + swz128(wn + np * 16 + b_r, kk + b_c));       \
            _Pragma("unroll") for (int mi = 0; mi < 4; mi++)                    \
                _Pragma("unroll") for (int ni = 0; ni < 8; ni++)                \
                    mma16(acc[mi][ni], af[mi], &bf[ni >> 1][(ni & 1) * 2]);     \
        }                                                                       \
        if (++s == 3) s = 0;                                                    \
    }

// Fused QKV with rotary in epilogue, plain fp16 outputs. grid (32,32,3), 128thr.
__global__ void __launch_bounds__(128, 2) gemm_qkv(const __half* __restrict__ A,
                                                   const __half* __restrict__ Wq,
                                                   const __half* __restrict__ Wk,
                                                   const __half* __restrict__ Wv,
                                                   const int* __restrict__ pid,
                                                   const float* __restrict__ emb,
                                                   __half* __restrict__ Qh,
                                                   __half* __restrict__ Kh,
                                                   __half* __restrict__ Cv) {
    extern __shared__ char smraw[];
    uint32_t smb = smem_u32(smraw);
    int z = blockIdx.z;
    const __half* B = (z == 0) ? Wq : (z == 1) ? Wk : Wv;

    int tid = threadIdx.x;
    int wid = tid >> 5, lane = tid & 31;
    int gid = lane >> 2, tig = lane & 3;
    int wm = (wid >> 1) * 64, wn = (wid & 1) * 64;
    int m0 = blockIdx.y * 128, n0 = blockIdx.x * 128;
    int a_r = lane & 15, a_c = (lane >> 4) << 3;
    int b_r = ((lane >> 4) << 3) + (lane & 7), b_c = ((lane >> 3) & 1) << 3;

    GEMM_MAIN_B(B)

    if (z == 2) {
#pragma unroll
        for (int mi = 0; mi < 4; mi++) {
            int r0 = m0 + wm + mi * 16 + gid;
#pragma unroll
            for (int ni = 0; ni < 8; ni++) {
                int col = n0 + wn + ni * 8 + tig * 2;
                *reinterpret_cast<__half2*>(Cv + (size_t)r0 * EMBED + col) =
                    __floats2half2_rn(acc[mi][ni][0], acc[mi][ni][1]);
                *reinterpret_cast<__half2*>(Cv + (size_t)(r0 + 8) * EMBED + col) =
                    __floats2half2_rn(acc[mi][ni][2], acc[mi][ni][3]);
            }
        }
    } else {
        __half* Hi = (z == 0) ? Qh : Kh;
#pragma unroll
        for (int mi = 0; mi < 4; mi++) {
            int r0 = m0 + wm + mi * 16 + gid;
            int p0 = pid[r0], p1 = pid[r0 + 8];
#pragma unroll
            for (int ni = 0; ni < 8; ni++) {
                int col = n0 + wn + ni * 8 + tig * 2;
                float v0 = acc[mi][ni][0], v1 = acc[mi][ni][1];
                float v2 = acc[mi][ni][2], v3 = acc[mi][ni][3];
                int c = col & 255;
                if (c < 64) {
                    int pr = c >> 1;
                    float sv0 = emb[p0 * 64 + pr], cv0 = emb[p0 * 64 + 32 + pr];
                    float sv1 = emb[p1 * 64 + pr], cv1 = emb[p1 * 64 + 32 + pr];
                    float a0 = v0 * cv0 - v1 * sv0, b0 = v1 * cv0 + v0 * sv0;
                    v0 = a0; v1 = b0;
                    float a1 = v2 * cv1 - v3 * sv1, b1 = v3 * cv1 + v2 * sv1;
                    v2 = a1; v3 = b1;
                }
                size_t o0 = (size_t)r0 * EMBED + col;
                size_t o1 = (size_t)(r0 + 8) * EMBED + col;
                *reinterpret_cast<__half2*>(Hi + o0) = __floats2half2_rn(v0, v1);
                *reinterpret_cast<__half2*>(Hi + o1) = __floats2half2_rn(v2, v3);
            }
        }
    }
}

// Out projection: half in, float out. 256 threads, 8 warps.
__global__ void __launch_bounds__(256, 2) gemm_h(const __half* __restrict__ A,
                                                 const __half* __restrict__ Bw,
                                                 float* __restrict__ C) {
    extern __shared__ char smraw[];
    uint32_t smb = smem_u32(smraw);
    int tid = threadIdx.x;
    int wid = tid >> 5, lane = tid & 31;
    int gid = lane >> 2, tig = lane & 3;
    int wm = (wid >> 2) * 64, wn = (wid & 3) * 32;
    int m0 = blockIdx.y * 128, n0 = blockIdx.x * 128;
    int a_r = lane & 15, a_c = (lane >> 4) << 3;
    int b_r = ((lane >> 4) << 3) + (lane & 7), b_c = ((lane >> 3) & 1) << 3;

    GEMM_MAIN_A(Bw)

#pragma unroll
    for (int mi = 0; mi < 4; mi++) {
        int r0 = m0 + wm + mi * 16 + gid;
#pragma unroll
        for (int ni = 0; ni < 4; ni++) {
            int col = n0 + wn + ni * 8 + tig * 2;
            *reinterpret_cast<float2*>(C + (size_t)r0 * EMBED + col) =
                make_float2(acc[mi][ni][0], acc[mi][ni][1]);
            *reinterpret_cast<float2*>(C + (size_t)(r0 + 8) * EMBED + col) =
                make_float2(acc[mi][ni][2], acc[mi][ni][3]);
        }
    }
}

// ---------------- fp16 HMMA causal flash attention, BQ=128, BK=64 -----------
// Softmax in base-2 domain: scale = (1/16)*log2(e), exp2f everywhere.
#define FL_SCALE 0.09016844f
#define FL_Q_B 65536
#define FL_KV_ST 65536
#define FL_SMEM (FL_Q_B + 2 * FL_KV_ST)  // 196608

__global__ void __launch_bounds__(256) flash_h(const __half* __restrict__ Qg,
                                               const __half* __restrict__ Kg,
                                               const __half* __restrict__ Vg,
                                               __half* __restrict__ Og) {
    extern __shared__ char smraw[];
    uint32_t smb = smem_u32(smraw);
    const uint32_t QS = smb, KV0 = smb + FL_Q_B;

    int tid = threadIdx.x;
    int wid = tid >> 5, lane = tid & 31;
    int gid = lane >> 2, tig = lane & 3;
    int rw0 = wid * 16;

    int bh = blockIdx.x & 31;
    int qb = 15 - (blockIdx.x >> 5);  // big tiles first
    int b = bh >> 4, h = bh & 15;
    int q0 = qb * 128;
    int nkt = 2 * qb + 2;             // 64-wide k tiles
    size_t tok0 = (size_t)b * NS;

    int a_r = lane & 15, a_c = (lane >> 4) << 3;
    int b_r = ((lane >> 4) << 3) + (lane & 7), b_c = ((lane >> 3) & 1) << 3;

#pragma unroll
    for (int i = 0; i < 16; i++) {  // Q: 128 rows x 256 halves
        int gi = tid + i * 256;
        int r = gi >> 5, g = gi & 31;
        uint32_t off = r * 512 + (((g & 24) | ((g ^ r) & 7)) << 4);
        cp16(QS + off, Qg + (tok0 + q0 + r) * EMBED + h * HD + g * 8);
    }
    auto loadkv = [&](int st, int kt) {
        uint32_t kb = KV0 + st * FL_KV_ST;
        int k0 = kt * 64;
#pragma unroll
        for (int i = 0; i < 8; i++) {  // 64 rows x 256 halves, K and V
            int gi = tid + i * 256;
            int r = gi >> 5, g = gi & 31;
            uint32_t off = r * 512 + (((g & 24) | ((g ^ r) & 7)) << 4);
            size_t src = (tok0 + k0 + r) * EMBED + h * HD + g * 8;
            cp16(kb + off, Kg + src);
            cp16(kb + 32768 + off, Vg + src);
        }
    };
    loadkv(0, 0);
    CP_COMMIT();

    float o[32][4];
#pragma unroll
    for (int nt = 0; nt < 32; nt++)
#pragma unroll
        for (int q = 0; q < 4; q++) o[nt][q] = 0.f;
    float m0v = -1e30f, m1v = -1e30f, l0v = 0.f, l1v = 0.f;
    int rg0 = q0 + rw0 + gid;

    for (int kt = 0; kt < nkt; kt++) {
        cp_wait<0>();        // stage kt resident (only 1 group ever in flight)
        __syncthreads();     // + all warps done with previous compute
        if (kt + 1 < nkt) loadkv((kt + 1) & 1, kt + 1);
        CP_COMMIT();

        int k0 = kt * 64;
        if (k0 <= q0 + rw0 + 15) {
            uint32_t kb = KV0 + (kt & 1) * FL_KV_ST;
            uint32_t vb = kb + 32768;

            float s4[8][4];
#pragma unroll
            for (int nt = 0; nt < 8; nt++)
#pragma unroll
                for (int q = 0; q < 4; q++) s4[nt][q] = 0.f;

#pragma unroll
            for (int kc = 0; kc < 16; kc++) {
                int kk = kc * 16;
                uint32_t ah[4], bh4[4][4];
                ldsm4(ah, QS + swz512(rw0 + a_r, kk + a_c));
#pragma unroll
                for (int np = 0; np < 4; np++)
                    ldsm4(bh4[np], kb + swz512(np * 16 + b_r, kk + b_c));
#pragma unroll
                for (int np = 0; np < 4; np++) {
                    mma16(s4[2 * np], ah, &bh4[np][0]);
                    mma16(s4[2 * np + 1], ah, &bh4[np][2]);
                }
            }

            bool needmask = (k0 + 63 > q0 + rw0);
#pragma unroll
            for (int nt = 0; nt < 8; nt++) {
#pragma unroll
                for (int q = 0; q < 4; q++) s4[nt][q] *= FL_SCALE;
                if (needmask) {
                    int c0 = k0 + nt * 8 + 2 * tig;
                    if (c0 > rg0) s4[nt][0] = -1e30f;
                    if (c0 + 1 > rg0) s4[nt][1] = -1e30f;
                    if (c0 > rg0 + 8) s4[nt][2] = -1e30f;
                    if (c0 + 1 > rg0 + 8) s4[nt][3] = -1e30f;
                }
            }

            float mx0 = -1e30f, mx1 = -1e30f;
#pragma unroll
            for (int nt = 0; nt < 8; nt++) {
                mx0 = fmaxf(mx0, fmaxf(s4[nt][0], s4[nt][1]));
                mx1 = fmaxf(mx1, fmaxf(s4[nt][2], s4[nt][3]));
            }
            mx0 = fmaxf(mx0, __shfl_xor_sync(0xffffffffu, mx0, 1));
            mx0 = fmaxf(mx0, __shfl_xor_sync(0xffffffffu, mx0, 2));
            mx1 = fmaxf(mx1, __shfl_xor_sync(0xffffffffu, mx1, 1));
            mx1 = fmaxf(mx1, __shfl_xor_sync(0xffffffffu, mx1, 2));
            float mn0 = fmaxf(m0v, mx0), mn1 = fmaxf(m1v, mx1);
            float cor0 = exp2f(m0v - mn0), cor1 = exp2f(m1v - mn1);
            m0v = mn0; m1v = mn1;

            float sum0 = 0.f, sum1 = 0.f;
            uint32_t ph[8][2];
#pragma unroll
            for (int nt = 0; nt < 8; nt++) {
                float p0 = exp2f(s4[nt][0] - mn0);
                float p1 = exp2f(s4[nt][1] - mn0);
                float p2 = exp2f(s4[nt][2] - mn1);
                float p3 = exp2f(s4[nt][3] - mn1);
                sum0 += p0 + p1; sum1 += p2 + p3;
                __half2 h01 = __floats2half2_rn(p0, p1);
                __half2 h23 = __floats2half2_rn(p2, p3);
                ph[nt][0] = *reinterpret_cast<uint32_t*>(&h01);
                ph[nt][1] = *reinterpret_cast<uint32_t*>(&h23);
            }
            sum0 += __shfl_xor_sync(0xffffffffu, sum0, 1);
            sum0 += __shfl_xor_sync(0xffffffffu, sum0, 2);
            sum1 += __shfl_xor_sync(0xffffffffu, sum1, 1);
            sum1 += __shfl_xor_sync(0xffffffffu, sum1, 2);
            l0v = l0v * cor0 + sum0;
            l1v = l1v * cor1 + sum1;

#pragma unroll
            for (int nt = 0; nt < 32; nt++) {
                o[nt][0] *= cor0; o[nt][1] *= cor0;
                o[nt][2] *= cor1; o[nt][3] *= cor1;
            }

#pragma unroll
            for (int kc = 0; kc < 4; kc++) {
                uint32_t a4[4] = {ph[2 * kc][0], ph[2 * kc][1],
                                  ph[2 * kc + 1][0], ph[2 * kc + 1][1]};
#pragma unroll
                for (int dp = 0; dp < 16; dp++) {
                    uint32_t b4[4];
                    ldsm4t(b4, vb + swz512(kc * 16 + a_r, dp * 16 + a_c));
                    mma16(o[2 * dp], a4, &b4[0]);
                    mma16(o[2 * dp + 1], a4, &b4[2]);
                }
            }
        }
    }

    float inv0 = 1.f / l0v, inv1 = 1.f / l1v;
    __half* r0p = Og + (tok0 + rg0) * EMBED + h * HD;
    __half* r1p = Og + (tok0 + rg0 + 8) * EMBED + h * HD;
#pragma unroll
    for (int nt = 0; nt < 32; nt++) {
        int col = nt * 8 + 2 * tig;
        *reinterpret_cast<__half2*>(r0p + col) =
            __floats2half2_rn(o[nt][0] * inv0, o[nt][1] * inv0);
        *reinterpret_cast<__half2*>(r1p + col) =
            __floats2half2_rn(o[nt][2] * inv1, o[nt][3] * inv1);
    }
}

// ---------------------------------------------------------------------------
extern "C" void kernel_launch(void* const* d_in, const int* in_sizes, int n_in,
                              void* d_out, int out_size) {
    const float* hs = (const float*)d_in[0];
    const int* pid = (const int*)d_in[1];
    const float* qw = (const float*)d_in[2];
    const float* kw = (const float*)d_in[3];
    const float* vw = (const float*)d_in[4];
    const float* ow = (const float*)d_in[5];
    const float* emb = (const float*)d_in[6];
    float* out = (float*)d_out;

    __half *hs_h, *wq_h, *wk_h, *wv_h, *wo_h, *qh, *kh, *vh, *att;
    cudaGetSymbolAddress((void**)&hs_h, g_hs_h);
    cudaGetSymbolAddress((void**)&wq_h, g_wq_h);
    cudaGetSymbolAddress((void**)&wk_h, g_wk_h);
    cudaGetSymbolAddress((void**)&wv_h, g_wv_h);
    cudaGetSymbolAddress((void**)&wo_h, g_wo_h);
    cudaGetSymbolAddress((void**)&qh, g_qh);
    cudaGetSymbolAddress((void**)&kh, g_kh);
    cudaGetSymbolAddress((void**)&vh, g_v);
    cudaGetSymbolAddress((void**)&att, g_att);

    cudaFuncSetAttribute(gemm_qkv, cudaFuncAttributeMaxDynamicSharedMemorySize, GEMM_SMEM);
    cudaFuncSetAttribute(gemm_h, cudaFuncAttributeMaxDynamicSharedMemorySize, GEMM_SMEM);
    cudaFuncSetAttribute(flash_h, cudaFuncAttributeMaxDynamicSharedMemorySize, FL_SMEM);

    int n8 = (int)(NELEM / 8);
    f2h5<<<dim3(n8 / 256, 5), 256>>>((const float4*)hs, (const float4*)qw,
                                     (const float4*)kw, (const float4*)vw,
                                     (const float4*)ow, (uint4*)hs_h, (uint4*)wq_h,
                                     (uint4*)wk_h, (uint4*)wv_h, (uint4*)wo_h, n8);

    gemm_qkv<<<dim3(32, 32, 3), 128, GEMM_SMEM>>>(hs_h, wq_h, wk_h, wv_h, pid, emb,
                                                  qh, kh, vh);

    flash_h<<<512, 256, FL_SMEM>>>(qh, kh, vh, att);

    gemm_h<<<dim3(32, 32), 256, GEMM_SMEM>>>(att, wo_h, out);
}

// round 15
// speedup vs baseline: 11.2471x; 1.0033x over previous
#include <cuda_runtime.h>
#include <cuda_fp16.h>
#include <cstdint>
#include <math.h>

#define EMBED 4096
#define NH 16
#define HD 256
#define NB 2
#define NS 2048
#define NTOK (NB * NS)
#define NELEM ((size_t)NTOK * EMBED)

__device__ __half g_hs_h[NELEM];
__device__ __half g_wq_h[NELEM];
__device__ __half g_wk_h[NELEM];
__device__ __half g_wv_h[NELEM];
__device__ __half g_wo_h[NELEM];
__device__ __half g_qh[NELEM];
__device__ __half g_kh[NELEM];
__device__ __half g_v[NELEM];
__device__ __half g_att[NELEM];

// ---------------- PTX helpers (baseline ISA; tcgen05 is sm_103a-gated) ------
__device__ __forceinline__ uint32_t smem_u32(const void* p) {
    uint32_t a;
    asm("{ .reg .u64 t; cvta.to.shared.u64 t, %1; cvt.u32.u64 %0, t; }"
        : "=r"(a) : "l"(p));
    return a;
}
__device__ __forceinline__ void cp16(uint32_t s, const void* g) {
    asm volatile("cp.async.cg.shared.global [%0], [%1], 16;\n" ::"r"(s), "l"(g));
}
#define CP_COMMIT() asm volatile("cp.async.commit_group;\n" ::: "memory")
template <int N>
__device__ __forceinline__ void cp_wait() {
    asm volatile("cp.async.wait_group %0;\n" ::"n"(N) : "memory");
}
__device__ __forceinline__ void ldsm4(uint32_t* r, uint32_t a) {
    asm volatile("ldmatrix.sync.aligned.m8n8.x4.shared.b16 {%0,%1,%2,%3}, [%4];"
                 : "=r"(r[0]), "=r"(r[1]), "=r"(r[2]), "=r"(r[3]) : "r"(a));
}
__device__ __forceinline__ void ldsm4t(uint32_t* r, uint32_t a) {
    asm volatile("ldmatrix.sync.aligned.m8n8.x4.trans.shared.b16 {%0,%1,%2,%3}, [%4];"
                 : "=r"(r[0]), "=r"(r[1]), "=r"(r[2]), "=r"(r[3]) : "r"(a));
}
__device__ __forceinline__ void mma16(float* c, const uint32_t* a, const uint32_t* b) {
    asm volatile(
        "mma.sync.aligned.m16n8k16.row.col.f32.f16.f16.f32 "
        "{%0,%1,%2,%3}, {%4,%5,%6,%7}, {%8,%9}, {%0,%1,%2,%3};"
        : "+f"(c[0]), "+f"(c[1]), "+f"(c[2]), "+f"(c[3])
        : "r"(a[0]), "r"(a[1]), "r"(a[2]), "r"(a[3]), "r"(b[0]), "r"(b[1]));
}
__device__ __forceinline__ uint32_t swz128(int r, int c) {  // row = 64 halves
    return (uint32_t)(r * 128 + ((((c >> 3) ^ r) & 7) << 4) + ((c & 7) << 1));
}
__device__ __forceinline__ uint32_t swz512(int r, int c) {  // row = 256 halves
    int g = c >> 3;
    return (uint32_t)(r * 512 + (((g & 24) | ((g ^ r) & 7)) << 4) + ((c & 7) << 1));
}

// ---------------- fp32 -> fp16, 5 arrays in one launch ----------------------
__global__ void f2h5(const float4* __restrict__ s0, const float4* __restrict__ s1,
                     const float4* __restrict__ s2, const float4* __restrict__ s3,
                     const float4* __restrict__ s4,
                     uint4* __restrict__ d0, uint4* __restrict__ d1,
                     uint4* __restrict__ d2, uint4* __restrict__ d3,
                     uint4* __restrict__ d4, int n8) {
    int z = blockIdx.y;
    const float4* s = (z == 0) ? s0 : (z == 1) ? s1 : (z == 2) ? s2 : (z == 3) ? s3 : s4;
    uint4* d = (z == 0) ? d0 : (z == 1) ? d1 : (z == 2) ? d2 : (z == 3) ? d3 : d4;
    int i = blockIdx.x * blockDim.x + threadIdx.x;
    if (i < n8) {
        float4 a = s[2 * i], b = s[2 * i + 1];
        __half2 h0 = __floats2half2_rn(a.x, a.y);
        __half2 h1 = __floats2half2_rn(a.z, a.w);
        __half2 h2 = __floats2half2_rn(b.x, b.y);
        __half2 h3 = __floats2half2_rn(b.z, b.w);
        uint4 o;
        o.x = *reinterpret_cast<uint32_t*>(&h0);
        o.y = *reinterpret_cast<uint32_t*>(&h1);
        o.z = *reinterpret_cast<uint32_t*>(&h2);
        o.w = *reinterpret_cast<uint32_t*>(&h3);
        d[i] = o;
    }
}

#define G_STAGE_B 32768
#define GEMM_SMEM (3 * G_STAGE_B)

// ---- variant A: 8 warps (2x4), warp tile 64x32, 256 threads (for gemm_h) ---
#define GEMM_MAIN_A(Bptr)                                                       \
    float acc[4][4][4];                                                         \
    _Pragma("unroll") for (int i = 0; i < 4; i++)                               \
        _Pragma("unroll") for (int j = 0; j < 4; j++)                           \
            _Pragma("unroll") for (int q = 0; q < 4; q++) acc[i][j][q] = 0.f;   \
    auto loadst = [&](int st, int k0) {                                         \
        uint32_t ab = smb + st * G_STAGE_B, bb = ab + 16384;                    \
        _Pragma("unroll") for (int i = 0; i < 4; i++) {                         \
            int gi = tid + i * 256;                                             \
            int r = gi >> 3, g = gi & 7;                                        \
            uint32_t off = r * 128 + (((g ^ r) & 7) << 4);                      \
            cp16(ab + off, A + (size_t)(m0 + r) * EMBED + k0 + g * 8);          \
            cp16(bb + off, Bptr + (size_t)(n0 + r) * EMBED + k0 + g * 8);       \
        }                                                                       \
    };                                                                          \
    loadst(0, 0); CP_COMMIT();                                                  \
    loadst(1, 64); CP_COMMIT();                                                 \
    int s = 0;                                                                  \
    for (int c = 0; c < 64; c++) {                                              \
        cp_wait<1>();                                                           \
        __syncthreads();                                                        \
        if (c + 2 < 64) loadst((s + 2) % 3, (c + 2) * 64);                      \
        CP_COMMIT();                                                            \
        uint32_t ab = smb + s * G_STAGE_B, bb = ab + 16384;                     \
        _Pragma("unroll") for (int kc = 0; kc < 4; kc++) {                      \
            int kk = kc * 16;                                                   \
            uint32_t af[4][4], bf[2][4];                                        \
            _Pragma("unroll") for (int mi = 0; mi < 4; mi++)                    \
                ldsm4(af[mi], ab + swz128(wm + mi * 16 + a_r, kk + a_c));       \
            _Pragma("unroll") for (int np = 0; np < 2; np++)                    \
                ldsm4(bf[np], bb + swz128(wn + np * 16 + b_r, kk + b_c));       \
            _Pragma("unroll") for (int mi = 0; mi < 4; mi++)                    \
                _Pragma("unroll") for (int ni = 0; ni < 4; ni++)                \
                    mma16(acc[mi][ni], af[mi], &bf[ni >> 1][(ni & 1) * 2]);     \
        }                                                                       \
        if (++s == 3) s = 0;                                                    \
    }

// ---- variant B: 4 warps (2x2), warp tile 64x64, 128 threads (for gemm_qkv) -
#define GEMM_MAIN_B(Bptr)                                                       \
    float acc[4][8][4];                                                         \
    _Pragma("unroll") for (int i = 0; i < 4; i++)                               \
        _Pragma("unroll") for (int j = 0; j < 8; j++)                           \
            _Pragma("unroll") for (int q = 0; q < 4; q++) acc[i][j][q] = 0.f;   \
    auto loadst = [&](int st, int k0) {                                         \
        uint32_t ab = smb + st * G_STAGE_B, bb = ab + 16384;                    \
        _Pragma("unroll") for (int i = 0; i < 8; i++) {                         \
            int gi = tid + i * 128;                                             \
            int r = gi >> 3, g = gi & 7;                                        \
            uint32_t off = r * 128 + (((g ^ r) & 7) << 4);                      \
            cp16(ab + off, A + (size_t)(m0 + r) * EMBED + k0 + g * 8);          \
            cp16(bb + off, Bptr + (size_t)(n0 + r) * EMBED + k0 + g * 8);       \
        }                                                                       \
    };                                                                          \
    loadst(0, 0); CP_COMMIT();                                                  \
    loadst(1, 64); CP_COMMIT();                                                 \
    int s = 0;                                                                  \
    for (int c = 0; c < 64; c++) {                                              \
        cp_wait<1>();                                                           \
        __syncthreads();                                                        \
        if (c + 2 < 64) loadst((s + 2) % 3, (c + 2) * 64);                      \
        CP_COMMIT();                                                            \
        uint32_t ab = smb + s * G_STAGE_B, bb = ab + 16384;                     \
        _Pragma("unroll") for (int kc = 0; kc < 4; kc++) {                      \
            int kk = kc * 16;                                                   \
            uint32_t af[4][4], bf[4][4];                                        \
            _Pragma("unroll") for (int mi = 0; mi < 4; mi++)                    \
                ldsm4(af[mi], ab + swz128(wm + mi * 16 + a_r, kk + a_c));       \
            _Pragma("unroll") for (int np = 0; np < 4; np++)                    \
                ldsm4(bf[np], bb + swz128(wn + np * 16 + b_r, kk + b_c));       \
            _Pragma("unroll") for (int mi = 0; mi < 4; mi++)                    \
                _Pragma("unroll") for (int ni = 0; ni < 8; ni++)                \
                    mma16(acc[mi][ni], af[mi], &bf[ni >> 1][(ni & 1) * 2]);     \
        }                                                                       \
        if (++s == 3) s = 0;                                                    \
    }

// Fused QKV with rotary in epilogue, plain fp16 outputs. grid (32,32,3), 128thr.
__global__ void __launch_bounds__(128, 2) gemm_qkv(const __half* __restrict__ A,
                                                   const __half* __restrict__ Wq,
                                                   const __half* __restrict__ Wk,
                                                   const __half* __restrict__ Wv,
                                                   const int* __restrict__ pid,
                                                   const float* __restrict__ emb,
                                                   __half* __restrict__ Qh,
                                                   __half* __restrict__ Kh,
                                                   __half* __restrict__ Cv) {
    extern __shared__ char smraw[];
    uint32_t smb = smem_u32(smraw);
    int z = blockIdx.z;
    const __half* B = (z == 0) ? Wq : (z == 1) ? Wk : Wv;

    int tid = threadIdx.x;
    int wid = tid >> 5, lane = tid & 31;
    int gid = lane >> 2, tig = lane & 3;
    int wm = (wid >> 1) * 64, wn = (wid & 1) * 64;
    int m0 = blockIdx.y * 128, n0 = blockIdx.x * 128;
    int a_r = lane & 15, a_c = (lane >> 4) << 3;
    int b_r = ((lane >> 4) << 3) + (lane & 7), b_c = ((lane >> 3) & 1) << 3;

    GEMM_MAIN_B(B)

    if (z == 2) {
#pragma unroll
        for (int mi = 0; mi < 4; mi++) {
            int r0 = m0 + wm + mi * 16 + gid;
#pragma unroll
            for (int ni = 0; ni < 8; ni++) {
                int col = n0 + wn + ni * 8 + tig * 2;
                *reinterpret_cast<__half2*>(Cv + (size_t)r0 * EMBED + col) =
                    __floats2half2_rn(acc[mi][ni][0], acc[mi][ni][1]);
                *reinterpret_cast<__half2*>(Cv + (size_t)(r0 + 8) * EMBED + col) =
                    __floats2half2_rn(acc[mi][ni][2], acc[mi][ni][3]);
            }
        }
    } else {
        __half* Hi = (z == 0) ? Qh : Kh;
#pragma unroll
        for (int mi = 0; mi < 4; mi++) {
            int r0 = m0 + wm + mi * 16 + gid;
            int p0 = pid[r0], p1 = pid[r0 + 8];
#pragma unroll
            for (int ni = 0; ni < 8; ni++) {
                int col = n0 + wn + ni * 8 + tig * 2;
                float v0 = acc[mi][ni][0], v1 = acc[mi][ni][1];
                float v2 = acc[mi][ni][2], v3 = acc[mi][ni][3];
                int c = col & 255;
                if (c < 64) {
                    int pr = c >> 1;
                    float sv0 = emb[p0 * 64 + pr], cv0 = emb[p0 * 64 + 32 + pr];
                    float sv1 = emb[p1 * 64 + pr], cv1 = emb[p1 * 64 + 32 + pr];
                    float a0 = v0 * cv0 - v1 * sv0, b0 = v1 * cv0 + v0 * sv0;
                    v0 = a0; v1 = b0;
                    float a1 = v2 * cv1 - v3 * sv1, b1 = v3 * cv1 + v2 * sv1;
                    v2 = a1; v3 = b1;
                }
                size_t o0 = (size_t)r0 * EMBED + col;
                size_t o1 = (size_t)(r0 + 8) * EMBED + col;
                *reinterpret_cast<__half2*>(Hi + o0) = __floats2half2_rn(v0, v1);
                *reinterpret_cast<__half2*>(Hi + o1) = __floats2half2_rn(v2, v3);
            }
        }
    }
}

// Out projection: half in, float out. 256 threads, 8 warps.
__global__ void __launch_bounds__(256, 2) gemm_h(const __half* __restrict__ A,
                                                 const __half* __restrict__ Bw,
                                                 float* __restrict__ C) {
    extern __shared__ char smraw[];
    uint32_t smb = smem_u32(smraw);
    int tid = threadIdx.x;
    int wid = tid >> 5, lane = tid & 31;
    int gid = lane >> 2, tig = lane & 3;
    int wm = (wid >> 2) * 64, wn = (wid & 3) * 32;
    int m0 = blockIdx.y * 128, n0 = blockIdx.x * 128;
    int a_r = lane & 15, a_c = (lane >> 4) << 3;
    int b_r = ((lane >> 4) << 3) + (lane & 7), b_c = ((lane >> 3) & 1) << 3;

    GEMM_MAIN_A(Bw)

#pragma unroll
    for (int mi = 0; mi < 4; mi++) {
        int r0 = m0 + wm + mi * 16 + gid;
#pragma unroll
        for (int ni = 0; ni < 4; ni++) {
            int col = n0 + wn + ni * 8 + tig * 2;
            *reinterpret_cast<float2*>(C + (size_t)r0 * EMBED + col) =
                make_float2(acc[mi][ni][0], acc[mi][ni][1]);
            *reinterpret_cast<float2*>(C + (size_t)(r0 + 8) * EMBED + col) =
                make_float2(acc[mi][ni][2], acc[mi][ni][3]);
        }
    }
}

// ---------------- fp16 HMMA causal flash attention ---------------------------
// BQ=64, BK=32, 4 warps (128 thr), smem 96KB -> 2 CTAs/SM.
// Softmax in base-2 domain: scale = (1/16)*log2(e), exp2f everywhere.
#define FL_SCALE 0.09016844f
#define FL_Q_B 32768
#define FL_KV_ST 32768
#define FL_SMEM (FL_Q_B + 2 * FL_KV_ST)  // 98304

__global__ void __launch_bounds__(128, 2) flash_h(const __half* __restrict__ Qg,
                                                  const __half* __restrict__ Kg,
                                                  const __half* __restrict__ Vg,
                                                  __half* __restrict__ Og) {
    extern __shared__ char smraw[];
    uint32_t smb = smem_u32(smraw);
    const uint32_t QS = smb, KV0 = smb + FL_Q_B;

    int tid = threadIdx.x;
    int wid = tid >> 5, lane = tid & 31;
    int gid = lane >> 2, tig = lane & 3;
    int rw0 = wid * 16;

    int bh = blockIdx.x & 31;
    int qb = 31 - (blockIdx.x >> 5);  // 32 q-blocks of 64; big tiles first
    int b = bh >> 4, h = bh & 15;
    int q0 = qb * 64;
    int nkt = 2 * qb + 2;             // 32-wide k tiles
    size_t tok0 = (size_t)b * NS;

    int a_r = lane & 15, a_c = (lane >> 4) << 3;
    int b_r = ((lane >> 4) << 3) + (lane & 7), b_c = ((lane >> 3) & 1) << 3;

#pragma unroll
    for (int i = 0; i < 16; i++) {  // Q: 64 rows x 256 halves = 2048 cp16
        int gi = tid + i * 128;
        int r = gi >> 5, g = gi & 31;
        uint32_t off = r * 512 + (((g & 24) | ((g ^ r) & 7)) << 4);
        cp16(QS + off, Qg + (tok0 + q0 + r) * EMBED + h * HD + g * 8);
    }
    auto loadkv = [&](int st, int kt) {
        uint32_t kb = KV0 + st * FL_KV_ST;
        int k0 = kt * 32;
#pragma unroll
        for (int i = 0; i < 8; i++) {  // 32 rows x 256 halves, K and V
            int gi = tid + i * 128;
            int r = gi >> 5, g = gi & 31;
            uint32_t off = r * 512 + (((g & 24) | ((g ^ r) & 7)) << 4);
            size_t src = (tok0 + k0 + r) * EMBED + h * HD + g * 8;
            cp16(kb + off, Kg + src);
            cp16(kb + 16384 + off, Vg + src);
        }
    };
    loadkv(0, 0);
    CP_COMMIT();

    float o[32][4];
#pragma unroll
    for (int nt = 0; nt < 32; nt++)
#pragma unroll
        for (int q = 0; q < 4; q++) o[nt][q] = 0.f;
    float m0v = -1e30f, m1v = -1e30f, l0v = 0.f, l1v = 0.f;
    int rg0 = q0 + rw0 + gid;

    for (int kt = 0; kt < nkt; kt++) {
        cp_wait<0>();        // stage kt resident (only 1 group ever in flight)
        __syncthreads();     // + all warps done with previous compute
        if (kt + 1 < nkt) loadkv((kt + 1) & 1, kt + 1);
        CP_COMMIT();

        int k0 = kt * 32;
        if (k0 <= q0 + rw0 + 15) {
            uint32_t kb = KV0 + (kt & 1) * FL_KV_ST;
            uint32_t vb = kb + 16384;

            float s4[4][4];
#pragma unroll
            for (int nt = 0; nt < 4; nt++)
#pragma unroll
                for (int q = 0; q < 4; q++) s4[nt][q] = 0.f;

#pragma unroll
            for (int kc = 0; kc < 16; kc++) {
                int kk = kc * 16;
                uint32_t ah[4], bh4[2][4];
                ldsm4(ah, QS + swz512(rw0 + a_r, kk + a_c));
#pragma unroll
                for (int np = 0; np < 2; np++)
                    ldsm4(bh4[np], kb + swz512(np * 16 + b_r, kk + b_c));
#pragma unroll
                for (int np = 0; np < 2; np++) {
                    mma16(s4[2 * np], ah, &bh4[np][0]);
                    mma16(s4[2 * np + 1], ah, &bh4[np][2]);
                }
            }

            bool needmask = (k0 + 31 > q0 + rw0);
#pragma unroll
            for (int nt = 0; nt < 4; nt++) {
#pragma unroll
                for (int q = 0; q < 4; q++) s4[nt][q] *= FL_SCALE;
                if (needmask) {
                    int c0 = k0 + nt * 8 + 2 * tig;
                    if (c0 > rg0) s4[nt][0] = -1e30f;
                    if (c0 + 1 > rg0) s4[nt][1] = -1e30f;
                    if (c0 > rg0 + 8) s4[nt][2] = -1e30f;
                    if (c0 + 1 > rg0 + 8) s4[nt][3] = -1e30f;
                }
            }

            float mx0 = -1e30f, mx1 = -1e30f;
#pragma unroll
            for (int nt = 0; nt < 4; nt++) {
                mx0 = fmaxf(mx0, fmaxf(s4[nt][0], s4[nt][1]));
                mx1 = fmaxf(mx1, fmaxf(s4[nt][2], s4[nt][3]));
            }
            mx0 = fmaxf(mx0, __shfl_xor_sync(0xffffffffu, mx0, 1));
            mx0 = fmaxf(mx0, __shfl_xor_sync(0xffffffffu, mx0, 2));
            mx1 = fmaxf(mx1, __shfl_xor_sync(0xffffffffu, mx1, 1));
            mx1 = fmaxf(mx1, __shfl_xor_sync(0xffffffffu, mx1, 2));
            float mn0 = fmaxf(m0v, mx0), mn1 = fmaxf(m1v, mx1);
            float cor0 = exp2f(m0v - mn0), cor1 = exp2f(m1v - mn1);
            m0v = mn0; m1v = mn1;

            float sum0 = 0.f, sum1 = 0.f;
            uint32_t ph[4][2];
#pragma unroll
            for (int nt = 0; nt < 4; nt++) {
                float p0 = exp2f(s4[nt][0] - mn0);
                float p1 = exp2f(s4[nt][1] - mn0);
                float p2 = exp2f(s4[nt][2] - mn1);
                float p3 = exp2f(s4[nt][3] - mn1);
                sum0 += p0 + p1; sum1 += p2 + p3;
                __half2 h01 = __floats2half2_rn(p0, p1);
                __half2 h23 = __floats2half2_rn(p2, p3);
                ph[nt][0] = *reinterpret_cast<uint32_t*>(&h01);
                ph[nt][1] = *reinterpret_cast<uint32_t*>(&h23);
            }
            sum0 += __shfl_xor_sync(0xffffffffu, sum0, 1);
            sum0 += __shfl_xor_sync(0xffffffffu, sum0, 2);
            sum1 += __shfl_xor_sync(0xffffffffu, sum1, 1);
            sum1 += __shfl_xor_sync(0xffffffffu, sum1, 2);
            l0v = l0v * cor0 + sum0;
            l1v = l1v * cor1 + sum1;

#pragma unroll
            for (int nt = 0; nt < 32; nt++) {
                o[nt][0] *= cor0; o[nt][1] *= cor0;
                o[nt][2] *= cor1; o[nt][3] *= cor1;
            }

#pragma unroll
            for (int kc = 0; kc < 2; kc++) {
                uint32_t a4[4] = {ph[2 * kc][0], ph[2 * kc][1],
                                  ph[2 * kc + 1][0], ph[2 * kc + 1][1]};
#pragma unroll
                for (int dp = 0; dp < 16; dp++) {
                    uint32_t b4[4];
                    ldsm4t(b4, vb + swz512(kc * 16 + a_r, dp * 16 + a_c));
                    mma16(o[2 * dp], a4, &b4[0]);
                    mma16(o[2 * dp + 1], a4, &b4[2]);
                }
            }
        }
    }

    float inv0 = 1.f / l0v, inv1 = 1.f / l1v;
    __half* r0p = Og + (tok0 + rg0) * EMBED + h * HD;
    __half* r1p = Og + (tok0 + rg0 + 8) * EMBED + h * HD;
#pragma unroll
    for (int nt = 0; nt < 32; nt++) {
        int col = nt * 8 + 2 * tig;
        *reinterpret_cast<__half2*>(r0p + col) =
            __floats2half2_rn(o[nt][0] * inv0, o[nt][1] * inv0);
        *reinterpret_cast<__half2*>(r1p + col) =
            __floats2half2_rn(o[nt][2] * inv1, o[nt][3] * inv1);
    }
}

// ---------------------------------------------------------------------------
extern "C" void kernel_launch(void* const* d_in, const int* in_sizes, int n_in,
                              void* d_out, int out_size) {
    const float* hs = (const float*)d_in[0];
    const int* pid = (const int*)d_in[1];
    const float* qw = (const float*)d_in[2];
    const float* kw = (const float*)d_in[3];
    const float* vw = (const float*)d_in[4];
    const float* ow = (const float*)d_in[5];
    const float* emb = (const float*)d_in[6];
    float* out = (float*)d_out;

    __half *hs_h, *wq_h, *wk_h, *wv_h, *wo_h, *qh, *kh, *vh, *att;
    cudaGetSymbolAddress((void**)&hs_h, g_hs_h);
    cudaGetSymbolAddress((void**)&wq_h, g_wq_h);
    cudaGetSymbolAddress((void**)&wk_h, g_wk_h);
    cudaGetSymbolAddress((void**)&wv_h, g_wv_h);
    cudaGetSymbolAddress((void**)&wo_h, g_wo_h);
    cudaGetSymbolAddress((void**)&qh, g_qh);
    cudaGetSymbolAddress((void**)&kh, g_kh);
    cudaGetSymbolAddress((void**)&vh, g_v);
    cudaGetSymbolAddress((void**)&att, g_att);

    cudaFuncSetAttribute(gemm_qkv, cudaFuncAttributeMaxDynamicSharedMemorySize, GEMM_SMEM);
    cudaFuncSetAttribute(gemm_h, cudaFuncAttributeMaxDynamicSharedMemorySize, GEMM_SMEM);
    cudaFuncSetAttribute(flash_h, cudaFuncAttributeMaxDynamicSharedMemorySize, FL_SMEM);

    int n8 = (int)(NELEM / 8);
    f2h5<<<dim3(n8 / 256, 5), 256>>>((const float4*)hs, (const float4*)qw,
                                     (const float4*)kw, (const float4*)vw,
                                     (const float4*)ow, (uint4*)hs_h, (uint4*)wq_h,
                                     (uint4*)wk_h, (uint4*)wv_h, (uint4*)wo_h, n8);

    gemm_qkv<<<dim3(32, 32, 3), 128, GEMM_SMEM>>>(hs_h, wq_h, wk_h, wv_h, pid, emb,
                                                  qh, kh, vh);

    flash_h<<<1024, 128, FL_SMEM>>>(qh, kh, vh, att);

    gemm_h<<<dim3(32, 32), 256, GEMM_SMEM>>>(att, wo_h, out);
}